// round 1
// baseline (speedup 1.0000x reference)
#include <cuda_runtime.h>
#include <cstddef>

// ---------------------------------------------------------------------------
// Problem constants: B=4, S=2048, D=768, H=3
//   tokens M = B*S = 8192
//   qkv width = H*D = 2304
// ---------------------------------------------------------------------------

#define BM 128
#define BN 128
#define BK 16
#define TM 8
#define TN 8
#define PAD 4          // smem column padding

// Scratch (allocation-free: __device__ globals)
__device__ float g_q[8192ull * 2304];   // 75.5 MB
__device__ float g_k[8192ull * 2304];
__device__ float g_v[8192ull * 2304];
__device__ float g_s[12ull * 2048 * 2048]; // 201 MB scores
__device__ float g_o[8192ull * 2304];
__device__ float g_a[8192ull * 768];
__device__ float g_part[1024];
__device__ float g_mean[1];

// ---------------------------------------------------------------------------
// Generic NN SGEMM with bias: C[M,N] = A[M,K]*B[K,N] + bias[N]
// All of M,N multiples of 128; K multiple of 16. No bounds checks.
// ---------------------------------------------------------------------------
__global__ __launch_bounds__(256, 2)
void sgemm_nn_bias(const float* __restrict__ A, int lda,
                   const float* __restrict__ B, int ldb,
                   const float* __restrict__ bias,
                   float* __restrict__ C, int ldc, int K)
{
    __shared__ float As[BK][BM + PAD];
    __shared__ float Bs[BK][BN + PAD];
    const int m0 = blockIdx.y * BM;
    const int n0 = blockIdx.x * BN;
    const int tid = threadIdx.x;
    const int trow = (tid >> 4) * TM;
    const int tcol = (tid & 15) * TN;

    float acc[TM][TN];
    #pragma unroll
    for (int i = 0; i < TM; i++)
        #pragma unroll
        for (int j = 0; j < TN; j++) acc[i][j] = 0.f;

    for (int k0 = 0; k0 < K; k0 += BK) {
        #pragma unroll
        for (int i = 0; i < 2; i++) {
            int idx = tid + i * 256;
            int r = idx >> 2, cg = (idx & 3) << 2;
            float4 va = *(const float4*)(A + (size_t)(m0 + r) * lda + k0 + cg);
            As[cg + 0][r] = va.x; As[cg + 1][r] = va.y;
            As[cg + 2][r] = va.z; As[cg + 3][r] = va.w;
        }
        #pragma unroll
        for (int i = 0; i < 2; i++) {
            int idx = tid + i * 256;
            int r = idx >> 5, c = (idx & 31) << 2;
            *(float4*)&Bs[r][c] = *(const float4*)(B + (size_t)(k0 + r) * ldb + n0 + c);
        }
        __syncthreads();
        #pragma unroll
        for (int kk = 0; kk < BK; kk++) {
            float ar[TM], br[TN];
            #pragma unroll
            for (int i = 0; i < TM; i++) ar[i] = As[kk][trow + i];
            #pragma unroll
            for (int j = 0; j < TN; j++) br[j] = Bs[kk][tcol + j];
            #pragma unroll
            for (int i = 0; i < TM; i++)
                #pragma unroll
                for (int j = 0; j < TN; j++) acc[i][j] = fmaf(ar[i], br[j], acc[i][j]);
        }
        __syncthreads();
    }

    #pragma unroll
    for (int i = 0; i < TM; i++) {
        float* cp = C + (size_t)(m0 + trow + i) * ldc + n0 + tcol;
        #pragma unroll
        for (int j = 0; j < TN; j += 4) {
            float4 v;
            v.x = acc[i][j + 0] + bias[n0 + tcol + j + 0];
            v.y = acc[i][j + 1] + bias[n0 + tcol + j + 1];
            v.z = acc[i][j + 2] + bias[n0 + tcol + j + 2];
            v.w = acc[i][j + 3] + bias[n0 + tcol + j + 3];
            *(float4*)(cp + j) = v;
        }
    }
}

// ---------------------------------------------------------------------------
// Scores: per (b,h), S = Q * K^T (NT), with exact reference masking:
//   masked[i,j] = (j>i || s==0) ? -99999 : s
// q,k are [8192, 2304]; per-(b,h) views use lda=2304, col offset h*768.
// Tiles fully above the diagonal write -99999 without compute.
// ---------------------------------------------------------------------------
__global__ __launch_bounds__(256, 2)
void scores_kernel(const float* __restrict__ q, const float* __restrict__ k,
                   float* __restrict__ s)
{
    const int bh = blockIdx.z;
    const int b = bh / 3, h = bh % 3;
    const float* A  = q + (size_t)b * 2048 * 2304 + h * 768;
    const float* Bm = k + (size_t)b * 2048 * 2304 + h * 768;
    float* C = s + (size_t)bh * 2048 * 2048;

    const int m0 = blockIdx.y * BM;
    const int n0 = blockIdx.x * BN;
    const int tid = threadIdx.x;
    const int trow = (tid >> 4) * TM;
    const int tcol = (tid & 15) * TN;

    if (n0 >= m0 + BM) {   // fully masked tile
        const float4 neg = make_float4(-99999.f, -99999.f, -99999.f, -99999.f);
        #pragma unroll
        for (int i = 0; i < TM; i++) {
            float4* pr = (float4*)(C + (size_t)(m0 + trow + i) * 2048 + n0 + tcol);
            pr[0] = neg; pr[1] = neg;
        }
        return;
    }

    __shared__ float As[BK][BM + PAD];
    __shared__ float Bs[BK][BN + PAD];
    float acc[TM][TN];
    #pragma unroll
    for (int i = 0; i < TM; i++)
        #pragma unroll
        for (int j = 0; j < TN; j++) acc[i][j] = 0.f;

    for (int k0 = 0; k0 < 768; k0 += BK) {
        #pragma unroll
        for (int i = 0; i < 2; i++) {
            int idx = tid + i * 256;
            int r = idx >> 2, cg = (idx & 3) << 2;
            float4 va = *(const float4*)(A + (size_t)(m0 + r) * 2304 + k0 + cg);
            As[cg + 0][r] = va.x; As[cg + 1][r] = va.y;
            As[cg + 2][r] = va.z; As[cg + 3][r] = va.w;
        }
        #pragma unroll
        for (int i = 0; i < 2; i++) {   // B^T: load rows of K, store transposed
            int idx = tid + i * 256;
            int r = idx >> 2, cg = (idx & 3) << 2;
            float4 vb = *(const float4*)(Bm + (size_t)(n0 + r) * 2304 + k0 + cg);
            Bs[cg + 0][r] = vb.x; Bs[cg + 1][r] = vb.y;
            Bs[cg + 2][r] = vb.z; Bs[cg + 3][r] = vb.w;
        }
        __syncthreads();
        #pragma unroll
        for (int kk = 0; kk < BK; kk++) {
            float ar[TM], br[TN];
            #pragma unroll
            for (int i = 0; i < TM; i++) ar[i] = As[kk][trow + i];
            #pragma unroll
            for (int j = 0; j < TN; j++) br[j] = Bs[kk][tcol + j];
            #pragma unroll
            for (int i = 0; i < TM; i++)
                #pragma unroll
                for (int j = 0; j < TN; j++) acc[i][j] = fmaf(ar[i], br[j], acc[i][j]);
        }
        __syncthreads();
    }

    #pragma unroll
    for (int i = 0; i < TM; i++) {
        const int gi = m0 + trow + i;
        float* cp = C + (size_t)gi * 2048 + n0 + tcol;
        #pragma unroll
        for (int j = 0; j < TN; j++) {
            const int gj = n0 + tcol + j;
            float v = acc[i][j];
            if (gj > gi || v == 0.0f) v = -99999.0f;
            cp[j] = v;
        }
    }
}

// ---------------------------------------------------------------------------
// Row softmax over 2048-wide rows. One block (256 thr) per row.
// ---------------------------------------------------------------------------
__global__ void softmax_kernel(float* __restrict__ s)
{
    float* p = s + (size_t)blockIdx.x * 2048;
    const int tid = threadIdx.x;
    __shared__ float sm[256];

    float v[8];
    float m = -3.4e38f;
    #pragma unroll
    for (int i = 0; i < 8; i++) { v[i] = p[tid + i * 256]; m = fmaxf(m, v[i]); }
    sm[tid] = m; __syncthreads();
    #pragma unroll
    for (int st = 128; st > 0; st >>= 1) {
        if (tid < st) sm[tid] = fmaxf(sm[tid], sm[tid + st]);
        __syncthreads();
    }
    m = sm[0]; __syncthreads();

    float ssum = 0.f;
    #pragma unroll
    for (int i = 0; i < 8; i++) { v[i] = expf(v[i] - m); ssum += v[i]; }
    sm[tid] = ssum; __syncthreads();
    #pragma unroll
    for (int st = 128; st > 0; st >>= 1) {
        if (tid < st) sm[tid] += sm[tid + st];
        __syncthreads();
    }
    const float inv = 1.0f / sm[0];
    #pragma unroll
    for (int i = 0; i < 8; i++) p[tid + i * 256] = v[i] * inv;
}

// ---------------------------------------------------------------------------
// O = P * V per (b,h). P is [2048,2048]; upper triangle is exactly 0 after
// softmax, so truncate the k-loop at the diagonal block (m0+BM).
// ---------------------------------------------------------------------------
__global__ __launch_bounds__(256, 2)
void av_kernel(const float* __restrict__ s, const float* __restrict__ v,
               float* __restrict__ o)
{
    const int bh = blockIdx.z;
    const int b = bh / 3, h = bh % 3;
    const float* A = s + (size_t)bh * 2048 * 2048;
    const float* B = v + (size_t)b * 2048 * 2304 + h * 768;
    float* C = o + (size_t)b * 2048 * 2304 + h * 768;

    const int m0 = blockIdx.y * BM;
    const int n0 = blockIdx.x * BN;
    const int tid = threadIdx.x;
    const int trow = (tid >> 4) * TM;
    const int tcol = (tid & 15) * TN;
    const int kend = m0 + BM;   // causal truncation

    __shared__ float As[BK][BM + PAD];
    __shared__ float Bs[BK][BN + PAD];
    float acc[TM][TN];
    #pragma unroll
    for (int i = 0; i < TM; i++)
        #pragma unroll
        for (int j = 0; j < TN; j++) acc[i][j] = 0.f;

    for (int k0 = 0; k0 < kend; k0 += BK) {
        #pragma unroll
        for (int i = 0; i < 2; i++) {
            int idx = tid + i * 256;
            int r = idx >> 2, cg = (idx & 3) << 2;
            float4 va = *(const float4*)(A + (size_t)(m0 + r) * 2048 + k0 + cg);
            As[cg + 0][r] = va.x; As[cg + 1][r] = va.y;
            As[cg + 2][r] = va.z; As[cg + 3][r] = va.w;
        }
        #pragma unroll
        for (int i = 0; i < 2; i++) {
            int idx = tid + i * 256;
            int r = idx >> 5, c = (idx & 31) << 2;
            *(float4*)&Bs[r][c] = *(const float4*)(B + (size_t)(k0 + r) * 2304 + n0 + c);
        }
        __syncthreads();
        #pragma unroll
        for (int kk = 0; kk < BK; kk++) {
            float ar[TM], br[TN];
            #pragma unroll
            for (int i = 0; i < TM; i++) ar[i] = As[kk][trow + i];
            #pragma unroll
            for (int j = 0; j < TN; j++) br[j] = Bs[kk][tcol + j];
            #pragma unroll
            for (int i = 0; i < TM; i++)
                #pragma unroll
                for (int j = 0; j < TN; j++) acc[i][j] = fmaf(ar[i], br[j], acc[i][j]);
        }
        __syncthreads();
    }

    #pragma unroll
    for (int i = 0; i < TM; i++) {
        float* cp = C + (size_t)(m0 + trow + i) * 2304 + n0 + tcol;
        #pragma unroll
        for (int j = 0; j < TN; j += 4) {
            float4 o4;
            o4.x = acc[i][j + 0]; o4.y = acc[i][j + 1];
            o4.z = acc[i][j + 2]; o4.w = acc[i][j + 3];
            *(float4*)(cp + j) = o4;
        }
    }
}

// ---------------------------------------------------------------------------
// Deterministic mean reduction over g_a (8192*768 = 6291456 floats), 2 stages.
// ---------------------------------------------------------------------------
__global__ void reduce_partial(const float* __restrict__ a, float* __restrict__ part)
{
    const int n = 8192 * 768;
    float s = 0.f;
    for (int i = blockIdx.x * 256 + threadIdx.x; i < n; i += 1024 * 256) s += a[i];
    __shared__ float sm[256];
    sm[threadIdx.x] = s; __syncthreads();
    #pragma unroll
    for (int st = 128; st > 0; st >>= 1) {
        if (threadIdx.x < st) sm[threadIdx.x] += sm[threadIdx.x + st];
        __syncthreads();
    }
    if (threadIdx.x == 0) part[blockIdx.x] = sm[0];
}

__global__ void reduce_final(const float* __restrict__ part, float* __restrict__ mean)
{
    float s = 0.f;
    for (int i = threadIdx.x; i < 1024; i += 256) s += part[i];
    __shared__ float sm[256];
    sm[threadIdx.x] = s; __syncthreads();
    #pragma unroll
    for (int st = 128; st > 0; st >>= 1) {
        if (threadIdx.x < st) sm[threadIdx.x] += sm[threadIdx.x + st];
        __syncthreads();
    }
    if (threadIdx.x == 0) mean[0] = sm[0] * (1.0f / (8192.0f * 768.0f));
}

// ---------------------------------------------------------------------------
// Final: out = leaky_relu((a - mean + x) @ Wf + bf, 0.01)
// A-operand synthesized at smem-load time.
// ---------------------------------------------------------------------------
__global__ __launch_bounds__(256, 2)
void final_kernel(const float* __restrict__ a, const float* __restrict__ x,
                  const float* __restrict__ Wf, const float* __restrict__ bf,
                  const float* __restrict__ meanp, float* __restrict__ out)
{
    const float mean = meanp[0];
    const int m0 = blockIdx.y * BM;
    const int n0 = blockIdx.x * BN;
    const int tid = threadIdx.x;
    const int trow = (tid >> 4) * TM;
    const int tcol = (tid & 15) * TN;

    __shared__ float As[BK][BM + PAD];
    __shared__ float Bs[BK][BN + PAD];
    float acc[TM][TN];
    #pragma unroll
    for (int i = 0; i < TM; i++)
        #pragma unroll
        for (int j = 0; j < TN; j++) acc[i][j] = 0.f;

    for (int k0 = 0; k0 < 768; k0 += BK) {
        #pragma unroll
        for (int i = 0; i < 2; i++) {
            int idx = tid + i * 256;
            int r = idx >> 2, cg = (idx & 3) << 2;
            size_t off = (size_t)(m0 + r) * 768 + k0 + cg;
            float4 va = *(const float4*)(a + off);
            float4 vx = *(const float4*)(x + off);
            As[cg + 0][r] = va.x - mean + vx.x;
            As[cg + 1][r] = va.y - mean + vx.y;
            As[cg + 2][r] = va.z - mean + vx.z;
            As[cg + 3][r] = va.w - mean + vx.w;
        }
        #pragma unroll
        for (int i = 0; i < 2; i++) {
            int idx = tid + i * 256;
            int r = idx >> 5, c = (idx & 31) << 2;
            *(float4*)&Bs[r][c] = *(const float4*)(Wf + (size_t)(k0 + r) * 768 + n0 + c);
        }
        __syncthreads();
        #pragma unroll
        for (int kk = 0; kk < BK; kk++) {
            float ar[TM], br[TN];
            #pragma unroll
            for (int i = 0; i < TM; i++) ar[i] = As[kk][trow + i];
            #pragma unroll
            for (int j = 0; j < TN; j++) br[j] = Bs[kk][tcol + j];
            #pragma unroll
            for (int i = 0; i < TM; i++)
                #pragma unroll
                for (int j = 0; j < TN; j++) acc[i][j] = fmaf(ar[i], br[j], acc[i][j]);
        }
        __syncthreads();
    }

    #pragma unroll
    for (int i = 0; i < TM; i++) {
        float* cp = out + (size_t)(m0 + trow + i) * 768 + n0 + tcol;
        #pragma unroll
        for (int j = 0; j < TN; j += 4) {
            float4 v;
            float t0 = acc[i][j + 0] + bf[n0 + tcol + j + 0];
            float t1 = acc[i][j + 1] + bf[n0 + tcol + j + 1];
            float t2 = acc[i][j + 2] + bf[n0 + tcol + j + 2];
            float t3 = acc[i][j + 3] + bf[n0 + tcol + j + 3];
            v.x = t0 > 0.f ? t0 : 0.01f * t0;
            v.y = t1 > 0.f ? t1 : 0.01f * t1;
            v.z = t2 > 0.f ? t2 : 0.01f * t2;
            v.w = t3 > 0.f ? t3 : 0.01f * t3;
            *(float4*)(cp + j) = v;
        }
    }
}

// ---------------------------------------------------------------------------
extern "C" void kernel_launch(void* const* d_in, const int* in_sizes, int n_in,
                              void* d_out, int out_size)
{
    const float* x  = (const float*)d_in[0];
    const float* Wq = (const float*)d_in[1];
    const float* bq = (const float*)d_in[2];
    const float* Wk = (const float*)d_in[3];
    const float* bk = (const float*)d_in[4];
    const float* Wv = (const float*)d_in[5];
    const float* bv = (const float*)d_in[6];
    const float* Wo = (const float*)d_in[7];
    const float* bo = (const float*)d_in[8];
    const float* Wf = (const float*)d_in[9];
    const float* bf = (const float*)d_in[10];
    float* out = (float*)d_out;

    float *q, *k, *v, *s, *o, *a, *part, *mean;
    cudaGetSymbolAddress((void**)&q, g_q);
    cudaGetSymbolAddress((void**)&k, g_k);
    cudaGetSymbolAddress((void**)&v, g_v);
    cudaGetSymbolAddress((void**)&s, g_s);
    cudaGetSymbolAddress((void**)&o, g_o);
    cudaGetSymbolAddress((void**)&a, g_a);
    cudaGetSymbolAddress((void**)&part, g_part);
    cudaGetSymbolAddress((void**)&mean, g_mean);

    // 1) QKV projections: [8192,768] @ [768,2304] + bias
    dim3 qkvGrid(2304 / BN, 8192 / BM);
    sgemm_nn_bias<<<qkvGrid, 256>>>(x, 768, Wq, 2304, bq, q, 2304, 768);
    sgemm_nn_bias<<<qkvGrid, 256>>>(x, 768, Wk, 2304, bk, k, 2304, 768);
    sgemm_nn_bias<<<qkvGrid, 256>>>(x, 768, Wv, 2304, bv, v, 2304, 768);

    // 2) scores = q k^T (per b,h) + mask
    scores_kernel<<<dim3(2048 / BN, 2048 / BM, 12), 256>>>(q, k, s);

    // 3) row softmax
    softmax_kernel<<<12 * 2048, 256>>>(s);

    // 4) o = attn @ v (causal-truncated k-loop)
    av_kernel<<<dim3(768 / BN, 2048 / BM, 12), 256>>>(s, v, o);

    // 5) a = o @ Wo + bo
    sgemm_nn_bias<<<dim3(768 / BN, 8192 / BM), 256>>>(o, 2304, Wo, 768, bo, a, 768, 2304);

    // 6) deterministic global mean of a
    reduce_partial<<<1024, 256>>>(a, part);
    reduce_final<<<1, 256>>>(part, mean);

    // 7) out = leaky_relu((a - mean + x) @ Wf + bf)
    final_kernel<<<dim3(768 / BN, 8192 / BM), 256>>>(a, x, Wf, bf, mean, out);
}

// round 5
// speedup vs baseline: 2.8760x; 2.8760x over previous
#include <cuda_runtime.h>
#include <cuda_bf16.h>
#include <cstdint>
#include <cstddef>

// ===========================================================================
// B=4, S=2048, D=768, H=3.  MTOK=8192, DQKV=2304.
// All GEMMs: bf16 split-3 (AhBh + AhBl + AlBh) on mma.sync.m16n8k16 HMMA.
// (tcgen05 is unavailable: harness PTX targets sm_103 without the 'a' feature.)
// ===========================================================================

#define MTOK 8192
#define DMODEL 768
#define DQKV 2304
#define SEQ 2048
#define NBH 12

#define TILE_B 16384          // 128 rows x 128B (64 bf16)
#define STAGE_B (4 * TILE_B)  // Ah, Al, Bh, Bl
#define DYN_SMEM (2 * STAGE_B) // 131072

// ---------------------------------------------------------------------------
// PTX helpers (non-'a' ISA only)
// ---------------------------------------------------------------------------
__device__ __forceinline__ uint32_t smem_to_u32(const void* p) {
    uint32_t a;
    asm("{ .reg .u64 t; cvta.to.shared.u64 t, %1; cvt.u32.u64 %0, t; }" : "=r"(a) : "l"(p));
    return a;
}

__device__ __forceinline__ void ldmatrix_x4(uint32_t* r, uint32_t addr) {
    asm volatile("ldmatrix.sync.aligned.m8n8.x4.shared.b16 {%0,%1,%2,%3}, [%4];"
                 : "=r"(r[0]), "=r"(r[1]), "=r"(r[2]), "=r"(r[3]) : "r"(addr));
}

__device__ __forceinline__ void mma16816(float* c, const uint32_t* a, const uint32_t* b) {
    asm volatile(
        "mma.sync.aligned.m16n8k16.row.col.f32.bf16.bf16.f32 "
        "{%0,%1,%2,%3}, {%4,%5,%6,%7}, {%8,%9}, {%0,%1,%2,%3};"
        : "+f"(c[0]), "+f"(c[1]), "+f"(c[2]), "+f"(c[3])
        : "r"(a[0]), "r"(a[1]), "r"(a[2]), "r"(a[3]), "r"(b[0]), "r"(b[1]));
}

#define CP_ASYNC16(dst, src) \
    asm volatile("cp.async.cg.shared.global [%0], [%1], 16;" :: "r"(dst), "l"(src))
#define CP_COMMIT() asm volatile("cp.async.commit_group;" ::: "memory")
#define CP_WAIT0()  asm volatile("cp.async.wait_group 0;" ::: "memory")
#define CP_WAIT1()  asm volatile("cp.async.wait_group 1;" ::: "memory")

// swizzled 16B-chunk offset inside a [128][64 bf16] tile (128B rows)
__device__ __forceinline__ uint32_t swz(int r, int g) {
    return (uint32_t)(r * 128 + ((g ^ (r & 7)) << 4));
}

// ---------------------------------------------------------------------------
// Scratch (allocation-free device globals)
// ---------------------------------------------------------------------------
__device__ __nv_bfloat16 g_xh[(size_t)MTOK * DMODEL], g_xl[(size_t)MTOK * DMODEL];
__device__ __nv_bfloat16 g_wqth[(size_t)DQKV * DMODEL], g_wqtl[(size_t)DQKV * DMODEL];
__device__ __nv_bfloat16 g_wkth[(size_t)DQKV * DMODEL], g_wktl[(size_t)DQKV * DMODEL];
__device__ __nv_bfloat16 g_wvth[(size_t)DQKV * DMODEL], g_wvtl[(size_t)DQKV * DMODEL];
__device__ __nv_bfloat16 g_woth[(size_t)DMODEL * DQKV], g_wotl[(size_t)DMODEL * DQKV];
__device__ __nv_bfloat16 g_wfth[(size_t)DMODEL * DMODEL], g_wftl[(size_t)DMODEL * DMODEL];
__device__ __nv_bfloat16 g_qh[(size_t)MTOK * DQKV], g_ql[(size_t)MTOK * DQKV];
__device__ __nv_bfloat16 g_kh[(size_t)MTOK * DQKV], g_kl[(size_t)MTOK * DQKV];
__device__ __nv_bfloat16 g_vth[(size_t)NBH * DMODEL * SEQ], g_vtl[(size_t)NBH * DMODEL * SEQ];
__device__ float         g_s[(size_t)NBH * SEQ * SEQ];
__device__ __nv_bfloat16 g_ph[(size_t)NBH * SEQ * SEQ], g_pl[(size_t)NBH * SEQ * SEQ];
__device__ __nv_bfloat16 g_oh[(size_t)MTOK * DQKV], g_ol[(size_t)MTOK * DQKV];
__device__ float         g_a[(size_t)MTOK * DMODEL];
__device__ __nv_bfloat16 g_nh[(size_t)MTOK * DMODEL], g_nl[(size_t)MTOK * DMODEL];
__device__ float         g_part[1024];
__device__ float         g_mean[1];

// ---------------------------------------------------------------------------
// GEMM engine
// ---------------------------------------------------------------------------
__device__ __forceinline__ void load_tile_async(uint32_t sbase,
                                                const __nv_bfloat16* __restrict__ G,
                                                int ld, int row0, int k0) {
    const int t = threadIdx.x;
    const int g = t & 7;
    const int r = t >> 3;                 // 0..31
    const __nv_bfloat16* src = G + (size_t)(row0 + r) * ld + k0 + g * 8;
    #pragma unroll
    for (int p = 0; p < 4; p++) {
        CP_ASYNC16(sbase + swz(r + p * 32, g), src + (size_t)p * 32 * ld);
    }
}

__device__ __forceinline__ void compute_chunk(uint32_t sbase, int warp_m, int warp_n,
                                              int lane, float acc[2][8][4]) {
    const int arow = warp_m * 32 + (lane & 7) + ((lane >> 3) & 1) * 8;
    const int brow = warp_n * 64 + (lane & 7) + (lane >> 4) * 8;
    #pragma unroll
    for (int kk = 0; kk < 4; kk++) {
        const int ag = kk * 2 + (lane >> 4);
        const int bg = kk * 2 + ((lane >> 3) & 1);
        uint32_t ah[2][4], al[2][4], bh[4][4], bl[4][4];
        #pragma unroll
        for (int mt = 0; mt < 2; mt++) {
            ldmatrix_x4(ah[mt], sbase + 0 * TILE_B + swz(arow + mt * 16, ag));
            ldmatrix_x4(al[mt], sbase + 1 * TILE_B + swz(arow + mt * 16, ag));
        }
        #pragma unroll
        for (int nt2 = 0; nt2 < 4; nt2++) {
            ldmatrix_x4(bh[nt2], sbase + 2 * TILE_B + swz(brow + nt2 * 16, bg));
            ldmatrix_x4(bl[nt2], sbase + 3 * TILE_B + swz(brow + nt2 * 16, bg));
        }
        #pragma unroll
        for (int mt = 0; mt < 2; mt++)
            #pragma unroll
            for (int nt = 0; nt < 8; nt++) {
                const uint32_t* pbh = &bh[nt >> 1][(nt & 1) * 2];
                const uint32_t* pbl = &bl[nt >> 1][(nt & 1) * 2];
                mma16816(acc[mt][nt], ah[mt], pbh);
                mma16816(acc[mt][nt], ah[mt], pbl);
                mma16816(acc[mt][nt], al[mt], pbh);
            }
    }
}

// D[128,128] = sum_K (AhBh + AhBl + AlBh), NT form (both operands k-contiguous)
__device__ void mma_mainloop(const __nv_bfloat16* __restrict__ Ah,
                             const __nv_bfloat16* __restrict__ Al, int lda, int arow0,
                             const __nv_bfloat16* __restrict__ Bh,
                             const __nv_bfloat16* __restrict__ Bl, int ldb, int brow0,
                             int K, uint32_t sb, float acc[2][8][4]) {
    const int C = K >> 6;
    const int warp = threadIdx.x >> 5, lane = threadIdx.x & 31;
    const int warp_m = warp & 3, warp_n = warp >> 2;

    #pragma unroll
    for (int mt = 0; mt < 2; mt++)
        #pragma unroll
        for (int nt = 0; nt < 8; nt++)
            #pragma unroll
            for (int i = 0; i < 4; i++) acc[mt][nt][i] = 0.f;

    // prologue: stage 0
    load_tile_async(sb + 0 * TILE_B, Ah, lda, arow0, 0);
    load_tile_async(sb + 1 * TILE_B, Al, lda, arow0, 0);
    load_tile_async(sb + 2 * TILE_B, Bh, ldb, brow0, 0);
    load_tile_async(sb + 3 * TILE_B, Bl, ldb, brow0, 0);
    CP_COMMIT();

    for (int c = 0; c < C; c++) {
        if (c + 1 < C) {
            const uint32_t st = sb + ((c + 1) & 1) * STAGE_B;
            const int k0 = (c + 1) << 6;
            load_tile_async(st + 0 * TILE_B, Ah, lda, arow0, k0);
            load_tile_async(st + 1 * TILE_B, Al, lda, arow0, k0);
            load_tile_async(st + 2 * TILE_B, Bh, ldb, brow0, k0);
            load_tile_async(st + 3 * TILE_B, Bl, ldb, brow0, k0);
            CP_COMMIT();
            CP_WAIT1();
        } else {
            CP_WAIT0();
        }
        __syncthreads();
        compute_chunk(sb + (c & 1) * STAGE_B, warp_m, warp_n, lane, acc);
        __syncthreads();
    }
}

// ---------------------------------------------------------------------------
// Epilogue helpers
// ---------------------------------------------------------------------------
__device__ __forceinline__ void split2(float v, __nv_bfloat16& h, __nv_bfloat16& l) {
    h = __float2bfloat16(v);
    l = __float2bfloat16(v - __bfloat162float(h));
}

__device__ __forceinline__ void split_store2(__nv_bfloat16* __restrict__ H,
                                             __nv_bfloat16* __restrict__ L,
                                             size_t off, float v0, float v1) {
    __nv_bfloat16 h0, h1, l0, l1;
    split2(v0, h0, l0); split2(v1, h1, l1);
    *(__nv_bfloat162*)(H + off) = __halves2bfloat162(h0, h1);
    *(__nv_bfloat162*)(L + off) = __halves2bfloat162(l0, l1);
}

// Split-store 64 consecutive values (bf16 hi/lo) — for V-transpose epilogue
__device__ __forceinline__ void store_split64(__nv_bfloat16* __restrict__ H,
                                              __nv_bfloat16* __restrict__ L,
                                              size_t off, const float* v) {
    uint32_t hp[32], lp[32];
    #pragma unroll
    for (int j = 0; j < 64; j += 2) {
        __nv_bfloat16 h0, h1, l0, l1;
        split2(v[j], h0, l0); split2(v[j + 1], h1, l1);
        __nv_bfloat162 hh = __halves2bfloat162(h0, h1);
        __nv_bfloat162 ll = __halves2bfloat162(l0, l1);
        hp[j >> 1] = reinterpret_cast<uint32_t&>(hh);
        lp[j >> 1] = reinterpret_cast<uint32_t&>(ll);
    }
    #pragma unroll
    for (int i = 0; i < 8; i++) {
        *(uint4*)((char*)(H + off) + i * 16) = ((uint4*)hp)[i];
        *(uint4*)((char*)(L + off) + i * 16) = ((uint4*)lp)[i];
    }
}

// per-thread fragment coordinates
#define FRAG_COORDS() \
    const int warp = threadIdx.x >> 5, lane = threadIdx.x & 31; \
    const int warp_m = warp & 3, warp_n = warp >> 2; \
    const int gid = lane >> 2, t4 = lane & 3;

// ---------------------------------------------------------------------------
// GEMM kernels
// ---------------------------------------------------------------------------

// C = A*B^T + bias, split-bf16 out (Q, K projections)
__global__ __launch_bounds__(256, 1)
void k_gemm_bias_split(const __nv_bfloat16* __restrict__ Ah, const __nv_bfloat16* __restrict__ Al, int lda,
                       const __nv_bfloat16* __restrict__ Bh, const __nv_bfloat16* __restrict__ Bl, int ldb,
                       const float* __restrict__ bias,
                       __nv_bfloat16* __restrict__ Ch, __nv_bfloat16* __restrict__ Cl, int ldc, int K) {
    extern __shared__ char smem[];
    const uint32_t sb = smem_to_u32(smem);
    const int m0 = blockIdx.y * 128, n0 = blockIdx.x * 128;
    float acc[2][8][4];
    mma_mainloop(Ah, Al, lda, m0, Bh, Bl, ldb, n0, K, sb, acc);
    FRAG_COORDS();
    #pragma unroll
    for (int mt = 0; mt < 2; mt++)
        #pragma unroll
        for (int nt = 0; nt < 8; nt++) {
            const int col = n0 + warp_n * 64 + nt * 8 + t4 * 2;
            const float bx = bias[col], by = bias[col + 1];
            const int r0 = m0 + warp_m * 32 + mt * 16 + gid;
            split_store2(Ch, Cl, (size_t)r0 * ldc + col, acc[mt][nt][0] + bx, acc[mt][nt][1] + by);
            split_store2(Ch, Cl, (size_t)(r0 + 8) * ldc + col, acc[mt][nt][2] + bx, acc[mt][nt][3] + by);
        }
}

// V projection: writes transposed vT[bh][dim][token] split-bf16
__global__ __launch_bounds__(256, 1)
void k_gemm_v(const __nv_bfloat16* __restrict__ Ah, const __nv_bfloat16* __restrict__ Al,
              const __nv_bfloat16* __restrict__ Bh, const __nv_bfloat16* __restrict__ Bl,
              const float* __restrict__ bias,
              __nv_bfloat16* __restrict__ VTh, __nv_bfloat16* __restrict__ VTl) {
    extern __shared__ char smem[];
    const uint32_t sb = smem_to_u32(smem);
    const int m0 = blockIdx.y * 128, n0 = blockIdx.x * 128;
    float acc[2][8][4];
    mma_mainloop(Ah, Al, DMODEL, m0, Bh, Bl, DMODEL, n0, DMODEL, sb, acc);
    FRAG_COORDS();

    float* smf = (float*)smem;  // [128][129]
    __syncthreads();
    #pragma unroll
    for (int mt = 0; mt < 2; mt++)
        #pragma unroll
        for (int nt = 0; nt < 8; nt++) {
            const int lc = warp_n * 64 + nt * 8 + t4 * 2;
            const float bx = bias[n0 + lc], by = bias[n0 + lc + 1];
            const int lr = warp_m * 32 + mt * 16 + gid;
            smf[lr * 129 + lc] = acc[mt][nt][0] + bx;
            smf[lr * 129 + lc + 1] = acc[mt][nt][1] + by;
            smf[(lr + 8) * 129 + lc] = acc[mt][nt][2] + bx;
            smf[(lr + 8) * 129 + lc + 1] = acc[mt][nt][3] + by;
        }
    __syncthreads();

    const int b = m0 / SEQ, tok0 = m0 % SEQ;
    const int h = n0 / DMODEL, dim0 = n0 % DMODEL;
    const int c = threadIdx.x & 127;
    const int seg = threadIdx.x >> 7;
    float vv[64];
    #pragma unroll
    for (int i = 0; i < 64; i++) vv[i] = smf[(seg * 64 + i) * 129 + c];
    const size_t off = ((size_t)(b * 3 + h) * DMODEL + dim0 + c) * SEQ + tok0 + seg * 64;
    store_split64(VTh, VTl, off, vv);
}

// scores = q k^T per (b,h) + exact reference masking, fp32; skip masked tiles
__global__ __launch_bounds__(256, 1)
void k_scores(const __nv_bfloat16* __restrict__ qh, const __nv_bfloat16* __restrict__ ql,
              const __nv_bfloat16* __restrict__ kh, const __nv_bfloat16* __restrict__ kl,
              float* __restrict__ s) {
    const int bh = blockIdx.z;
    const int b = bh / 3, h = bh % 3;
    const int m0 = blockIdx.y * 128, n0 = blockIdx.x * 128;
    float* C = s + (size_t)bh * SEQ * SEQ;

    if (n0 > m0) {  // fully masked tile
        const int r = threadIdx.x >> 1, half = threadIdx.x & 1;
        float4* p = (float4*)(C + (size_t)(m0 + r) * SEQ + n0 + half * 64);
        const float4 neg = make_float4(-99999.f, -99999.f, -99999.f, -99999.f);
        #pragma unroll
        for (int i = 0; i < 16; i++) p[i] = neg;
        return;
    }

    extern __shared__ char smem[];
    const uint32_t sb = smem_to_u32(smem);
    float acc[2][8][4];
    mma_mainloop(qh + h * DMODEL, ql + h * DMODEL, DQKV, b * SEQ + m0,
                 kh + h * DMODEL, kl + h * DMODEL, DQKV, b * SEQ + n0,
                 DMODEL, sb, acc);
    FRAG_COORDS();
    #pragma unroll
    for (int mt = 0; mt < 2; mt++)
        #pragma unroll
        for (int nt = 0; nt < 8; nt++) {
            const int gj = n0 + warp_n * 64 + nt * 8 + t4 * 2;
            #pragma unroll
            for (int half = 0; half < 2; half++) {
                const int gi = m0 + warp_m * 32 + mt * 16 + gid + half * 8;
                float v0 = acc[mt][nt][half * 2];
                float v1 = acc[mt][nt][half * 2 + 1];
                if (gj > gi || v0 == 0.0f) v0 = -99999.0f;
                if (gj + 1 > gi || v1 == 0.0f) v1 = -99999.0f;
                *(float2*)(C + (size_t)gi * SEQ + gj) = make_float2(v0, v1);
            }
        }
}

// o = attn @ v per (b,h); K truncated at diagonal; split-bf16 out [8192,2304]
__global__ __launch_bounds__(256, 1)
void k_pv(const __nv_bfloat16* __restrict__ ph, const __nv_bfloat16* __restrict__ pl,
          const __nv_bfloat16* __restrict__ vth, const __nv_bfloat16* __restrict__ vtl,
          __nv_bfloat16* __restrict__ oh, __nv_bfloat16* __restrict__ ol) {
    extern __shared__ char smem[];
    const uint32_t sb = smem_to_u32(smem);
    const int bh = blockIdx.z;
    const int b = bh / 3, h = bh % 3;
    const int m0 = blockIdx.y * 128, n0 = blockIdx.x * 128;
    float acc[2][8][4];
    mma_mainloop(ph + (size_t)bh * SEQ * SEQ, pl + (size_t)bh * SEQ * SEQ, SEQ, m0,
                 vth + (size_t)bh * DMODEL * SEQ, vtl + (size_t)bh * DMODEL * SEQ, SEQ, n0,
                 m0 + 128, sb, acc);
    FRAG_COORDS();
    #pragma unroll
    for (int mt = 0; mt < 2; mt++)
        #pragma unroll
        for (int nt = 0; nt < 8; nt++) {
            const int col = h * DMODEL + n0 + warp_n * 64 + nt * 8 + t4 * 2;
            const int r0 = b * SEQ + m0 + warp_m * 32 + mt * 16 + gid;
            split_store2(oh, ol, (size_t)r0 * DQKV + col, acc[mt][nt][0], acc[mt][nt][1]);
            split_store2(oh, ol, (size_t)(r0 + 8) * DQKV + col, acc[mt][nt][2], acc[mt][nt][3]);
        }
}

// C = A*B^T + bias, fp32 out (Wo projection)
__global__ __launch_bounds__(256, 1)
void k_gemm_bias_f32(const __nv_bfloat16* __restrict__ Ah, const __nv_bfloat16* __restrict__ Al, int lda,
                     const __nv_bfloat16* __restrict__ Bh, const __nv_bfloat16* __restrict__ Bl, int ldb,
                     const float* __restrict__ bias, float* __restrict__ C, int ldc, int K) {
    extern __shared__ char smem[];
    const uint32_t sb = smem_to_u32(smem);
    const int m0 = blockIdx.y * 128, n0 = blockIdx.x * 128;
    float acc[2][8][4];
    mma_mainloop(Ah, Al, lda, m0, Bh, Bl, ldb, n0, K, sb, acc);
    FRAG_COORDS();
    #pragma unroll
    for (int mt = 0; mt < 2; mt++)
        #pragma unroll
        for (int nt = 0; nt < 8; nt++) {
            const int col = n0 + warp_n * 64 + nt * 8 + t4 * 2;
            const float bx = bias[col], by = bias[col + 1];
            const int r0 = m0 + warp_m * 32 + mt * 16 + gid;
            *(float2*)(C + (size_t)r0 * ldc + col) =
                make_float2(acc[mt][nt][0] + bx, acc[mt][nt][1] + by);
            *(float2*)(C + (size_t)(r0 + 8) * ldc + col) =
                make_float2(acc[mt][nt][2] + bx, acc[mt][nt][3] + by);
        }
}

// final: out = leaky_relu(A*Wf^T + bf)
__global__ __launch_bounds__(256, 1)
void k_final(const __nv_bfloat16* __restrict__ Ah, const __nv_bfloat16* __restrict__ Al,
             const __nv_bfloat16* __restrict__ Bh, const __nv_bfloat16* __restrict__ Bl,
             const float* __restrict__ bias, float* __restrict__ out) {
    extern __shared__ char smem[];
    const uint32_t sb = smem_to_u32(smem);
    const int m0 = blockIdx.y * 128, n0 = blockIdx.x * 128;
    float acc[2][8][4];
    mma_mainloop(Ah, Al, DMODEL, m0, Bh, Bl, DMODEL, n0, DMODEL, sb, acc);
    FRAG_COORDS();
    #pragma unroll
    for (int mt = 0; mt < 2; mt++)
        #pragma unroll
        for (int nt = 0; nt < 8; nt++) {
            const int col = n0 + warp_n * 64 + nt * 8 + t4 * 2;
            const float bx = bias[col], by = bias[col + 1];
            const int r0 = m0 + warp_m * 32 + mt * 16 + gid;
            float t0 = acc[mt][nt][0] + bx, t1 = acc[mt][nt][1] + by;
            float t2 = acc[mt][nt][2] + bx, t3 = acc[mt][nt][3] + by;
            t0 = t0 > 0.f ? t0 : 0.01f * t0;
            t1 = t1 > 0.f ? t1 : 0.01f * t1;
            t2 = t2 > 0.f ? t2 : 0.01f * t2;
            t3 = t3 > 0.f ? t3 : 0.01f * t3;
            *(float2*)(out + (size_t)r0 * DMODEL + col) = make_float2(t0, t1);
            *(float2*)(out + (size_t)(r0 + 8) * DMODEL + col) = make_float2(t2, t3);
        }
}

// ---------------------------------------------------------------------------
// Non-GEMM kernels
// ---------------------------------------------------------------------------
__global__ void split_kernel(const float* __restrict__ src,
                             __nv_bfloat16* __restrict__ H, __nv_bfloat16* __restrict__ L, int n) {
    int i = (blockIdx.x * 256 + threadIdx.x) * 4;
    if (i >= n) return;
    float4 v = *(const float4*)(src + i);
    __nv_bfloat16 h0, h1, h2, h3, l0, l1, l2, l3;
    split2(v.x, h0, l0); split2(v.y, h1, l1); split2(v.z, h2, l2); split2(v.w, h3, l3);
    __nv_bfloat162 a = __halves2bfloat162(h0, h1), b2 = __halves2bfloat162(h2, h3);
    __nv_bfloat162 c = __halves2bfloat162(l0, l1), d = __halves2bfloat162(l2, l3);
    uint2 hp, lp;
    hp.x = reinterpret_cast<uint32_t&>(a); hp.y = reinterpret_cast<uint32_t&>(b2);
    lp.x = reinterpret_cast<uint32_t&>(c); lp.y = reinterpret_cast<uint32_t&>(d);
    *(uint2*)(H + i) = hp;
    *(uint2*)(L + i) = lp;
}

// W[K,N] fp32 -> Wt[N,K] split-bf16
__global__ void transpose_split_kernel(const float* __restrict__ W, int K, int N,
                                       __nv_bfloat16* __restrict__ TH, __nv_bfloat16* __restrict__ TL) {
    __shared__ float t[32][33];
    const int n0 = blockIdx.x * 32, k0 = blockIdx.y * 32;
    const int tx = threadIdx.x, ty = threadIdx.y;
    #pragma unroll
    for (int i = ty; i < 32; i += 8)
        t[i][tx] = W[(size_t)(k0 + i) * N + n0 + tx];
    __syncthreads();
    #pragma unroll
    for (int i = ty; i < 32; i += 8) {
        float v = t[tx][i];
        __nv_bfloat16 h, l;
        split2(v, h, l);
        const size_t off = (size_t)(n0 + i) * K + k0 + tx;
        TH[off] = h;
        TL[off] = l;
    }
}

// row softmax over 2048; writes split-bf16 probabilities
__global__ void softmax_split_kernel(const float* __restrict__ s,
                                     __nv_bfloat16* __restrict__ PH, __nv_bfloat16* __restrict__ PL) {
    const float* p = s + (size_t)blockIdx.x * SEQ;
    __nv_bfloat16* ph = PH + (size_t)blockIdx.x * SEQ;
    __nv_bfloat16* pl = PL + (size_t)blockIdx.x * SEQ;
    const int tid = threadIdx.x;
    __shared__ float sm[256];

    float v[8];
    float m = -3.4e38f;
    #pragma unroll
    for (int i = 0; i < 8; i++) { v[i] = p[tid + i * 256]; m = fmaxf(m, v[i]); }
    sm[tid] = m; __syncthreads();
    #pragma unroll
    for (int st = 128; st > 0; st >>= 1) {
        if (tid < st) sm[tid] = fmaxf(sm[tid], sm[tid + st]);
        __syncthreads();
    }
    m = sm[0]; __syncthreads();

    float ssum = 0.f;
    #pragma unroll
    for (int i = 0; i < 8; i++) { v[i] = expf(v[i] - m); ssum += v[i]; }
    sm[tid] = ssum; __syncthreads();
    #pragma unroll
    for (int st = 128; st > 0; st >>= 1) {
        if (tid < st) sm[tid] += sm[tid + st];
        __syncthreads();
    }
    const float inv = 1.0f / sm[0];
    #pragma unroll
    for (int i = 0; i < 8; i++) {
        float pv = v[i] * inv;
        __nv_bfloat16 h, l;
        split2(pv, h, l);
        ph[tid + i * 256] = h;
        pl[tid + i * 256] = l;
    }
}

__global__ void reduce_partial(const float* __restrict__ a, float* __restrict__ part) {
    const int n = MTOK * DMODEL;
    float s = 0.f;
    for (int i = blockIdx.x * 256 + threadIdx.x; i < n; i += 1024 * 256) s += a[i];
    __shared__ float sm[256];
    sm[threadIdx.x] = s; __syncthreads();
    #pragma unroll
    for (int st = 128; st > 0; st >>= 1) {
        if (threadIdx.x < st) sm[threadIdx.x] += sm[threadIdx.x + st];
        __syncthreads();
    }
    if (threadIdx.x == 0) part[blockIdx.x] = sm[0];
}

__global__ void reduce_final(const float* __restrict__ part, float* __restrict__ mean) {
    float s = 0.f;
    for (int i = threadIdx.x; i < 1024; i += 256) s += part[i];
    __shared__ float sm[256];
    sm[threadIdx.x] = s; __syncthreads();
    #pragma unroll
    for (int st = 128; st > 0; st >>= 1) {
        if (threadIdx.x < st) sm[threadIdx.x] += sm[threadIdx.x + st];
        __syncthreads();
    }
    if (threadIdx.x == 0) mean[0] = sm[0] * (1.0f / ((float)MTOK * DMODEL));
}

// n = a - mean + x, split-bf16
__global__ void fuse_split_kernel(const float* __restrict__ a, const float* __restrict__ x,
                                  const float* __restrict__ meanp,
                                  __nv_bfloat16* __restrict__ NH, __nv_bfloat16* __restrict__ NL, int n) {
    const float mean = meanp[0];
    int i = (blockIdx.x * 256 + threadIdx.x) * 4;
    if (i >= n) return;
    float4 va = *(const float4*)(a + i);
    float4 vx = *(const float4*)(x + i);
    float f0 = va.x - mean + vx.x, f1 = va.y - mean + vx.y;
    float f2 = va.z - mean + vx.z, f3 = va.w - mean + vx.w;
    __nv_bfloat16 h0, h1, h2, h3, l0, l1, l2, l3;
    split2(f0, h0, l0); split2(f1, h1, l1); split2(f2, h2, l2); split2(f3, h3, l3);
    __nv_bfloat162 aa = __halves2bfloat162(h0, h1), bb = __halves2bfloat162(h2, h3);
    __nv_bfloat162 cc = __halves2bfloat162(l0, l1), dd = __halves2bfloat162(l2, l3);
    uint2 hp, lp;
    hp.x = reinterpret_cast<uint32_t&>(aa); hp.y = reinterpret_cast<uint32_t&>(bb);
    lp.x = reinterpret_cast<uint32_t&>(cc); lp.y = reinterpret_cast<uint32_t&>(dd);
    *(uint2*)(NH + i) = hp;
    *(uint2*)(NL + i) = lp;
}

// ---------------------------------------------------------------------------
extern "C" void kernel_launch(void* const* d_in, const int* in_sizes, int n_in,
                              void* d_out, int out_size) {
    const float* x  = (const float*)d_in[0];
    const float* Wq = (const float*)d_in[1];
    const float* bq = (const float*)d_in[2];
    const float* Wk = (const float*)d_in[3];
    const float* bk = (const float*)d_in[4];
    const float* Wv = (const float*)d_in[5];
    const float* bv = (const float*)d_in[6];
    const float* Wo = (const float*)d_in[7];
    const float* bo = (const float*)d_in[8];
    const float* Wf = (const float*)d_in[9];
    const float* bf = (const float*)d_in[10];
    float* out = (float*)d_out;

    static bool attr_done = false;
    if (!attr_done) {
        cudaFuncSetAttribute(k_gemm_bias_split, cudaFuncAttributeMaxDynamicSharedMemorySize, DYN_SMEM);
        cudaFuncSetAttribute(k_gemm_v,          cudaFuncAttributeMaxDynamicSharedMemorySize, DYN_SMEM);
        cudaFuncSetAttribute(k_scores,          cudaFuncAttributeMaxDynamicSharedMemorySize, DYN_SMEM);
        cudaFuncSetAttribute(k_pv,              cudaFuncAttributeMaxDynamicSharedMemorySize, DYN_SMEM);
        cudaFuncSetAttribute(k_gemm_bias_f32,   cudaFuncAttributeMaxDynamicSharedMemorySize, DYN_SMEM);
        cudaFuncSetAttribute(k_final,           cudaFuncAttributeMaxDynamicSharedMemorySize, DYN_SMEM);
        attr_done = true;
    }

    __nv_bfloat16 *xh, *xl, *wqth, *wqtl, *wkth, *wktl, *wvth, *wvtl, *woth, *wotl, *wfth, *wftl;
    __nv_bfloat16 *qh, *ql, *kh, *kl, *vth, *vtl, *ph, *pl, *oh, *ol, *nh, *nl;
    float *s, *a, *part, *mean;
    cudaGetSymbolAddress((void**)&xh, g_xh);     cudaGetSymbolAddress((void**)&xl, g_xl);
    cudaGetSymbolAddress((void**)&wqth, g_wqth); cudaGetSymbolAddress((void**)&wqtl, g_wqtl);
    cudaGetSymbolAddress((void**)&wkth, g_wkth); cudaGetSymbolAddress((void**)&wktl, g_wktl);
    cudaGetSymbolAddress((void**)&wvth, g_wvth); cudaGetSymbolAddress((void**)&wvtl, g_wvtl);
    cudaGetSymbolAddress((void**)&woth, g_woth); cudaGetSymbolAddress((void**)&wotl, g_wotl);
    cudaGetSymbolAddress((void**)&wfth, g_wfth); cudaGetSymbolAddress((void**)&wftl, g_wftl);
    cudaGetSymbolAddress((void**)&qh, g_qh);     cudaGetSymbolAddress((void**)&ql, g_ql);
    cudaGetSymbolAddress((void**)&kh, g_kh);     cudaGetSymbolAddress((void**)&kl, g_kl);
    cudaGetSymbolAddress((void**)&vth, g_vth);   cudaGetSymbolAddress((void**)&vtl, g_vtl);
    cudaGetSymbolAddress((void**)&s, g_s);
    cudaGetSymbolAddress((void**)&ph, g_ph);     cudaGetSymbolAddress((void**)&pl, g_pl);
    cudaGetSymbolAddress((void**)&oh, g_oh);     cudaGetSymbolAddress((void**)&ol, g_ol);
    cudaGetSymbolAddress((void**)&a, g_a);
    cudaGetSymbolAddress((void**)&nh, g_nh);     cudaGetSymbolAddress((void**)&nl, g_nl);
    cudaGetSymbolAddress((void**)&part, g_part); cudaGetSymbolAddress((void**)&mean, g_mean);

    // 0) splits / transposes of inputs
    const int nx = MTOK * DMODEL;
    split_kernel<<<(nx / 4 + 255) / 256, 256>>>(x, xh, xl, nx);
    transpose_split_kernel<<<dim3(DQKV / 32, DMODEL / 32), dim3(32, 8)>>>(Wq, DMODEL, DQKV, wqth, wqtl);
    transpose_split_kernel<<<dim3(DQKV / 32, DMODEL / 32), dim3(32, 8)>>>(Wk, DMODEL, DQKV, wkth, wktl);
    transpose_split_kernel<<<dim3(DQKV / 32, DMODEL / 32), dim3(32, 8)>>>(Wv, DMODEL, DQKV, wvth, wvtl);
    transpose_split_kernel<<<dim3(DMODEL / 32, DQKV / 32), dim3(32, 8)>>>(Wo, DQKV, DMODEL, woth, wotl);
    transpose_split_kernel<<<dim3(DMODEL / 32, DMODEL / 32), dim3(32, 8)>>>(Wf, DMODEL, DMODEL, wfth, wftl);

    // 1) Q, K projections (split-bf16 outputs), V projection (transposed out)
    dim3 qkvGrid(DQKV / 128, MTOK / 128);
    k_gemm_bias_split<<<qkvGrid, 256, DYN_SMEM>>>(xh, xl, DMODEL, wqth, wqtl, DMODEL, bq, qh, ql, DQKV, DMODEL);
    k_gemm_bias_split<<<qkvGrid, 256, DYN_SMEM>>>(xh, xl, DMODEL, wkth, wktl, DMODEL, bk, kh, kl, DQKV, DMODEL);
    k_gemm_v<<<qkvGrid, 256, DYN_SMEM>>>(xh, xl, wvth, wvtl, bv, vth, vtl);

    // 2) masked scores
    k_scores<<<dim3(SEQ / 128, SEQ / 128, NBH), 256, DYN_SMEM>>>(qh, ql, kh, kl, s);

    // 3) softmax + split
    softmax_split_kernel<<<NBH * SEQ, 256>>>(s, ph, pl);

    // 4) o = attn @ v (causal-truncated k-loop)
    k_pv<<<dim3(DMODEL / 128, SEQ / 128, NBH), 256, DYN_SMEM>>>(ph, pl, vth, vtl, oh, ol);

    // 5) a = o @ Wo + bo (fp32)
    k_gemm_bias_f32<<<dim3(DMODEL / 128, MTOK / 128), 256, DYN_SMEM>>>(
        oh, ol, DQKV, woth, wotl, DQKV, bo, a, DMODEL, DQKV);

    // 6) deterministic global mean
    reduce_partial<<<1024, 256>>>(a, part);
    reduce_final<<<1, 256>>>(part, mean);

    // 7) n = a - mean + x (split)
    fuse_split_kernel<<<(nx / 4 + 255) / 256, 256>>>(a, x, mean, nh, nl, nx);

    // 8) out = leaky_relu(n @ Wf + bf)
    k_final<<<dim3(DMODEL / 128, MTOK / 128), 256, DYN_SMEM>>>(nh, nl, wfth, wftl, bf, out);
}

// round 8
// speedup vs baseline: 3.0274x; 1.0526x over previous
#include <cuda_runtime.h>
#include <cuda_bf16.h>
#include <cstdint>
#include <cstddef>

// ===========================================================================
// B=4, S=2048, D=768, H=3.  MTOK=8192, DQKV=2304.
// All GEMMs: bf16 split-3 (AhBh + AhBl + AlBh) on mma.sync.m16n8k16 HMMA.
// R6: causal-aware softmax (half the exps), 3-stage cp.async pipeline with
// one __syncthreads per chunk, merged prep launches.
// ===========================================================================

#define MTOK 8192
#define DMODEL 768
#define DQKV 2304
#define SEQ 2048
#define NBH 12

#define TILE_B 16384          // 128 rows x 128B (64 bf16)
#define STAGE_B (4 * TILE_B)  // Ah, Al, Bh, Bl
#define DYN_SMEM (3 * STAGE_B) // 196608 (3 stages)

// ---------------------------------------------------------------------------
// PTX helpers (non-'a' ISA only)
// ---------------------------------------------------------------------------
__device__ __forceinline__ uint32_t smem_to_u32(const void* p) {
    uint32_t a;
    asm("{ .reg .u64 t; cvta.to.shared.u64 t, %1; cvt.u32.u64 %0, t; }" : "=r"(a) : "l"(p));
    return a;
}

__device__ __forceinline__ void ldmatrix_x4(uint32_t* r, uint32_t addr) {
    asm volatile("ldmatrix.sync.aligned.m8n8.x4.shared.b16 {%0,%1,%2,%3}, [%4];"
                 : "=r"(r[0]), "=r"(r[1]), "=r"(r[2]), "=r"(r[3]) : "r"(addr));
}

__device__ __forceinline__ void mma16816(float* c, const uint32_t* a, const uint32_t* b) {
    asm volatile(
        "mma.sync.aligned.m16n8k16.row.col.f32.bf16.bf16.f32 "
        "{%0,%1,%2,%3}, {%4,%5,%6,%7}, {%8,%9}, {%0,%1,%2,%3};"
        : "+f"(c[0]), "+f"(c[1]), "+f"(c[2]), "+f"(c[3])
        : "r"(a[0]), "r"(a[1]), "r"(a[2]), "r"(a[3]), "r"(b[0]), "r"(b[1]));
}

#define CP_ASYNC16(dst, src) \
    asm volatile("cp.async.cg.shared.global [%0], [%1], 16;" :: "r"(dst), "l"(src))
#define CP_COMMIT() asm volatile("cp.async.commit_group;" ::: "memory")
#define CP_WAIT0()  asm volatile("cp.async.wait_group 0;" ::: "memory")
#define CP_WAIT1()  asm volatile("cp.async.wait_group 1;" ::: "memory")

// swizzled 16B-chunk offset inside a [128][64 bf16] tile (128B rows)
__device__ __forceinline__ uint32_t swz(int r, int g) {
    return (uint32_t)(r * 128 + ((g ^ (r & 7)) << 4));
}

// ---------------------------------------------------------------------------
// Scratch (allocation-free device globals)
// ---------------------------------------------------------------------------
__device__ __nv_bfloat16 g_xh[(size_t)MTOK * DMODEL], g_xl[(size_t)MTOK * DMODEL];
__device__ __nv_bfloat16 g_wqth[(size_t)DQKV * DMODEL], g_wqtl[(size_t)DQKV * DMODEL];
__device__ __nv_bfloat16 g_wkth[(size_t)DQKV * DMODEL], g_wktl[(size_t)DQKV * DMODEL];
__device__ __nv_bfloat16 g_wvth[(size_t)DQKV * DMODEL], g_wvtl[(size_t)DQKV * DMODEL];
__device__ __nv_bfloat16 g_woth[(size_t)DMODEL * DQKV], g_wotl[(size_t)DMODEL * DQKV];
__device__ __nv_bfloat16 g_wfth[(size_t)DMODEL * DMODEL], g_wftl[(size_t)DMODEL * DMODEL];
__device__ __nv_bfloat16 g_qh[(size_t)MTOK * DQKV], g_ql[(size_t)MTOK * DQKV];
__device__ __nv_bfloat16 g_kh[(size_t)MTOK * DQKV], g_kl[(size_t)MTOK * DQKV];
__device__ __nv_bfloat16 g_vth[(size_t)NBH * DMODEL * SEQ], g_vtl[(size_t)NBH * DMODEL * SEQ];
__device__ float         g_s[(size_t)NBH * SEQ * SEQ];
__device__ __nv_bfloat16 g_ph[(size_t)NBH * SEQ * SEQ], g_pl[(size_t)NBH * SEQ * SEQ];
__device__ __nv_bfloat16 g_oh[(size_t)MTOK * DQKV], g_ol[(size_t)MTOK * DQKV];
__device__ float         g_a[(size_t)MTOK * DMODEL];
__device__ __nv_bfloat16 g_nh[(size_t)MTOK * DMODEL], g_nl[(size_t)MTOK * DMODEL];
__device__ float         g_part[1024];
__device__ float         g_mean[1];

// ---------------------------------------------------------------------------
// GEMM engine
// ---------------------------------------------------------------------------
__device__ __forceinline__ void load_tile_async(uint32_t sbase,
                                                const __nv_bfloat16* __restrict__ G,
                                                int ld, int row0, int k0) {
    const int t = threadIdx.x;
    const int g = t & 7;
    const int r = t >> 3;                 // 0..31
    const __nv_bfloat16* src = G + (size_t)(row0 + r) * ld + k0 + g * 8;
    #pragma unroll
    for (int p = 0; p < 4; p++) {
        CP_ASYNC16(sbase + swz(r + p * 32, g), src + (size_t)p * 32 * ld);
    }
}

__device__ __forceinline__ void fill_stage(uint32_t st,
                                           const __nv_bfloat16* __restrict__ Ah,
                                           const __nv_bfloat16* __restrict__ Al, int lda, int arow0,
                                           const __nv_bfloat16* __restrict__ Bh,
                                           const __nv_bfloat16* __restrict__ Bl, int ldb, int brow0,
                                           int k0) {
    load_tile_async(st + 0 * TILE_B, Ah, lda, arow0, k0);
    load_tile_async(st + 1 * TILE_B, Al, lda, arow0, k0);
    load_tile_async(st + 2 * TILE_B, Bh, ldb, brow0, k0);
    load_tile_async(st + 3 * TILE_B, Bl, ldb, brow0, k0);
    CP_COMMIT();
}

__device__ __forceinline__ void compute_chunk(uint32_t sbase, int warp_m, int warp_n,
                                              int lane, float acc[2][8][4]) {
    const int arow = warp_m * 32 + (lane & 7) + ((lane >> 3) & 1) * 8;
    const int brow = warp_n * 64 + (lane & 7) + (lane >> 4) * 8;
    #pragma unroll
    for (int kk = 0; kk < 4; kk++) {
        const int ag = kk * 2 + (lane >> 4);
        const int bg = kk * 2 + ((lane >> 3) & 1);
        uint32_t ah[2][4], al[2][4], bh[4][4], bl[4][4];
        #pragma unroll
        for (int mt = 0; mt < 2; mt++) {
            ldmatrix_x4(ah[mt], sbase + 0 * TILE_B + swz(arow + mt * 16, ag));
            ldmatrix_x4(al[mt], sbase + 1 * TILE_B + swz(arow + mt * 16, ag));
        }
        #pragma unroll
        for (int nt2 = 0; nt2 < 4; nt2++) {
            ldmatrix_x4(bh[nt2], sbase + 2 * TILE_B + swz(brow + nt2 * 16, bg));
            ldmatrix_x4(bl[nt2], sbase + 3 * TILE_B + swz(brow + nt2 * 16, bg));
        }
        #pragma unroll
        for (int mt = 0; mt < 2; mt++)
            #pragma unroll
            for (int nt = 0; nt < 8; nt++) {
                const uint32_t* pbh = &bh[nt >> 1][(nt & 1) * 2];
                const uint32_t* pbl = &bl[nt >> 1][(nt & 1) * 2];
                mma16816(acc[mt][nt], ah[mt], pbh);
                mma16816(acc[mt][nt], ah[mt], pbl);
                mma16816(acc[mt][nt], al[mt], pbh);
            }
    }
}

// D[128,128] = sum_K (AhBh + AhBl + AlBh), NT form, 3-stage pipeline.
__device__ void mma_mainloop(const __nv_bfloat16* __restrict__ Ah,
                             const __nv_bfloat16* __restrict__ Al, int lda, int arow0,
                             const __nv_bfloat16* __restrict__ Bh,
                             const __nv_bfloat16* __restrict__ Bl, int ldb, int brow0,
                             int K, uint32_t sb, float acc[2][8][4]) {
    const int C = K >> 6;
    const int warp = threadIdx.x >> 5, lane = threadIdx.x & 31;
    const int warp_m = warp & 3, warp_n = warp >> 2;

    #pragma unroll
    for (int mt = 0; mt < 2; mt++)
        #pragma unroll
        for (int nt = 0; nt < 8; nt++)
            #pragma unroll
            for (int i = 0; i < 4; i++) acc[mt][nt][i] = 0.f;

    // prologue: stages 0,1 (C >= 2 always here)
    fill_stage(sb + 0 * STAGE_B, Ah, Al, lda, arow0, Bh, Bl, ldb, brow0, 0);
    fill_stage(sb + 1 * STAGE_B, Ah, Al, lda, arow0, Bh, Bl, ldb, brow0, 64);

    int slot = 0;
    for (int c = 0; c < C; c++) {
        if (c + 1 < C) { CP_WAIT1(); } else { CP_WAIT0(); }
        __syncthreads();
        compute_chunk(sb + slot * STAGE_B, warp_m, warp_n, lane, acc);
        if (c + 2 < C) {
            // slot (c+2)%3 == slot of chunk c-1: all threads finished reading it
            // before this iteration's __syncthreads().
            fill_stage(sb + ((c + 2) % 3) * STAGE_B, Ah, Al, lda, arow0,
                       Bh, Bl, ldb, brow0, (c + 2) << 6);
        }
        slot = (slot + 1) % 3;
    }
}

// ---------------------------------------------------------------------------
// Epilogue helpers
// ---------------------------------------------------------------------------
__device__ __forceinline__ void split2(float v, __nv_bfloat16& h, __nv_bfloat16& l) {
    h = __float2bfloat16(v);
    l = __float2bfloat16(v - __bfloat162float(h));
}

__device__ __forceinline__ void split_store2(__nv_bfloat16* __restrict__ H,
                                             __nv_bfloat16* __restrict__ L,
                                             size_t off, float v0, float v1) {
    __nv_bfloat16 h0, h1, l0, l1;
    split2(v0, h0, l0); split2(v1, h1, l1);
    *(__nv_bfloat162*)(H + off) = __halves2bfloat162(h0, h1);
    *(__nv_bfloat162*)(L + off) = __halves2bfloat162(l0, l1);
}

// Split-store 64 consecutive values (bf16 hi/lo) — for V-transpose epilogue
__device__ __forceinline__ void store_split64(__nv_bfloat16* __restrict__ H,
                                              __nv_bfloat16* __restrict__ L,
                                              size_t off, const float* v) {
    uint32_t hp[32], lp[32];
    #pragma unroll
    for (int j = 0; j < 64; j += 2) {
        __nv_bfloat16 h0, h1, l0, l1;
        split2(v[j], h0, l0); split2(v[j + 1], h1, l1);
        __nv_bfloat162 hh = __halves2bfloat162(h0, h1);
        __nv_bfloat162 ll = __halves2bfloat162(l0, l1);
        hp[j >> 1] = reinterpret_cast<uint32_t&>(hh);
        lp[j >> 1] = reinterpret_cast<uint32_t&>(ll);
    }
    #pragma unroll
    for (int i = 0; i < 8; i++) {
        *(uint4*)((char*)(H + off) + i * 16) = ((uint4*)hp)[i];
        *(uint4*)((char*)(L + off) + i * 16) = ((uint4*)lp)[i];
    }
}

// per-thread fragment coordinates
#define FRAG_COORDS() \
    const int warp = threadIdx.x >> 5, lane = threadIdx.x & 31; \
    const int warp_m = warp & 3, warp_n = warp >> 2; \
    const int gid = lane >> 2, t4 = lane & 3;

// ---------------------------------------------------------------------------
// GEMM kernels
// ---------------------------------------------------------------------------

// C = A*B^T + bias, split-bf16 out (Q, K projections)
__global__ __launch_bounds__(256, 1)
void k_gemm_bias_split(const __nv_bfloat16* __restrict__ Ah, const __nv_bfloat16* __restrict__ Al, int lda,
                       const __nv_bfloat16* __restrict__ Bh, const __nv_bfloat16* __restrict__ Bl, int ldb,
                       const float* __restrict__ bias,
                       __nv_bfloat16* __restrict__ Ch, __nv_bfloat16* __restrict__ Cl, int ldc, int K) {
    extern __shared__ char smem[];
    const uint32_t sb = smem_to_u32(smem);
    const int m0 = blockIdx.y * 128, n0 = blockIdx.x * 128;
    float acc[2][8][4];
    mma_mainloop(Ah, Al, lda, m0, Bh, Bl, ldb, n0, K, sb, acc);
    FRAG_COORDS();
    #pragma unroll
    for (int mt = 0; mt < 2; mt++)
        #pragma unroll
        for (int nt = 0; nt < 8; nt++) {
            const int col = n0 + warp_n * 64 + nt * 8 + t4 * 2;
            const float bx = bias[col], by = bias[col + 1];
            const int r0 = m0 + warp_m * 32 + mt * 16 + gid;
            split_store2(Ch, Cl, (size_t)r0 * ldc + col, acc[mt][nt][0] + bx, acc[mt][nt][1] + by);
            split_store2(Ch, Cl, (size_t)(r0 + 8) * ldc + col, acc[mt][nt][2] + bx, acc[mt][nt][3] + by);
        }
}

// V projection: writes transposed vT[bh][dim][token] split-bf16
__global__ __launch_bounds__(256, 1)
void k_gemm_v(const __nv_bfloat16* __restrict__ Ah, const __nv_bfloat16* __restrict__ Al,
              const __nv_bfloat16* __restrict__ Bh, const __nv_bfloat16* __restrict__ Bl,
              const float* __restrict__ bias,
              __nv_bfloat16* __restrict__ VTh, __nv_bfloat16* __restrict__ VTl) {
    extern __shared__ char smem[];
    const uint32_t sb = smem_to_u32(smem);
    const int m0 = blockIdx.y * 128, n0 = blockIdx.x * 128;
    float acc[2][8][4];
    mma_mainloop(Ah, Al, DMODEL, m0, Bh, Bl, DMODEL, n0, DMODEL, sb, acc);
    FRAG_COORDS();

    float* smf = (float*)smem;  // [128][129]
    __syncthreads();
    #pragma unroll
    for (int mt = 0; mt < 2; mt++)
        #pragma unroll
        for (int nt = 0; nt < 8; nt++) {
            const int lc = warp_n * 64 + nt * 8 + t4 * 2;
            const float bx = bias[n0 + lc], by = bias[n0 + lc + 1];
            const int lr = warp_m * 32 + mt * 16 + gid;
            smf[lr * 129 + lc] = acc[mt][nt][0] + bx;
            smf[lr * 129 + lc + 1] = acc[mt][nt][1] + by;
            smf[(lr + 8) * 129 + lc] = acc[mt][nt][2] + bx;
            smf[(lr + 8) * 129 + lc + 1] = acc[mt][nt][3] + by;
        }
    __syncthreads();

    const int b = m0 / SEQ, tok0 = m0 % SEQ;
    const int h = n0 / DMODEL, dim0 = n0 % DMODEL;
    const int c = threadIdx.x & 127;
    const int seg = threadIdx.x >> 7;
    float vv[64];
    #pragma unroll
    for (int i = 0; i < 64; i++) vv[i] = smf[(seg * 64 + i) * 129 + c];
    const size_t off = ((size_t)(b * 3 + h) * DMODEL + dim0 + c) * SEQ + tok0 + seg * 64;
    store_split64(VTh, VTl, off, vv);
}

// scores = q k^T per (b,h) + exact reference masking, fp32; upper tiles skipped
// entirely (never read downstream).
__global__ __launch_bounds__(256, 1)
void k_scores(const __nv_bfloat16* __restrict__ qh, const __nv_bfloat16* __restrict__ ql,
              const __nv_bfloat16* __restrict__ kh, const __nv_bfloat16* __restrict__ kl,
              float* __restrict__ s) {
    const int bh = blockIdx.z;
    const int b = bh / 3, h = bh % 3;
    const int m0 = blockIdx.y * 128, n0 = blockIdx.x * 128;
    if (n0 > m0) return;   // fully masked tile: not written, not read
    float* C = s + (size_t)bh * SEQ * SEQ;

    extern __shared__ char smem[];
    const uint32_t sb = smem_to_u32(smem);
    float acc[2][8][4];
    mma_mainloop(qh + h * DMODEL, ql + h * DMODEL, DQKV, b * SEQ + m0,
                 kh + h * DMODEL, kl + h * DMODEL, DQKV, b * SEQ + n0,
                 DMODEL, sb, acc);
    FRAG_COORDS();
    #pragma unroll
    for (int mt = 0; mt < 2; mt++)
        #pragma unroll
        for (int nt = 0; nt < 8; nt++) {
            const int gj = n0 + warp_n * 64 + nt * 8 + t4 * 2;
            #pragma unroll
            for (int half = 0; half < 2; half++) {
                const int gi = m0 + warp_m * 32 + mt * 16 + gid + half * 8;
                float v0 = acc[mt][nt][half * 2];
                float v1 = acc[mt][nt][half * 2 + 1];
                if (gj > gi || v0 == 0.0f) v0 = -99999.0f;
                if (gj + 1 > gi || v1 == 0.0f) v1 = -99999.0f;
                *(float2*)(C + (size_t)gi * SEQ + gj) = make_float2(v0, v1);
            }
        }
}

// o = attn @ v per (b,h); K truncated at diagonal; split-bf16 out [8192,2304]
__global__ __launch_bounds__(256, 1)
void k_pv(const __nv_bfloat16* __restrict__ ph, const __nv_bfloat16* __restrict__ pl,
          const __nv_bfloat16* __restrict__ vth, const __nv_bfloat16* __restrict__ vtl,
          __nv_bfloat16* __restrict__ oh, __nv_bfloat16* __restrict__ ol) {
    extern __shared__ char smem[];
    const uint32_t sb = smem_to_u32(smem);
    const int bh = blockIdx.z;
    const int b = bh / 3, h = bh % 3;
    const int m0 = blockIdx.y * 128, n0 = blockIdx.x * 128;
    float acc[2][8][4];
    mma_mainloop(ph + (size_t)bh * SEQ * SEQ, pl + (size_t)bh * SEQ * SEQ, SEQ, m0,
                 vth + (size_t)bh * DMODEL * SEQ, vtl + (size_t)bh * DMODEL * SEQ, SEQ, n0,
                 m0 + 128, sb, acc);
    FRAG_COORDS();
    #pragma unroll
    for (int mt = 0; mt < 2; mt++)
        #pragma unroll
        for (int nt = 0; nt < 8; nt++) {
            const int col = h * DMODEL + n0 + warp_n * 64 + nt * 8 + t4 * 2;
            const int r0 = b * SEQ + m0 + warp_m * 32 + mt * 16 + gid;
            split_store2(oh, ol, (size_t)r0 * DQKV + col, acc[mt][nt][0], acc[mt][nt][1]);
            split_store2(oh, ol, (size_t)(r0 + 8) * DQKV + col, acc[mt][nt][2], acc[mt][nt][3]);
        }
}

// C = A*B^T + bias, fp32 out (Wo projection)
__global__ __launch_bounds__(256, 1)
void k_gemm_bias_f32(const __nv_bfloat16* __restrict__ Ah, const __nv_bfloat16* __restrict__ Al, int lda,
                     const __nv_bfloat16* __restrict__ Bh, const __nv_bfloat16* __restrict__ Bl, int ldb,
                     const float* __restrict__ bias, float* __restrict__ C, int ldc, int K) {
    extern __shared__ char smem[];
    const uint32_t sb = smem_to_u32(smem);
    const int m0 = blockIdx.y * 128, n0 = blockIdx.x * 128;
    float acc[2][8][4];
    mma_mainloop(Ah, Al, lda, m0, Bh, Bl, ldb, n0, K, sb, acc);
    FRAG_COORDS();
    #pragma unroll
    for (int mt = 0; mt < 2; mt++)
        #pragma unroll
        for (int nt = 0; nt < 8; nt++) {
            const int col = n0 + warp_n * 64 + nt * 8 + t4 * 2;
            const float bx = bias[col], by = bias[col + 1];
            const int r0 = m0 + warp_m * 32 + mt * 16 + gid;
            *(float2*)(C + (size_t)r0 * ldc + col) =
                make_float2(acc[mt][nt][0] + bx, acc[mt][nt][1] + by);
            *(float2*)(C + (size_t)(r0 + 8) * ldc + col) =
                make_float2(acc[mt][nt][2] + bx, acc[mt][nt][3] + by);
        }
}

// final: out = leaky_relu(A*Wf^T + bf)
__global__ __launch_bounds__(256, 1)
void k_final(const __nv_bfloat16* __restrict__ Ah, const __nv_bfloat16* __restrict__ Al,
             const __nv_bfloat16* __restrict__ Bh, const __nv_bfloat16* __restrict__ Bl,
             const float* __restrict__ bias, float* __restrict__ out) {
    extern __shared__ char smem[];
    const uint32_t sb = smem_to_u32(smem);
    const int m0 = blockIdx.y * 128, n0 = blockIdx.x * 128;
    float acc[2][8][4];
    mma_mainloop(Ah, Al, DMODEL, m0, Bh, Bl, DMODEL, n0, DMODEL, sb, acc);
    FRAG_COORDS();
    #pragma unroll
    for (int mt = 0; mt < 2; mt++)
        #pragma unroll
        for (int nt = 0; nt < 8; nt++) {
            const int col = n0 + warp_n * 64 + nt * 8 + t4 * 2;
            const float bx = bias[col], by = bias[col + 1];
            const int r0 = m0 + warp_m * 32 + mt * 16 + gid;
            float t0 = acc[mt][nt][0] + bx, t1 = acc[mt][nt][1] + by;
            float t2 = acc[mt][nt][2] + bx, t3 = acc[mt][nt][3] + by;
            t0 = t0 > 0.f ? t0 : 0.01f * t0;
            t1 = t1 > 0.f ? t1 : 0.01f * t1;
            t2 = t2 > 0.f ? t2 : 0.01f * t2;
            t3 = t3 > 0.f ? t3 : 0.01f * t3;
            *(float2*)(out + (size_t)r0 * DMODEL + col) = make_float2(t0, t1);
            *(float2*)(out + (size_t)(r0 + 8) * DMODEL + col) = make_float2(t2, t3);
        }
}

// ---------------------------------------------------------------------------
// Non-GEMM kernels
// ---------------------------------------------------------------------------
__global__ void split_kernel(const float* __restrict__ src,
                             __nv_bfloat16* __restrict__ H, __nv_bfloat16* __restrict__ L, int n) {
    int i = (blockIdx.x * 256 + threadIdx.x) * 4;
    if (i >= n) return;
    float4 v = *(const float4*)(src + i);
    __nv_bfloat16 h0, h1, h2, h3, l0, l1, l2, l3;
    split2(v.x, h0, l0); split2(v.y, h1, l1); split2(v.z, h2, l2); split2(v.w, h3, l3);
    __nv_bfloat162 a = __halves2bfloat162(h0, h1), b2 = __halves2bfloat162(h2, h3);
    __nv_bfloat162 c = __halves2bfloat162(l0, l1), d = __halves2bfloat162(l2, l3);
    uint2 hp, lp;
    hp.x = reinterpret_cast<uint32_t&>(a); hp.y = reinterpret_cast<uint32_t&>(b2);
    lp.x = reinterpret_cast<uint32_t&>(c); lp.y = reinterpret_cast<uint32_t&>(d);
    *(uint2*)(H + i) = hp;
    *(uint2*)(L + i) = lp;
}

// W[K,N] fp32 -> Wt[N,K] split-bf16 (generic, used for Wo, Wf)
__global__ void transpose_split_kernel(const float* __restrict__ W, int K, int N,
                                       __nv_bfloat16* __restrict__ TH, __nv_bfloat16* __restrict__ TL) {
    __shared__ float t[32][33];
    const int n0 = blockIdx.x * 32, k0 = blockIdx.y * 32;
    const int tx = threadIdx.x, ty = threadIdx.y;
    #pragma unroll
    for (int i = ty; i < 32; i += 8)
        t[i][tx] = W[(size_t)(k0 + i) * N + n0 + tx];
    __syncthreads();
    #pragma unroll
    for (int i = ty; i < 32; i += 8) {
        float v = t[tx][i];
        __nv_bfloat16 h, l;
        split2(v, h, l);
        const size_t off = (size_t)(n0 + i) * K + k0 + tx;
        TH[off] = h;
        TL[off] = l;
    }
}

// Wq/Wk/Wv transposes merged: blockIdx.z selects the weight
__global__ void transpose_split_qkv(const float* __restrict__ Wq, const float* __restrict__ Wk,
                                    const float* __restrict__ Wv,
                                    __nv_bfloat16* __restrict__ QH, __nv_bfloat16* __restrict__ QL,
                                    __nv_bfloat16* __restrict__ KH, __nv_bfloat16* __restrict__ KL,
                                    __nv_bfloat16* __restrict__ VH, __nv_bfloat16* __restrict__ VL) {
    const float* W = (blockIdx.z == 0) ? Wq : (blockIdx.z == 1) ? Wk : Wv;
    __nv_bfloat16* TH = (blockIdx.z == 0) ? QH : (blockIdx.z == 1) ? KH : VH;
    __nv_bfloat16* TL = (blockIdx.z == 0) ? QL : (blockIdx.z == 1) ? KL : VL;
    __shared__ float t[32][33];
    const int n0 = blockIdx.x * 32, k0 = blockIdx.y * 32;
    const int tx = threadIdx.x, ty = threadIdx.y;
    #pragma unroll
    for (int i = ty; i < 32; i += 8)
        t[i][tx] = W[(size_t)(k0 + i) * DQKV + n0 + tx];
    __syncthreads();
    #pragma unroll
    for (int i = ty; i < 32; i += 8) {
        float v = t[tx][i];
        __nv_bfloat16 h, l;
        split2(v, h, l);
        const size_t off = (size_t)(n0 + i) * DMODEL + k0 + tx;
        TH[off] = h;
        TL[off] = l;
    }
}

// causal-aware row softmax: row `r` only touches cols [0, round128(r+1));
// diagonal-tile entries above the diagonal hold -99999 -> exp underflows to 0,
// matching the reference bit-for-bit. Upper tiles are never read.
__global__ void softmax_split_causal(const float* __restrict__ s,
                                     __nv_bfloat16* __restrict__ PH, __nv_bfloat16* __restrict__ PL) {
    const int row = blockIdx.x & (SEQ - 1);
    const int L = ((row >> 7) + 1) << 7;
    const float* p = s + (size_t)blockIdx.x * SEQ;
    __nv_bfloat16* ph = PH + (size_t)blockIdx.x * SEQ;
    __nv_bfloat16* pl = PL + (size_t)blockIdx.x * SEQ;
    const int tid = threadIdx.x;
    const int lane = tid & 31, wid = tid >> 5;
    __shared__ float red[8];

    float v[8];
    int cnt = 0;
    float m = -3.4e38f;
    for (int j = tid; j < L; j += 256) { float x = p[j]; v[cnt++] = x; m = fmaxf(m, x); }
    #pragma unroll
    for (int o = 16; o; o >>= 1) m = fmaxf(m, __shfl_xor_sync(0xffffffffu, m, o));
    if (lane == 0) red[wid] = m;
    __syncthreads();
    float mall = red[0];
    #pragma unroll
    for (int i = 1; i < 8; i++) mall = fmaxf(mall, red[i]);

    float ssum = 0.f;
    for (int i = 0; i < cnt; i++) {
        v[i] = exp2f((v[i] - mall) * 1.4426950408889634f);
        ssum += v[i];
    }
    #pragma unroll
    for (int o = 16; o; o >>= 1) ssum += __shfl_xor_sync(0xffffffffu, ssum, o);
    __syncthreads();   // red[] reuse
    if (lane == 0) red[wid] = ssum;
    __syncthreads();
    float tot = 0.f;
    #pragma unroll
    for (int i = 0; i < 8; i++) tot += red[i];
    const float inv = 1.0f / tot;

    int i2 = 0;
    for (int j = tid; j < L; j += 256) {
        float pv = v[i2++] * inv;
        __nv_bfloat16 h, l;
        split2(pv, h, l);
        ph[j] = h;
        pl[j] = l;
    }
}

__global__ void reduce_partial(const float* __restrict__ a, float* __restrict__ part) {
    const int n = MTOK * DMODEL;
    float s = 0.f;
    for (int i = blockIdx.x * 256 + threadIdx.x; i < n; i += 1024 * 256) s += a[i];
    __shared__ float sm[256];
    sm[threadIdx.x] = s; __syncthreads();
    #pragma unroll
    for (int st = 128; st > 0; st >>= 1) {
        if (threadIdx.x < st) sm[threadIdx.x] += sm[threadIdx.x + st];
        __syncthreads();
    }
    if (threadIdx.x == 0) part[blockIdx.x] = sm[0];
}

__global__ void reduce_final(const float* __restrict__ part, float* __restrict__ mean) {
    float s = 0.f;
    for (int i = threadIdx.x; i < 1024; i += 256) s += part[i];
    __shared__ float sm[256];
    sm[threadIdx.x] = s; __syncthreads();
    #pragma unroll
    for (int st = 128; st > 0; st >>= 1) {
        if (threadIdx.x < st) sm[threadIdx.x] += sm[threadIdx.x + st];
        __syncthreads();
    }
    if (threadIdx.x == 0) mean[0] = sm[0] * (1.0f / ((float)MTOK * DMODEL));
}

// n = a - mean + x, split-bf16
__global__ void fuse_split_kernel(const float* __restrict__ a, const float* __restrict__ x,
                                  const float* __restrict__ meanp,
                                  __nv_bfloat16* __restrict__ NH, __nv_bfloat16* __restrict__ NL, int n) {
    const float mean = meanp[0];
    int i = (blockIdx.x * 256 + threadIdx.x) * 4;
    if (i >= n) return;
    float4 va = *(const float4*)(a + i);
    float4 vx = *(const float4*)(x + i);
    float f0 = va.x - mean + vx.x, f1 = va.y - mean + vx.y;
    float f2 = va.z - mean + vx.z, f3 = va.w - mean + vx.w;
    __nv_bfloat16 h0, h1, h2, h3, l0, l1, l2, l3;
    split2(f0, h0, l0); split2(f1, h1, l1); split2(f2, h2, l2); split2(f3, h3, l3);
    __nv_bfloat162 aa = __halves2bfloat162(h0, h1), bb = __halves2bfloat162(h2, h3);
    __nv_bfloat162 cc = __halves2bfloat162(l0, l1), dd = __halves2bfloat162(l2, l3);
    uint2 hp, lp;
    hp.x = reinterpret_cast<uint32_t&>(aa); hp.y = reinterpret_cast<uint32_t&>(bb);
    lp.x = reinterpret_cast<uint32_t&>(cc); lp.y = reinterpret_cast<uint32_t&>(dd);
    *(uint2*)(NH + i) = hp;
    *(uint2*)(NL + i) = lp;
}

// ---------------------------------------------------------------------------
extern "C" void kernel_launch(void* const* d_in, const int* in_sizes, int n_in,
                              void* d_out, int out_size) {
    const float* x  = (const float*)d_in[0];
    const float* Wq = (const float*)d_in[1];
    const float* bq = (const float*)d_in[2];
    const float* Wk = (const float*)d_in[3];
    const float* bk = (const float*)d_in[4];
    const float* Wv = (const float*)d_in[5];
    const float* bv = (const float*)d_in[6];
    const float* Wo = (const float*)d_in[7];
    const float* bo = (const float*)d_in[8];
    const float* Wf = (const float*)d_in[9];
    const float* bf = (const float*)d_in[10];
    float* out = (float*)d_out;

    static bool attr_done = false;
    if (!attr_done) {
        cudaFuncSetAttribute(k_gemm_bias_split, cudaFuncAttributeMaxDynamicSharedMemorySize, DYN_SMEM);
        cudaFuncSetAttribute(k_gemm_v,          cudaFuncAttributeMaxDynamicSharedMemorySize, DYN_SMEM);
        cudaFuncSetAttribute(k_scores,          cudaFuncAttributeMaxDynamicSharedMemorySize, DYN_SMEM);
        cudaFuncSetAttribute(k_pv,              cudaFuncAttributeMaxDynamicSharedMemorySize, DYN_SMEM);
        cudaFuncSetAttribute(k_gemm_bias_f32,   cudaFuncAttributeMaxDynamicSharedMemorySize, DYN_SMEM);
        cudaFuncSetAttribute(k_final,           cudaFuncAttributeMaxDynamicSharedMemorySize, DYN_SMEM);
        attr_done = true;
    }

    __nv_bfloat16 *xh, *xl, *wqth, *wqtl, *wkth, *wktl, *wvth, *wvtl, *woth, *wotl, *wfth, *wftl;
    __nv_bfloat16 *qh, *ql, *kh, *kl, *vth, *vtl, *ph, *pl, *oh, *ol, *nh, *nl;
    float *s, *a, *part, *mean;
    cudaGetSymbolAddress((void**)&xh, g_xh);     cudaGetSymbolAddress((void**)&xl, g_xl);
    cudaGetSymbolAddress((void**)&wqth, g_wqth); cudaGetSymbolAddress((void**)&wqtl, g_wqtl);
    cudaGetSymbolAddress((void**)&wkth, g_wkth); cudaGetSymbolAddress((void**)&wktl, g_wktl);
    cudaGetSymbolAddress((void**)&wvth, g_wvth); cudaGetSymbolAddress((void**)&wvtl, g_wvtl);
    cudaGetSymbolAddress((void**)&woth, g_woth); cudaGetSymbolAddress((void**)&wotl, g_wotl);
    cudaGetSymbolAddress((void**)&wfth, g_wfth); cudaGetSymbolAddress((void**)&wftl, g_wftl);
    cudaGetSymbolAddress((void**)&qh, g_qh);     cudaGetSymbolAddress((void**)&ql, g_ql);
    cudaGetSymbolAddress((void**)&kh, g_kh);     cudaGetSymbolAddress((void**)&kl, g_kl);
    cudaGetSymbolAddress((void**)&vth, g_vth);   cudaGetSymbolAddress((void**)&vtl, g_vtl);
    cudaGetSymbolAddress((void**)&s, g_s);
    cudaGetSymbolAddress((void**)&ph, g_ph);     cudaGetSymbolAddress((void**)&pl, g_pl);
    cudaGetSymbolAddress((void**)&oh, g_oh);     cudaGetSymbolAddress((void**)&ol, g_ol);
    cudaGetSymbolAddress((void**)&a, g_a);
    cudaGetSymbolAddress((void**)&nh, g_nh);     cudaGetSymbolAddress((void**)&nl, g_nl);
    cudaGetSymbolAddress((void**)&part, g_part); cudaGetSymbolAddress((void**)&mean, g_mean);

    // 0) splits / transposes of inputs
    const int nx = MTOK * DMODEL;
    split_kernel<<<(nx / 4 + 255) / 256, 256>>>(x, xh, xl, nx);
    transpose_split_qkv<<<dim3(DQKV / 32, DMODEL / 32, 3), dim3(32, 8)>>>(
        Wq, Wk, Wv, wqth, wqtl, wkth, wktl, wvth, wvtl);
    transpose_split_kernel<<<dim3(DMODEL / 32, DQKV / 32), dim3(32, 8)>>>(Wo, DQKV, DMODEL, woth, wotl);
    transpose_split_kernel<<<dim3(DMODEL / 32, DMODEL / 32), dim3(32, 8)>>>(Wf, DMODEL, DMODEL, wfth, wftl);

    // 1) Q, K projections (split-bf16 outputs), V projection (transposed out)
    dim3 qkvGrid(DQKV / 128, MTOK / 128);
    k_gemm_bias_split<<<qkvGrid, 256, DYN_SMEM>>>(xh, xl, DMODEL, wqth, wqtl, DMODEL, bq, qh, ql, DQKV, DMODEL);
    k_gemm_bias_split<<<qkvGrid, 256, DYN_SMEM>>>(xh, xl, DMODEL, wkth, wktl, DMODEL, bk, kh, kl, DQKV, DMODEL);
    k_gemm_v<<<qkvGrid, 256, DYN_SMEM>>>(xh, xl, wvth, wvtl, bv, vth, vtl);

    // 2) masked scores (lower-triangle tiles only)
    k_scores<<<dim3(SEQ / 128, SEQ / 128, NBH), 256, DYN_SMEM>>>(qh, ql, kh, kl, s);

    // 3) causal softmax + split
    softmax_split_causal<<<NBH * SEQ, 256>>>(s, ph, pl);

    // 4) o = attn @ v (causal-truncated k-loop)
    k_pv<<<dim3(DMODEL / 128, SEQ / 128, NBH), 256, DYN_SMEM>>>(ph, pl, vth, vtl, oh, ol);

    // 5) a = o @ Wo + bo (fp32)
    k_gemm_bias_f32<<<dim3(DMODEL / 128, MTOK / 128), 256, DYN_SMEM>>>(
        oh, ol, DQKV, woth, wotl, DQKV, bo, a, DMODEL, DQKV);

    // 6) deterministic global mean
    reduce_partial<<<1024, 256>>>(a, part);
    reduce_final<<<1, 256>>>(part, mean);

    // 7) n = a - mean + x (split)
    fuse_split_kernel<<<(nx / 4 + 255) / 256, 256>>>(a, x, mean, nh, nl, nx);

    // 8) out = leaky_relu(n @ Wf + bf)
    k_final<<<dim3(DMODEL / 128, MTOK / 128), 256, DYN_SMEM>>>(nh, nl, wfth, wftl, bf, out);
}

// round 10
// speedup vs baseline: 3.5888x; 1.1854x over previous
#include <cuda_runtime.h>
#include <cuda_bf16.h>
#include <cuda_fp16.h>
#include <cstdint>
#include <cstddef>

// ===========================================================================
// B=4, S=2048, D=768, H=3.  MTOK=8192, DQKV=2304.
// Q/K proj + scores: bf16 split-3 (AhBh+AhBl+AlBh), 3 MMAs -> err ~1e-5.
// V proj, PV, Wo, Wf: fp16 A-split-2 x B-single, 2 MMAs -> err ~3e-4.
// ===========================================================================

#define MTOK 8192
#define DMODEL 768
#define DQKV 2304
#define SEQ 2048
#define NBH 12

#define TILE_B 16384            // 128 rows x 128B
#define STAGE_B (4 * TILE_B)    // bf16 path: Ah, Al, Bh, Bl
#define DYN_SMEM (3 * STAGE_B)  // 196608
#define STAGE2_B (3 * TILE_B)   // f16 path: Ah, Al, B
#define DYN_SMEM2 (3 * STAGE2_B) // 147456

// ---------------------------------------------------------------------------
// PTX helpers (non-'a' ISA only)
// ---------------------------------------------------------------------------
__device__ __forceinline__ uint32_t smem_to_u32(const void* p) {
    uint32_t a;
    asm("{ .reg .u64 t; cvta.to.shared.u64 t, %1; cvt.u32.u64 %0, t; }" : "=r"(a) : "l"(p));
    return a;
}

__device__ __forceinline__ void ldmatrix_x4(uint32_t* r, uint32_t addr) {
    asm volatile("ldmatrix.sync.aligned.m8n8.x4.shared.b16 {%0,%1,%2,%3}, [%4];"
                 : "=r"(r[0]), "=r"(r[1]), "=r"(r[2]), "=r"(r[3]) : "r"(addr));
}

__device__ __forceinline__ void mma16816(float* c, const uint32_t* a, const uint32_t* b) {
    asm volatile(
        "mma.sync.aligned.m16n8k16.row.col.f32.bf16.bf16.f32 "
        "{%0,%1,%2,%3}, {%4,%5,%6,%7}, {%8,%9}, {%0,%1,%2,%3};"
        : "+f"(c[0]), "+f"(c[1]), "+f"(c[2]), "+f"(c[3])
        : "r"(a[0]), "r"(a[1]), "r"(a[2]), "r"(a[3]), "r"(b[0]), "r"(b[1]));
}

__device__ __forceinline__ void mma16816h(float* c, const uint32_t* a, const uint32_t* b) {
    asm volatile(
        "mma.sync.aligned.m16n8k16.row.col.f32.f16.f16.f32 "
        "{%0,%1,%2,%3}, {%4,%5,%6,%7}, {%8,%9}, {%0,%1,%2,%3};"
        : "+f"(c[0]), "+f"(c[1]), "+f"(c[2]), "+f"(c[3])
        : "r"(a[0]), "r"(a[1]), "r"(a[2]), "r"(a[3]), "r"(b[0]), "r"(b[1]));
}

#define CP_ASYNC16(dst, src) \
    asm volatile("cp.async.cg.shared.global [%0], [%1], 16;" :: "r"(dst), "l"(src))
#define CP_COMMIT() asm volatile("cp.async.commit_group;" ::: "memory")
#define CP_WAIT0()  asm volatile("cp.async.wait_group 0;" ::: "memory")
#define CP_WAIT1()  asm volatile("cp.async.wait_group 1;" ::: "memory")

__device__ __forceinline__ uint32_t swz(int r, int g) {
    return (uint32_t)(r * 128 + ((g ^ (r & 7)) << 4));
}

// ---------------------------------------------------------------------------
// Scratch (allocation-free device globals)
// ---------------------------------------------------------------------------
__device__ __nv_bfloat16 g_xh[(size_t)MTOK * DMODEL], g_xl[(size_t)MTOK * DMODEL];
__device__ __half        g_xh2[(size_t)MTOK * DMODEL], g_xl2[(size_t)MTOK * DMODEL];
__device__ __nv_bfloat16 g_wqth[(size_t)DQKV * DMODEL], g_wqtl[(size_t)DQKV * DMODEL];
__device__ __nv_bfloat16 g_wkth[(size_t)DQKV * DMODEL], g_wktl[(size_t)DQKV * DMODEL];
__device__ __half        g_wvt16[(size_t)DQKV * DMODEL];
__device__ __half        g_wot16[(size_t)DMODEL * DQKV];
__device__ __half        g_wft16[(size_t)DMODEL * DMODEL];
__device__ __nv_bfloat16 g_qh[(size_t)MTOK * DQKV], g_ql[(size_t)MTOK * DQKV];
__device__ __nv_bfloat16 g_kh[(size_t)MTOK * DQKV], g_kl[(size_t)MTOK * DQKV];
__device__ __half        g_vt16[(size_t)NBH * DMODEL * SEQ];
__device__ float         g_s[(size_t)NBH * SEQ * SEQ];
__device__ __half        g_ph[(size_t)NBH * SEQ * SEQ], g_pl[(size_t)NBH * SEQ * SEQ];
__device__ __half        g_oh[(size_t)MTOK * DQKV], g_ol[(size_t)MTOK * DQKV];
__device__ float         g_a[(size_t)MTOK * DMODEL];
__device__ __half        g_nh[(size_t)MTOK * DMODEL], g_nl[(size_t)MTOK * DMODEL];
__device__ float         g_part[1024];
__device__ float         g_mean[1];

// ---------------------------------------------------------------------------
// Shared engine pieces
// ---------------------------------------------------------------------------
template <typename T>
__device__ __forceinline__ void load_tile_async(uint32_t sbase, const T* __restrict__ G,
                                                int ld, int row0, int k0) {
    const int t = threadIdx.x;
    const int g = t & 7;
    const int r = t >> 3;
    const T* src = G + (size_t)(row0 + r) * ld + k0 + g * 8;
    #pragma unroll
    for (int p = 0; p < 4; p++) {
        CP_ASYNC16(sbase + swz(r + p * 32, g), src + (size_t)p * 32 * ld);
    }
}

// ----- bf16 split-3 mainloop (Q/K proj, scores) -----
__device__ __forceinline__ void fill_stage(uint32_t st,
                                           const __nv_bfloat16* __restrict__ Ah,
                                           const __nv_bfloat16* __restrict__ Al, int lda, int arow0,
                                           const __nv_bfloat16* __restrict__ Bh,
                                           const __nv_bfloat16* __restrict__ Bl, int ldb, int brow0,
                                           int k0) {
    load_tile_async(st + 0 * TILE_B, Ah, lda, arow0, k0);
    load_tile_async(st + 1 * TILE_B, Al, lda, arow0, k0);
    load_tile_async(st + 2 * TILE_B, Bh, ldb, brow0, k0);
    load_tile_async(st + 3 * TILE_B, Bl, ldb, brow0, k0);
    CP_COMMIT();
}

__device__ __forceinline__ void compute_chunk(uint32_t sbase, int warp_m, int warp_n,
                                              int lane, float acc[2][8][4]) {
    const int arow = warp_m * 32 + (lane & 7) + ((lane >> 3) & 1) * 8;
    const int brow = warp_n * 64 + (lane & 7) + (lane >> 4) * 8;
    #pragma unroll
    for (int kk = 0; kk < 4; kk++) {
        const int ag = kk * 2 + (lane >> 4);
        const int bg = kk * 2 + ((lane >> 3) & 1);
        uint32_t ah[2][4], al[2][4], bh[4][4], bl[4][4];
        #pragma unroll
        for (int mt = 0; mt < 2; mt++) {
            ldmatrix_x4(ah[mt], sbase + 0 * TILE_B + swz(arow + mt * 16, ag));
            ldmatrix_x4(al[mt], sbase + 1 * TILE_B + swz(arow + mt * 16, ag));
        }
        #pragma unroll
        for (int nt2 = 0; nt2 < 4; nt2++) {
            ldmatrix_x4(bh[nt2], sbase + 2 * TILE_B + swz(brow + nt2 * 16, bg));
            ldmatrix_x4(bl[nt2], sbase + 3 * TILE_B + swz(brow + nt2 * 16, bg));
        }
        #pragma unroll
        for (int mt = 0; mt < 2; mt++)
            #pragma unroll
            for (int nt = 0; nt < 8; nt++) {
                const uint32_t* pbh = &bh[nt >> 1][(nt & 1) * 2];
                const uint32_t* pbl = &bl[nt >> 1][(nt & 1) * 2];
                mma16816(acc[mt][nt], ah[mt], pbh);
                mma16816(acc[mt][nt], ah[mt], pbl);
                mma16816(acc[mt][nt], al[mt], pbh);
            }
    }
}

__device__ void mma_mainloop(const __nv_bfloat16* __restrict__ Ah,
                             const __nv_bfloat16* __restrict__ Al, int lda, int arow0,
                             const __nv_bfloat16* __restrict__ Bh,
                             const __nv_bfloat16* __restrict__ Bl, int ldb, int brow0,
                             int K, uint32_t sb, float acc[2][8][4]) {
    const int C = K >> 6;
    const int warp = threadIdx.x >> 5, lane = threadIdx.x & 31;
    const int warp_m = warp & 3, warp_n = warp >> 2;

    #pragma unroll
    for (int mt = 0; mt < 2; mt++)
        #pragma unroll
        for (int nt = 0; nt < 8; nt++)
            #pragma unroll
            for (int i = 0; i < 4; i++) acc[mt][nt][i] = 0.f;

    fill_stage(sb + 0 * STAGE_B, Ah, Al, lda, arow0, Bh, Bl, ldb, brow0, 0);
    fill_stage(sb + 1 * STAGE_B, Ah, Al, lda, arow0, Bh, Bl, ldb, brow0, 64);

    int slot = 0;
    for (int c = 0; c < C; c++) {
        if (c + 1 < C) { CP_WAIT1(); } else { CP_WAIT0(); }
        __syncthreads();
        compute_chunk(sb + slot * STAGE_B, warp_m, warp_n, lane, acc);
        if (c + 2 < C) {
            fill_stage(sb + ((c + 2) % 3) * STAGE_B, Ah, Al, lda, arow0,
                       Bh, Bl, ldb, brow0, (c + 2) << 6);
        }
        slot = (slot + 1) % 3;
    }
}

// ----- fp16 split-2 mainloop (V proj, PV, Wo, Wf): A hi/lo, B single -----
__device__ __forceinline__ void fill_stage_f16(uint32_t st,
                                               const __half* __restrict__ Ah,
                                               const __half* __restrict__ Al, int lda, int arow0,
                                               const __half* __restrict__ B, int ldb, int brow0,
                                               int k0) {
    load_tile_async(st + 0 * TILE_B, Ah, lda, arow0, k0);
    load_tile_async(st + 1 * TILE_B, Al, lda, arow0, k0);
    load_tile_async(st + 2 * TILE_B, B, ldb, brow0, k0);
    CP_COMMIT();
}

__device__ __forceinline__ void compute_chunk_f16(uint32_t sbase, int warp_m, int warp_n,
                                                  int lane, float acc[2][8][4]) {
    const int arow = warp_m * 32 + (lane & 7) + ((lane >> 3) & 1) * 8;
    const int brow = warp_n * 64 + (lane & 7) + (lane >> 4) * 8;
    #pragma unroll
    for (int kk = 0; kk < 4; kk++) {
        const int ag = kk * 2 + (lane >> 4);
        const int bg = kk * 2 + ((lane >> 3) & 1);
        uint32_t ah[2][4], al[2][4], b[4][4];
        #pragma unroll
        for (int mt = 0; mt < 2; mt++) {
            ldmatrix_x4(ah[mt], sbase + 0 * TILE_B + swz(arow + mt * 16, ag));
            ldmatrix_x4(al[mt], sbase + 1 * TILE_B + swz(arow + mt * 16, ag));
        }
        #pragma unroll
        for (int nt2 = 0; nt2 < 4; nt2++)
            ldmatrix_x4(b[nt2], sbase + 2 * TILE_B + swz(brow + nt2 * 16, bg));
        #pragma unroll
        for (int mt = 0; mt < 2; mt++)
            #pragma unroll
            for (int nt = 0; nt < 8; nt++) {
                const uint32_t* pb = &b[nt >> 1][(nt & 1) * 2];
                mma16816h(acc[mt][nt], ah[mt], pb);
                mma16816h(acc[mt][nt], al[mt], pb);
            }
    }
}

__device__ void mma_mainloop_f16(const __half* __restrict__ Ah,
                                 const __half* __restrict__ Al, int lda, int arow0,
                                 const __half* __restrict__ B, int ldb, int brow0,
                                 int K, uint32_t sb, float acc[2][8][4]) {
    const int C = K >> 6;
    const int warp = threadIdx.x >> 5, lane = threadIdx.x & 31;
    const int warp_m = warp & 3, warp_n = warp >> 2;

    #pragma unroll
    for (int mt = 0; mt < 2; mt++)
        #pragma unroll
        for (int nt = 0; nt < 8; nt++)
            #pragma unroll
            for (int i = 0; i < 4; i++) acc[mt][nt][i] = 0.f;

    fill_stage_f16(sb + 0 * STAGE2_B, Ah, Al, lda, arow0, B, ldb, brow0, 0);
    fill_stage_f16(sb + 1 * STAGE2_B, Ah, Al, lda, arow0, B, ldb, brow0, 64);

    int slot = 0;
    for (int c = 0; c < C; c++) {
        if (c + 1 < C) { CP_WAIT1(); } else { CP_WAIT0(); }
        __syncthreads();
        compute_chunk_f16(sb + slot * STAGE2_B, warp_m, warp_n, lane, acc);
        if (c + 2 < C) {
            fill_stage_f16(sb + ((c + 2) % 3) * STAGE2_B, Ah, Al, lda, arow0,
                           B, ldb, brow0, (c + 2) << 6);
        }
        slot = (slot + 1) % 3;
    }
}

// ---------------------------------------------------------------------------
// Epilogue helpers
// ---------------------------------------------------------------------------
__device__ __forceinline__ void split2(float v, __nv_bfloat16& h, __nv_bfloat16& l) {
    h = __float2bfloat16(v);
    l = __float2bfloat16(v - __bfloat162float(h));
}
__device__ __forceinline__ void split2h(float v, __half& h, __half& l) {
    h = __float2half(v);
    l = __float2half(v - __half2float(h));
}

__device__ __forceinline__ void split_store2(__nv_bfloat16* __restrict__ H,
                                             __nv_bfloat16* __restrict__ L,
                                             size_t off, float v0, float v1) {
    __nv_bfloat16 h0, h1, l0, l1;
    split2(v0, h0, l0); split2(v1, h1, l1);
    *(__nv_bfloat162*)(H + off) = __halves2bfloat162(h0, h1);
    *(__nv_bfloat162*)(L + off) = __halves2bfloat162(l0, l1);
}

__device__ __forceinline__ void split_store2h(__half* __restrict__ H,
                                              __half* __restrict__ L,
                                              size_t off, float v0, float v1) {
    __half h0, h1, l0, l1;
    split2h(v0, h0, l0); split2h(v1, h1, l1);
    *(__half2*)(H + off) = __halves2half2(h0, h1);
    *(__half2*)(L + off) = __halves2half2(l0, l1);
}

// store 64 consecutive fp16 values (single precision tier)
__device__ __forceinline__ void store_h64(__half* __restrict__ V, size_t off, const float* v) {
    uint32_t p[32];
    #pragma unroll
    for (int j = 0; j < 64; j += 2) {
        __half2 hh = __halves2half2(__float2half(v[j]), __float2half(v[j + 1]));
        p[j >> 1] = reinterpret_cast<uint32_t&>(hh);
    }
    #pragma unroll
    for (int i = 0; i < 8; i++)
        *(uint4*)((char*)(V + off) + i * 16) = ((uint4*)p)[i];
}

#define FRAG_COORDS() \
    const int warp = threadIdx.x >> 5, lane = threadIdx.x & 31; \
    const int warp_m = warp & 3, warp_n = warp >> 2; \
    const int gid = lane >> 2, t4 = lane & 3;

// ---------------------------------------------------------------------------
// GEMM kernels
// ---------------------------------------------------------------------------

// Q/K projections: bf16 split-3, split-bf16 out
__global__ __launch_bounds__(256, 1)
void k_gemm_bias_split(const __nv_bfloat16* __restrict__ Ah, const __nv_bfloat16* __restrict__ Al, int lda,
                       const __nv_bfloat16* __restrict__ Bh, const __nv_bfloat16* __restrict__ Bl, int ldb,
                       const float* __restrict__ bias,
                       __nv_bfloat16* __restrict__ Ch, __nv_bfloat16* __restrict__ Cl, int ldc, int K) {
    extern __shared__ char smem[];
    const uint32_t sb = smem_to_u32(smem);
    const int m0 = blockIdx.y * 128, n0 = blockIdx.x * 128;
    float acc[2][8][4];
    mma_mainloop(Ah, Al, lda, m0, Bh, Bl, ldb, n0, K, sb, acc);
    FRAG_COORDS();
    #pragma unroll
    for (int mt = 0; mt < 2; mt++)
        #pragma unroll
        for (int nt = 0; nt < 8; nt++) {
            const int col = n0 + warp_n * 64 + nt * 8 + t4 * 2;
            const float bx = bias[col], by = bias[col + 1];
            const int r0 = m0 + warp_m * 32 + mt * 16 + gid;
            split_store2(Ch, Cl, (size_t)r0 * ldc + col, acc[mt][nt][0] + bx, acc[mt][nt][1] + by);
            split_store2(Ch, Cl, (size_t)(r0 + 8) * ldc + col, acc[mt][nt][2] + bx, acc[mt][nt][3] + by);
        }
}

// V projection (fp16 path): A = x split-2 fp16, B = Wv^T single fp16;
// writes transposed vT[bh][dim][token] single fp16
__global__ __launch_bounds__(256, 1)
void k_gemm_v(const __half* __restrict__ Ah, const __half* __restrict__ Al,
              const __half* __restrict__ B, const float* __restrict__ bias,
              __half* __restrict__ VT) {
    extern __shared__ char smem[];
    const uint32_t sb = smem_to_u32(smem);
    const int m0 = blockIdx.y * 128, n0 = blockIdx.x * 128;
    float acc[2][8][4];
    mma_mainloop_f16(Ah, Al, DMODEL, m0, B, DMODEL, n0, DMODEL, sb, acc);
    FRAG_COORDS();

    float* smf = (float*)smem;  // [128][129]
    __syncthreads();
    #pragma unroll
    for (int mt = 0; mt < 2; mt++)
        #pragma unroll
        for (int nt = 0; nt < 8; nt++) {
            const int lc = warp_n * 64 + nt * 8 + t4 * 2;
            const float bx = bias[n0 + lc], by = bias[n0 + lc + 1];
            const int lr = warp_m * 32 + mt * 16 + gid;
            smf[lr * 129 + lc] = acc[mt][nt][0] + bx;
            smf[lr * 129 + lc + 1] = acc[mt][nt][1] + by;
            smf[(lr + 8) * 129 + lc] = acc[mt][nt][2] + bx;
            smf[(lr + 8) * 129 + lc + 1] = acc[mt][nt][3] + by;
        }
    __syncthreads();

    const int b = m0 / SEQ, tok0 = m0 % SEQ;
    const int h = n0 / DMODEL, dim0 = n0 % DMODEL;
    const int c = threadIdx.x & 127;
    const int seg = threadIdx.x >> 7;
    float vv[64];
    #pragma unroll
    for (int i = 0; i < 64; i++) vv[i] = smf[(seg * 64 + i) * 129 + c];
    const size_t off = ((size_t)(b * 3 + h) * DMODEL + dim0 + c) * SEQ + tok0 + seg * 64;
    store_h64(VT, off, vv);
}

// scores: bf16 split-3 + exact reference masking; upper tiles skipped
__global__ __launch_bounds__(256, 1)
void k_scores(const __nv_bfloat16* __restrict__ qh, const __nv_bfloat16* __restrict__ ql,
              const __nv_bfloat16* __restrict__ kh, const __nv_bfloat16* __restrict__ kl,
              float* __restrict__ s) {
    const int bh = blockIdx.z;
    const int b = bh / 3, h = bh % 3;
    const int m0 = blockIdx.y * 128, n0 = blockIdx.x * 128;
    if (n0 > m0) return;
    float* C = s + (size_t)bh * SEQ * SEQ;

    extern __shared__ char smem[];
    const uint32_t sb = smem_to_u32(smem);
    float acc[2][8][4];
    mma_mainloop(qh + h * DMODEL, ql + h * DMODEL, DQKV, b * SEQ + m0,
                 kh + h * DMODEL, kl + h * DMODEL, DQKV, b * SEQ + n0,
                 DMODEL, sb, acc);
    FRAG_COORDS();
    #pragma unroll
    for (int mt = 0; mt < 2; mt++)
        #pragma unroll
        for (int nt = 0; nt < 8; nt++) {
            const int gj = n0 + warp_n * 64 + nt * 8 + t4 * 2;
            #pragma unroll
            for (int half = 0; half < 2; half++) {
                const int gi = m0 + warp_m * 32 + mt * 16 + gid + half * 8;
                float v0 = acc[mt][nt][half * 2];
                float v1 = acc[mt][nt][half * 2 + 1];
                if (gj > gi || v0 == 0.0f) v0 = -99999.0f;
                if (gj + 1 > gi || v1 == 0.0f) v1 = -99999.0f;
                *(float2*)(C + (size_t)gi * SEQ + gj) = make_float2(v0, v1);
            }
        }
}

// PV (fp16 path): A = P split-2 fp16, B = vT single fp16; K truncated at diagonal;
// split-fp16 out into [8192,2304]
__global__ __launch_bounds__(256, 1)
void k_pv(const __half* __restrict__ ph, const __half* __restrict__ pl,
          const __half* __restrict__ vt,
          __half* __restrict__ oh, __half* __restrict__ ol) {
    extern __shared__ char smem[];
    const uint32_t sb = smem_to_u32(smem);
    const int bh = blockIdx.z;
    const int b = bh / 3, h = bh % 3;
    const int m0 = blockIdx.y * 128, n0 = blockIdx.x * 128;
    float acc[2][8][4];
    mma_mainloop_f16(ph + (size_t)bh * SEQ * SEQ, pl + (size_t)bh * SEQ * SEQ, SEQ, m0,
                     vt + (size_t)bh * DMODEL * SEQ, SEQ, n0, m0 + 128, sb, acc);
    FRAG_COORDS();
    #pragma unroll
    for (int mt = 0; mt < 2; mt++)
        #pragma unroll
        for (int nt = 0; nt < 8; nt++) {
            const int col = h * DMODEL + n0 + warp_n * 64 + nt * 8 + t4 * 2;
            const int r0 = b * SEQ + m0 + warp_m * 32 + mt * 16 + gid;
            split_store2h(oh, ol, (size_t)r0 * DQKV + col, acc[mt][nt][0], acc[mt][nt][1]);
            split_store2h(oh, ol, (size_t)(r0 + 8) * DQKV + col, acc[mt][nt][2], acc[mt][nt][3]);
        }
}

// Wo projection (fp16 path): fp32 out
__global__ __launch_bounds__(256, 1)
void k_gemm_wo(const __half* __restrict__ Ah, const __half* __restrict__ Al,
               const __half* __restrict__ B, const float* __restrict__ bias,
               float* __restrict__ C) {
    extern __shared__ char smem[];
    const uint32_t sb = smem_to_u32(smem);
    const int m0 = blockIdx.y * 128, n0 = blockIdx.x * 128;
    float acc[2][8][4];
    mma_mainloop_f16(Ah, Al, DQKV, m0, B, DQKV, n0, DQKV, sb, acc);
    FRAG_COORDS();
    #pragma unroll
    for (int mt = 0; mt < 2; mt++)
        #pragma unroll
        for (int nt = 0; nt < 8; nt++) {
            const int col = n0 + warp_n * 64 + nt * 8 + t4 * 2;
            const float bx = bias[col], by = bias[col + 1];
            const int r0 = m0 + warp_m * 32 + mt * 16 + gid;
            *(float2*)(C + (size_t)r0 * DMODEL + col) =
                make_float2(acc[mt][nt][0] + bx, acc[mt][nt][1] + by);
            *(float2*)(C + (size_t)(r0 + 8) * DMODEL + col) =
                make_float2(acc[mt][nt][2] + bx, acc[mt][nt][3] + by);
        }
}

// final (fp16 path): out = leaky_relu(A*Wf^T + bf)
__global__ __launch_bounds__(256, 1)
void k_final(const __half* __restrict__ Ah, const __half* __restrict__ Al,
             const __half* __restrict__ B, const float* __restrict__ bias,
             float* __restrict__ out) {
    extern __shared__ char smem[];
    const uint32_t sb = smem_to_u32(smem);
    const int m0 = blockIdx.y * 128, n0 = blockIdx.x * 128;
    float acc[2][8][4];
    mma_mainloop_f16(Ah, Al, DMODEL, m0, B, DMODEL, n0, DMODEL, sb, acc);
    FRAG_COORDS();
    #pragma unroll
    for (int mt = 0; mt < 2; mt++)
        #pragma unroll
        for (int nt = 0; nt < 8; nt++) {
            const int col = n0 + warp_n * 64 + nt * 8 + t4 * 2;
            const float bx = bias[col], by = bias[col + 1];
            const int r0 = m0 + warp_m * 32 + mt * 16 + gid;
            float t0 = acc[mt][nt][0] + bx, t1 = acc[mt][nt][1] + by;
            float t2 = acc[mt][nt][2] + bx, t3 = acc[mt][nt][3] + by;
            t0 = t0 > 0.f ? t0 : 0.01f * t0;
            t1 = t1 > 0.f ? t1 : 0.01f * t1;
            t2 = t2 > 0.f ? t2 : 0.01f * t2;
            t3 = t3 > 0.f ? t3 : 0.01f * t3;
            *(float2*)(out + (size_t)r0 * DMODEL + col) = make_float2(t0, t1);
            *(float2*)(out + (size_t)(r0 + 8) * DMODEL + col) = make_float2(t2, t3);
        }
}

// ---------------------------------------------------------------------------
// Non-GEMM kernels
// ---------------------------------------------------------------------------
// x -> bf16 hi/lo (Q/K path) + fp16 hi/lo (V path)
__global__ void split_kernel(const float* __restrict__ src,
                             __nv_bfloat16* __restrict__ H, __nv_bfloat16* __restrict__ L,
                             __half* __restrict__ H2, __half* __restrict__ L2, int n) {
    int i = (blockIdx.x * 256 + threadIdx.x) * 4;
    if (i >= n) return;
    float4 v = *(const float4*)(src + i);
    {
        __nv_bfloat16 h0, h1, h2, h3, l0, l1, l2, l3;
        split2(v.x, h0, l0); split2(v.y, h1, l1); split2(v.z, h2, l2); split2(v.w, h3, l3);
        __nv_bfloat162 a = __halves2bfloat162(h0, h1), b2 = __halves2bfloat162(h2, h3);
        __nv_bfloat162 c = __halves2bfloat162(l0, l1), d = __halves2bfloat162(l2, l3);
        uint2 hp, lp;
        hp.x = reinterpret_cast<uint32_t&>(a); hp.y = reinterpret_cast<uint32_t&>(b2);
        lp.x = reinterpret_cast<uint32_t&>(c); lp.y = reinterpret_cast<uint32_t&>(d);
        *(uint2*)(H + i) = hp;
        *(uint2*)(L + i) = lp;
    }
    {
        __half h0, h1, h2, h3, l0, l1, l2, l3;
        split2h(v.x, h0, l0); split2h(v.y, h1, l1); split2h(v.z, h2, l2); split2h(v.w, h3, l3);
        __half2 a = __halves2half2(h0, h1), b2 = __halves2half2(h2, h3);
        __half2 c = __halves2half2(l0, l1), d = __halves2half2(l2, l3);
        uint2 hp, lp;
        hp.x = reinterpret_cast<uint32_t&>(a); hp.y = reinterpret_cast<uint32_t&>(b2);
        lp.x = reinterpret_cast<uint32_t&>(c); lp.y = reinterpret_cast<uint32_t&>(d);
        *(uint2*)(H2 + i) = hp;
        *(uint2*)(L2 + i) = lp;
    }
}

// Wq/Wk -> bf16 hi/lo transpose; Wv -> single fp16 transpose (z selects)
__global__ void transpose_split_qkv(const float* __restrict__ Wq, const float* __restrict__ Wk,
                                    const float* __restrict__ Wv,
                                    __nv_bfloat16* __restrict__ QH, __nv_bfloat16* __restrict__ QL,
                                    __nv_bfloat16* __restrict__ KH, __nv_bfloat16* __restrict__ KL,
                                    __half* __restrict__ V16) {
    const float* W = (blockIdx.z == 0) ? Wq : (blockIdx.z == 1) ? Wk : Wv;
    __shared__ float t[32][33];
    const int n0 = blockIdx.x * 32, k0 = blockIdx.y * 32;
    const int tx = threadIdx.x, ty = threadIdx.y;
    #pragma unroll
    for (int i = ty; i < 32; i += 8)
        t[i][tx] = W[(size_t)(k0 + i) * DQKV + n0 + tx];
    __syncthreads();
    if (blockIdx.z == 2) {
        #pragma unroll
        for (int i = ty; i < 32; i += 8) {
            const size_t off = (size_t)(n0 + i) * DMODEL + k0 + tx;
            V16[off] = __float2half(t[tx][i]);
        }
    } else {
        __nv_bfloat16* TH = (blockIdx.z == 0) ? QH : KH;
        __nv_bfloat16* TL = (blockIdx.z == 0) ? QL : KL;
        #pragma unroll
        for (int i = ty; i < 32; i += 8) {
            float v = t[tx][i];
            __nv_bfloat16 h, l;
            split2(v, h, l);
            const size_t off = (size_t)(n0 + i) * DMODEL + k0 + tx;
            TH[off] = h;
            TL[off] = l;
        }
    }
}

// W[K,N] fp32 -> Wt[N,K] single fp16 (Wo, Wf)
__global__ void transpose_f16(const float* __restrict__ W, int K, int N,
                              __half* __restrict__ T) {
    __shared__ float t[32][33];
    const int n0 = blockIdx.x * 32, k0 = blockIdx.y * 32;
    const int tx = threadIdx.x, ty = threadIdx.y;
    #pragma unroll
    for (int i = ty; i < 32; i += 8)
        t[i][tx] = W[(size_t)(k0 + i) * N + n0 + tx];
    __syncthreads();
    #pragma unroll
    for (int i = ty; i < 32; i += 8) {
        const size_t off = (size_t)(n0 + i) * K + k0 + tx;
        T[off] = __float2half(t[tx][i]);
    }
}

// causal-aware row softmax -> split-fp16 probabilities
__global__ void softmax_split_causal(const float* __restrict__ s,
                                     __half* __restrict__ PH, __half* __restrict__ PL) {
    const int row = blockIdx.x & (SEQ - 1);
    const int L = ((row >> 7) + 1) << 7;
    const float* p = s + (size_t)blockIdx.x * SEQ;
    __half* ph = PH + (size_t)blockIdx.x * SEQ;
    __half* pl = PL + (size_t)blockIdx.x * SEQ;
    const int tid = threadIdx.x;
    const int lane = tid & 31, wid = tid >> 5;
    __shared__ float red[8];

    float v[8];
    int cnt = 0;
    float m = -3.4e38f;
    for (int j = tid; j < L; j += 256) { float x = p[j]; v[cnt++] = x; m = fmaxf(m, x); }
    #pragma unroll
    for (int o = 16; o; o >>= 1) m = fmaxf(m, __shfl_xor_sync(0xffffffffu, m, o));
    if (lane == 0) red[wid] = m;
    __syncthreads();
    float mall = red[0];
    #pragma unroll
    for (int i = 1; i < 8; i++) mall = fmaxf(mall, red[i]);

    float ssum = 0.f;
    for (int i = 0; i < cnt; i++) {
        v[i] = exp2f((v[i] - mall) * 1.4426950408889634f);
        ssum += v[i];
    }
    #pragma unroll
    for (int o = 16; o; o >>= 1) ssum += __shfl_xor_sync(0xffffffffu, ssum, o);
    __syncthreads();
    if (lane == 0) red[wid] = ssum;
    __syncthreads();
    float tot = 0.f;
    #pragma unroll
    for (int i = 0; i < 8; i++) tot += red[i];
    const float inv = 1.0f / tot;

    int i2 = 0;
    for (int j = tid; j < L; j += 256) {
        float pv = v[i2++] * inv;
        __half h, l;
        split2h(pv, h, l);
        ph[j] = h;
        pl[j] = l;
    }
}

__global__ void reduce_partial(const float* __restrict__ a, float* __restrict__ part) {
    const int n = MTOK * DMODEL;
    float s = 0.f;
    for (int i = blockIdx.x * 256 + threadIdx.x; i < n; i += 1024 * 256) s += a[i];
    __shared__ float sm[256];
    sm[threadIdx.x] = s; __syncthreads();
    #pragma unroll
    for (int st = 128; st > 0; st >>= 1) {
        if (threadIdx.x < st) sm[threadIdx.x] += sm[threadIdx.x + st];
        __syncthreads();
    }
    if (threadIdx.x == 0) part[blockIdx.x] = sm[0];
}

__global__ void reduce_final(const float* __restrict__ part, float* __restrict__ mean) {
    float s = 0.f;
    for (int i = threadIdx.x; i < 1024; i += 256) s += part[i];
    __shared__ float sm[256];
    sm[threadIdx.x] = s; __syncthreads();
    #pragma unroll
    for (int st = 128; st > 0; st >>= 1) {
        if (threadIdx.x < st) sm[threadIdx.x] += sm[threadIdx.x + st];
        __syncthreads();
    }
    if (threadIdx.x == 0) mean[0] = sm[0] * (1.0f / ((float)MTOK * DMODEL));
}

// n = a - mean + x, split-fp16
__global__ void fuse_split_kernel(const float* __restrict__ a, const float* __restrict__ x,
                                  const float* __restrict__ meanp,
                                  __half* __restrict__ NH, __half* __restrict__ NL, int n) {
    const float mean = meanp[0];
    int i = (blockIdx.x * 256 + threadIdx.x) * 4;
    if (i >= n) return;
    float4 va = *(const float4*)(a + i);
    float4 vx = *(const float4*)(x + i);
    float f0 = va.x - mean + vx.x, f1 = va.y - mean + vx.y;
    float f2 = va.z - mean + vx.z, f3 = va.w - mean + vx.w;
    __half h0, h1, h2, h3, l0, l1, l2, l3;
    split2h(f0, h0, l0); split2h(f1, h1, l1); split2h(f2, h2, l2); split2h(f3, h3, l3);
    __half2 aa = __halves2half2(h0, h1), bb = __halves2half2(h2, h3);
    __half2 cc = __halves2half2(l0, l1), dd = __halves2half2(l2, l3);
    uint2 hp, lp;
    hp.x = reinterpret_cast<uint32_t&>(aa); hp.y = reinterpret_cast<uint32_t&>(bb);
    lp.x = reinterpret_cast<uint32_t&>(cc); lp.y = reinterpret_cast<uint32_t&>(dd);
    *(uint2*)(NH + i) = hp;
    *(uint2*)(NL + i) = lp;
}

// ---------------------------------------------------------------------------
extern "C" void kernel_launch(void* const* d_in, const int* in_sizes, int n_in,
                              void* d_out, int out_size) {
    const float* x  = (const float*)d_in[0];
    const float* Wq = (const float*)d_in[1];
    const float* bq = (const float*)d_in[2];
    const float* Wk = (const float*)d_in[3];
    const float* bk = (const float*)d_in[4];
    const float* Wv = (const float*)d_in[5];
    const float* bv = (const float*)d_in[6];
    const float* Wo = (const float*)d_in[7];
    const float* bo = (const float*)d_in[8];
    const float* Wf = (const float*)d_in[9];
    const float* bf = (const float*)d_in[10];
    float* out = (float*)d_out;

    static bool attr_done = false;
    if (!attr_done) {
        cudaFuncSetAttribute(k_gemm_bias_split, cudaFuncAttributeMaxDynamicSharedMemorySize, DYN_SMEM);
        cudaFuncSetAttribute(k_scores,          cudaFuncAttributeMaxDynamicSharedMemorySize, DYN_SMEM);
        cudaFuncSetAttribute(k_gemm_v,          cudaFuncAttributeMaxDynamicSharedMemorySize, DYN_SMEM2);
        cudaFuncSetAttribute(k_pv,              cudaFuncAttributeMaxDynamicSharedMemorySize, DYN_SMEM2);
        cudaFuncSetAttribute(k_gemm_wo,         cudaFuncAttributeMaxDynamicSharedMemorySize, DYN_SMEM2);
        cudaFuncSetAttribute(k_final,           cudaFuncAttributeMaxDynamicSharedMemorySize, DYN_SMEM2);
        attr_done = true;
    }

    __nv_bfloat16 *xh, *xl, *wqth, *wqtl, *wkth, *wktl, *qh, *ql, *kh, *kl;
    __half *xh2, *xl2, *wvt16, *wot16, *wft16, *vt16, *ph, *pl, *oh, *ol, *nh, *nl;
    float *s, *a, *part, *mean;
    cudaGetSymbolAddress((void**)&xh, g_xh);     cudaGetSymbolAddress((void**)&xl, g_xl);
    cudaGetSymbolAddress((void**)&xh2, g_xh2);   cudaGetSymbolAddress((void**)&xl2, g_xl2);
    cudaGetSymbolAddress((void**)&wqth, g_wqth); cudaGetSymbolAddress((void**)&wqtl, g_wqtl);
    cudaGetSymbolAddress((void**)&wkth, g_wkth); cudaGetSymbolAddress((void**)&wktl, g_wktl);
    cudaGetSymbolAddress((void**)&wvt16, g_wvt16);
    cudaGetSymbolAddress((void**)&wot16, g_wot16);
    cudaGetSymbolAddress((void**)&wft16, g_wft16);
    cudaGetSymbolAddress((void**)&qh, g_qh);     cudaGetSymbolAddress((void**)&ql, g_ql);
    cudaGetSymbolAddress((void**)&kh, g_kh);     cudaGetSymbolAddress((void**)&kl, g_kl);
    cudaGetSymbolAddress((void**)&vt16, g_vt16);
    cudaGetSymbolAddress((void**)&s, g_s);
    cudaGetSymbolAddress((void**)&ph, g_ph);     cudaGetSymbolAddress((void**)&pl, g_pl);
    cudaGetSymbolAddress((void**)&oh, g_oh);     cudaGetSymbolAddress((void**)&ol, g_ol);
    cudaGetSymbolAddress((void**)&a, g_a);
    cudaGetSymbolAddress((void**)&nh, g_nh);     cudaGetSymbolAddress((void**)&nl, g_nl);
    cudaGetSymbolAddress((void**)&part, g_part); cudaGetSymbolAddress((void**)&mean, g_mean);

    // 0) splits / transposes of inputs
    const int nx = MTOK * DMODEL;
    split_kernel<<<(nx / 4 + 255) / 256, 256>>>(x, xh, xl, xh2, xl2, nx);
    transpose_split_qkv<<<dim3(DQKV / 32, DMODEL / 32, 3), dim3(32, 8)>>>(
        Wq, Wk, Wv, wqth, wqtl, wkth, wktl, wvt16);
    transpose_f16<<<dim3(DMODEL / 32, DQKV / 32), dim3(32, 8)>>>(Wo, DQKV, DMODEL, wot16);
    transpose_f16<<<dim3(DMODEL / 32, DMODEL / 32), dim3(32, 8)>>>(Wf, DMODEL, DMODEL, wft16);

    // 1) Q, K projections (bf16 split-3), V projection (fp16 split-2, transposed out)
    dim3 qkvGrid(DQKV / 128, MTOK / 128);
    k_gemm_bias_split<<<qkvGrid, 256, DYN_SMEM>>>(xh, xl, DMODEL, wqth, wqtl, DMODEL, bq, qh, ql, DQKV, DMODEL);
    k_gemm_bias_split<<<qkvGrid, 256, DYN_SMEM>>>(xh, xl, DMODEL, wkth, wktl, DMODEL, bk, kh, kl, DQKV, DMODEL);
    k_gemm_v<<<qkvGrid, 256, DYN_SMEM2>>>(xh2, xl2, wvt16, bv, vt16);

    // 2) masked scores (lower-triangle tiles only)
    k_scores<<<dim3(SEQ / 128, SEQ / 128, NBH), 256, DYN_SMEM>>>(qh, ql, kh, kl, s);

    // 3) causal softmax -> split-fp16 P
    softmax_split_causal<<<NBH * SEQ, 256>>>(s, ph, pl);

    // 4) o = attn @ v (fp16 split-2, causal-truncated k-loop)
    k_pv<<<dim3(DMODEL / 128, SEQ / 128, NBH), 256, DYN_SMEM2>>>(ph, pl, vt16, oh, ol);

    // 5) a = o @ Wo + bo (fp16 split-2, fp32 out)
    k_gemm_wo<<<dim3(DMODEL / 128, MTOK / 128), 256, DYN_SMEM2>>>(oh, ol, wot16, bo, a);

    // 6) deterministic global mean
    reduce_partial<<<1024, 256>>>(a, part);
    reduce_final<<<1, 256>>>(part, mean);

    // 7) n = a - mean + x (split-fp16)
    fuse_split_kernel<<<(nx / 4 + 255) / 256, 256>>>(a, x, mean, nh, nl, nx);

    // 8) out = leaky_relu(n @ Wf + bf) (fp16 split-2)
    k_final<<<dim3(DMODEL / 128, MTOK / 128), 256, DYN_SMEM2>>>(nh, nl, wft16, bf, out);
}

// round 13
// speedup vs baseline: 3.6515x; 1.0175x over previous
#include <cuda_runtime.h>
#include <cuda_bf16.h>
#include <cuda_fp16.h>
#include <cstdint>
#include <cstddef>

// ===========================================================================
// B=4, S=2048, D=768, H=3.  MTOK=8192, DQKV=2304.
// Q/K proj + scores: bf16 split-3 (AhBh+AhBl+AlBh), 3 MMAs -> err ~1e-5.
// V proj, PV, Wo, Wf: fp16 A-split-2 x B-single, 2 MMAs -> err ~3e-4.
// R11: fp16 path uses 2-stage pipeline (96KB smem) + launch_bounds(256,2)
//      so two CTAs co-reside per SM and cover each other's sync bubbles.
// ===========================================================================

#define MTOK 8192
#define DMODEL 768
#define DQKV 2304
#define SEQ 2048
#define NBH 12

#define TILE_B 16384            // 128 rows x 128B
#define STAGE_B (4 * TILE_B)    // bf16 path: Ah, Al, Bh, Bl
#define DYN_SMEM (3 * STAGE_B)  // 196608
#define STAGE2_B (3 * TILE_B)   // f16 path: Ah, Al, B
#define DYN_SMEM2 (2 * STAGE2_B) // 98304 -> 2 CTAs/SM

// ---------------------------------------------------------------------------
// PTX helpers (non-'a' ISA only)
// ---------------------------------------------------------------------------
__device__ __forceinline__ uint32_t smem_to_u32(const void* p) {
    uint32_t a;
    asm("{ .reg .u64 t; cvta.to.shared.u64 t, %1; cvt.u32.u64 %0, t; }" : "=r"(a) : "l"(p));
    return a;
}

__device__ __forceinline__ void ldmatrix_x4(uint32_t* r, uint32_t addr) {
    asm volatile("ldmatrix.sync.aligned.m8n8.x4.shared.b16 {%0,%1,%2,%3}, [%4];"
                 : "=r"(r[0]), "=r"(r[1]), "=r"(r[2]), "=r"(r[3]) : "r"(addr));
}

__device__ __forceinline__ void mma16816(float* c, const uint32_t* a, const uint32_t* b) {
    asm volatile(
        "mma.sync.aligned.m16n8k16.row.col.f32.bf16.bf16.f32 "
        "{%0,%1,%2,%3}, {%4,%5,%6,%7}, {%8,%9}, {%0,%1,%2,%3};"
        : "+f"(c[0]), "+f"(c[1]), "+f"(c[2]), "+f"(c[3])
        : "r"(a[0]), "r"(a[1]), "r"(a[2]), "r"(a[3]), "r"(b[0]), "r"(b[1]));
}

__device__ __forceinline__ void mma16816h(float* c, const uint32_t* a, const uint32_t* b) {
    asm volatile(
        "mma.sync.aligned.m16n8k16.row.col.f32.f16.f16.f32 "
        "{%0,%1,%2,%3}, {%4,%5,%6,%7}, {%8,%9}, {%0,%1,%2,%3};"
        : "+f"(c[0]), "+f"(c[1]), "+f"(c[2]), "+f"(c[3])
        : "r"(a[0]), "r"(a[1]), "r"(a[2]), "r"(a[3]), "r"(b[0]), "r"(b[1]));
}

#define CP_ASYNC16(dst, src) \
    asm volatile("cp.async.cg.shared.global [%0], [%1], 16;" :: "r"(dst), "l"(src))
#define CP_COMMIT() asm volatile("cp.async.commit_group;" ::: "memory")
#define CP_WAIT0()  asm volatile("cp.async.wait_group 0;" ::: "memory")
#define CP_WAIT1()  asm volatile("cp.async.wait_group 1;" ::: "memory")

__device__ __forceinline__ uint32_t swz(int r, int g) {
    return (uint32_t)(r * 128 + ((g ^ (r & 7)) << 4));
}

// ---------------------------------------------------------------------------
// Scratch (allocation-free device globals)
// ---------------------------------------------------------------------------
__device__ __nv_bfloat16 g_xh[(size_t)MTOK * DMODEL], g_xl[(size_t)MTOK * DMODEL];
__device__ __half        g_xh2[(size_t)MTOK * DMODEL], g_xl2[(size_t)MTOK * DMODEL];
__device__ __nv_bfloat16 g_wqth[(size_t)DQKV * DMODEL], g_wqtl[(size_t)DQKV * DMODEL];
__device__ __nv_bfloat16 g_wkth[(size_t)DQKV * DMODEL], g_wktl[(size_t)DQKV * DMODEL];
__device__ __half        g_wvt16[(size_t)DQKV * DMODEL];
__device__ __half        g_wot16[(size_t)DMODEL * DQKV];
__device__ __half        g_wft16[(size_t)DMODEL * DMODEL];
__device__ __nv_bfloat16 g_qh[(size_t)MTOK * DQKV], g_ql[(size_t)MTOK * DQKV];
__device__ __nv_bfloat16 g_kh[(size_t)MTOK * DQKV], g_kl[(size_t)MTOK * DQKV];
__device__ __half        g_vt16[(size_t)NBH * DMODEL * SEQ];
__device__ float         g_s[(size_t)NBH * SEQ * SEQ];
__device__ __half        g_ph[(size_t)NBH * SEQ * SEQ], g_pl[(size_t)NBH * SEQ * SEQ];
__device__ __half        g_oh[(size_t)MTOK * DQKV], g_ol[(size_t)MTOK * DQKV];
__device__ float         g_a[(size_t)MTOK * DMODEL];
__device__ __half        g_nh[(size_t)MTOK * DMODEL], g_nl[(size_t)MTOK * DMODEL];
__device__ float         g_part[1024];
__device__ float         g_mean[1];

// ---------------------------------------------------------------------------
// Shared engine pieces
// ---------------------------------------------------------------------------
template <typename T>
__device__ __forceinline__ void load_tile_async(uint32_t sbase, const T* __restrict__ G,
                                                int ld, int row0, int k0) {
    const int t = threadIdx.x;
    const int g = t & 7;
    const int r = t >> 3;
    const T* src = G + (size_t)(row0 + r) * ld + k0 + g * 8;
    #pragma unroll
    for (int p = 0; p < 4; p++) {
        CP_ASYNC16(sbase + swz(r + p * 32, g), src + (size_t)p * 32 * ld);
    }
}

// ----- bf16 split-3 mainloop (Q/K proj, scores): 3-stage, 1 sync/chunk -----
__device__ __forceinline__ void fill_stage(uint32_t st,
                                           const __nv_bfloat16* __restrict__ Ah,
                                           const __nv_bfloat16* __restrict__ Al, int lda, int arow0,
                                           const __nv_bfloat16* __restrict__ Bh,
                                           const __nv_bfloat16* __restrict__ Bl, int ldb, int brow0,
                                           int k0) {
    load_tile_async(st + 0 * TILE_B, Ah, lda, arow0, k0);
    load_tile_async(st + 1 * TILE_B, Al, lda, arow0, k0);
    load_tile_async(st + 2 * TILE_B, Bh, ldb, brow0, k0);
    load_tile_async(st + 3 * TILE_B, Bl, ldb, brow0, k0);
    CP_COMMIT();
}

__device__ __forceinline__ void compute_chunk(uint32_t sbase, int warp_m, int warp_n,
                                              int lane, float acc[2][8][4]) {
    const int arow = warp_m * 32 + (lane & 7) + ((lane >> 3) & 1) * 8;
    const int brow = warp_n * 64 + (lane & 7) + (lane >> 4) * 8;
    #pragma unroll
    for (int kk = 0; kk < 4; kk++) {
        const int ag = kk * 2 + (lane >> 4);
        const int bg = kk * 2 + ((lane >> 3) & 1);
        uint32_t ah[2][4], al[2][4], bh[4][4], bl[4][4];
        #pragma unroll
        for (int mt = 0; mt < 2; mt++) {
            ldmatrix_x4(ah[mt], sbase + 0 * TILE_B + swz(arow + mt * 16, ag));
            ldmatrix_x4(al[mt], sbase + 1 * TILE_B + swz(arow + mt * 16, ag));
        }
        #pragma unroll
        for (int nt2 = 0; nt2 < 4; nt2++) {
            ldmatrix_x4(bh[nt2], sbase + 2 * TILE_B + swz(brow + nt2 * 16, bg));
            ldmatrix_x4(bl[nt2], sbase + 3 * TILE_B + swz(brow + nt2 * 16, bg));
        }
        #pragma unroll
        for (int mt = 0; mt < 2; mt++)
            #pragma unroll
            for (int nt = 0; nt < 8; nt++) {
                const uint32_t* pbh = &bh[nt >> 1][(nt & 1) * 2];
                const uint32_t* pbl = &bl[nt >> 1][(nt & 1) * 2];
                mma16816(acc[mt][nt], ah[mt], pbh);
                mma16816(acc[mt][nt], ah[mt], pbl);
                mma16816(acc[mt][nt], al[mt], pbh);
            }
    }
}

__device__ void mma_mainloop(const __nv_bfloat16* __restrict__ Ah,
                             const __nv_bfloat16* __restrict__ Al, int lda, int arow0,
                             const __nv_bfloat16* __restrict__ Bh,
                             const __nv_bfloat16* __restrict__ Bl, int ldb, int brow0,
                             int K, uint32_t sb, float acc[2][8][4]) {
    const int C = K >> 6;
    const int warp = threadIdx.x >> 5, lane = threadIdx.x & 31;
    const int warp_m = warp & 3, warp_n = warp >> 2;

    #pragma unroll
    for (int mt = 0; mt < 2; mt++)
        #pragma unroll
        for (int nt = 0; nt < 8; nt++)
            #pragma unroll
            for (int i = 0; i < 4; i++) acc[mt][nt][i] = 0.f;

    fill_stage(sb + 0 * STAGE_B, Ah, Al, lda, arow0, Bh, Bl, ldb, brow0, 0);
    fill_stage(sb + 1 * STAGE_B, Ah, Al, lda, arow0, Bh, Bl, ldb, brow0, 64);

    int slot = 0;
    for (int c = 0; c < C; c++) {
        if (c + 1 < C) { CP_WAIT1(); } else { CP_WAIT0(); }
        __syncthreads();
        compute_chunk(sb + slot * STAGE_B, warp_m, warp_n, lane, acc);
        if (c + 2 < C) {
            fill_stage(sb + ((c + 2) % 3) * STAGE_B, Ah, Al, lda, arow0,
                       Bh, Bl, ldb, brow0, (c + 2) << 6);
        }
        slot = (slot + 1) % 3;
    }
}

// ----- fp16 split-2 mainloop: 2-stage (96KB), 2 syncs/chunk, 2 CTAs/SM -----
__device__ __forceinline__ void fill_stage_f16(uint32_t st,
                                               const __half* __restrict__ Ah,
                                               const __half* __restrict__ Al, int lda, int arow0,
                                               const __half* __restrict__ B, int ldb, int brow0,
                                               int k0) {
    load_tile_async(st + 0 * TILE_B, Ah, lda, arow0, k0);
    load_tile_async(st + 1 * TILE_B, Al, lda, arow0, k0);
    load_tile_async(st + 2 * TILE_B, B, ldb, brow0, k0);
    CP_COMMIT();
}

__device__ __forceinline__ void compute_chunk_f16(uint32_t sbase, int warp_m, int warp_n,
                                                  int lane, float acc[2][8][4]) {
    const int arow = warp_m * 32 + (lane & 7) + ((lane >> 3) & 1) * 8;
    const int brow = warp_n * 64 + (lane & 7) + (lane >> 4) * 8;
    #pragma unroll
    for (int kk = 0; kk < 4; kk++) {
        const int ag = kk * 2 + (lane >> 4);
        const int bg = kk * 2 + ((lane >> 3) & 1);
        uint32_t ah[2][4], al[2][4], b[4][4];
        #pragma unroll
        for (int mt = 0; mt < 2; mt++) {
            ldmatrix_x4(ah[mt], sbase + 0 * TILE_B + swz(arow + mt * 16, ag));
            ldmatrix_x4(al[mt], sbase + 1 * TILE_B + swz(arow + mt * 16, ag));
        }
        #pragma unroll
        for (int nt2 = 0; nt2 < 4; nt2++)
            ldmatrix_x4(b[nt2], sbase + 2 * TILE_B + swz(brow + nt2 * 16, bg));
        #pragma unroll
        for (int mt = 0; mt < 2; mt++)
            #pragma unroll
            for (int nt = 0; nt < 8; nt++) {
                const uint32_t* pb = &b[nt >> 1][(nt & 1) * 2];
                mma16816h(acc[mt][nt], ah[mt], pb);
                mma16816h(acc[mt][nt], al[mt], pb);
            }
    }
}

__device__ void mma_mainloop_f16(const __half* __restrict__ Ah,
                                 const __half* __restrict__ Al, int lda, int arow0,
                                 const __half* __restrict__ B, int ldb, int brow0,
                                 int K, uint32_t sb, float acc[2][8][4]) {
    const int C = K >> 6;
    const int warp = threadIdx.x >> 5, lane = threadIdx.x & 31;
    const int warp_m = warp & 3, warp_n = warp >> 2;

    #pragma unroll
    for (int mt = 0; mt < 2; mt++)
        #pragma unroll
        for (int nt = 0; nt < 8; nt++)
            #pragma unroll
            for (int i = 0; i < 4; i++) acc[mt][nt][i] = 0.f;

    fill_stage_f16(sb + 0 * STAGE2_B, Ah, Al, lda, arow0, B, ldb, brow0, 0);
    fill_stage_f16(sb + 1 * STAGE2_B, Ah, Al, lda, arow0, B, ldb, brow0, 64);

    for (int c = 0; c < C; c++) {
        if (c + 1 < C) { CP_WAIT1(); } else { CP_WAIT0(); }
        __syncthreads();
        compute_chunk_f16(sb + (c & 1) * STAGE2_B, warp_m, warp_n, lane, acc);
        __syncthreads();   // all reads of slot c&1 done before refilling it
        if (c + 2 < C) {
            fill_stage_f16(sb + (c & 1) * STAGE2_B, Ah, Al, lda, arow0,
                           B, ldb, brow0, (c + 2) << 6);
        }
    }
}

// ---------------------------------------------------------------------------
// Epilogue helpers
// ---------------------------------------------------------------------------
__device__ __forceinline__ void split2(float v, __nv_bfloat16& h, __nv_bfloat16& l) {
    h = __float2bfloat16(v);
    l = __float2bfloat16(v - __bfloat162float(h));
}
__device__ __forceinline__ void split2h(float v, __half& h, __half& l) {
    h = __float2half(v);
    l = __float2half(v - __half2float(h));
}

__device__ __forceinline__ void split_store2(__nv_bfloat16* __restrict__ H,
                                             __nv_bfloat16* __restrict__ L,
                                             size_t off, float v0, float v1) {
    __nv_bfloat16 h0, h1, l0, l1;
    split2(v0, h0, l0); split2(v1, h1, l1);
    *(__nv_bfloat162*)(H + off) = __halves2bfloat162(h0, h1);
    *(__nv_bfloat162*)(L + off) = __halves2bfloat162(l0, l1);
}

__device__ __forceinline__ void split_store2h(__half* __restrict__ H,
                                              __half* __restrict__ L,
                                              size_t off, float v0, float v1) {
    __half h0, h1, l0, l1;
    split2h(v0, h0, l0); split2h(v1, h1, l1);
    *(__half2*)(H + off) = __halves2half2(h0, h1);
    *(__half2*)(L + off) = __halves2half2(l0, l1);
}

// store 64 consecutive fp16 values (single precision tier)
__device__ __forceinline__ void store_h64(__half* __restrict__ V, size_t off, const float* v) {
    uint32_t p[32];
    #pragma unroll
    for (int j = 0; j < 64; j += 2) {
        __half2 hh = __halves2half2(__float2half(v[j]), __float2half(v[j + 1]));
        p[j >> 1] = reinterpret_cast<uint32_t&>(hh);
    }
    #pragma unroll
    for (int i = 0; i < 8; i++)
        *(uint4*)((char*)(V + off) + i * 16) = ((uint4*)p)[i];
}

#define FRAG_COORDS() \
    const int warp = threadIdx.x >> 5, lane = threadIdx.x & 31; \
    const int warp_m = warp & 3, warp_n = warp >> 2; \
    const int gid = lane >> 2, t4 = lane & 3;

// ---------------------------------------------------------------------------
// GEMM kernels
// ---------------------------------------------------------------------------

// Q/K projections: bf16 split-3, split-bf16 out
__global__ __launch_bounds__(256, 1)
void k_gemm_bias_split(const __nv_bfloat16* __restrict__ Ah, const __nv_bfloat16* __restrict__ Al, int lda,
                       const __nv_bfloat16* __restrict__ Bh, const __nv_bfloat16* __restrict__ Bl, int ldb,
                       const float* __restrict__ bias,
                       __nv_bfloat16* __restrict__ Ch, __nv_bfloat16* __restrict__ Cl, int ldc, int K) {
    extern __shared__ char smem[];
    const uint32_t sb = smem_to_u32(smem);
    const int m0 = blockIdx.y * 128, n0 = blockIdx.x * 128;
    float acc[2][8][4];
    mma_mainloop(Ah, Al, lda, m0, Bh, Bl, ldb, n0, K, sb, acc);
    FRAG_COORDS();
    #pragma unroll
    for (int mt = 0; mt < 2; mt++)
        #pragma unroll
        for (int nt = 0; nt < 8; nt++) {
            const int col = n0 + warp_n * 64 + nt * 8 + t4 * 2;
            const float bx = bias[col], by = bias[col + 1];
            const int r0 = m0 + warp_m * 32 + mt * 16 + gid;
            split_store2(Ch, Cl, (size_t)r0 * ldc + col, acc[mt][nt][0] + bx, acc[mt][nt][1] + by);
            split_store2(Ch, Cl, (size_t)(r0 + 8) * ldc + col, acc[mt][nt][2] + bx, acc[mt][nt][3] + by);
        }
}

// V projection (fp16 path): writes transposed vT[bh][dim][token] single fp16
__global__ __launch_bounds__(256, 2)
void k_gemm_v(const __half* __restrict__ Ah, const __half* __restrict__ Al,
              const __half* __restrict__ B, const float* __restrict__ bias,
              __half* __restrict__ VT) {
    extern __shared__ char smem[];
    const uint32_t sb = smem_to_u32(smem);
    const int m0 = blockIdx.y * 128, n0 = blockIdx.x * 128;
    float acc[2][8][4];
    mma_mainloop_f16(Ah, Al, DMODEL, m0, B, DMODEL, n0, DMODEL, sb, acc);
    FRAG_COORDS();

    float* smf = (float*)smem;  // [128][129] = 66048 B <= 96KB
    __syncthreads();
    #pragma unroll
    for (int mt = 0; mt < 2; mt++)
        #pragma unroll
        for (int nt = 0; nt < 8; nt++) {
            const int lc = warp_n * 64 + nt * 8 + t4 * 2;
            const float bx = bias[n0 + lc], by = bias[n0 + lc + 1];
            const int lr = warp_m * 32 + mt * 16 + gid;
            smf[lr * 129 + lc] = acc[mt][nt][0] + bx;
            smf[lr * 129 + lc + 1] = acc[mt][nt][1] + by;
            smf[(lr + 8) * 129 + lc] = acc[mt][nt][2] + bx;
            smf[(lr + 8) * 129 + lc + 1] = acc[mt][nt][3] + by;
        }
    __syncthreads();

    const int b = m0 / SEQ, tok0 = m0 % SEQ;
    const int h = n0 / DMODEL, dim0 = n0 % DMODEL;
    const int c = threadIdx.x & 127;
    const int seg = threadIdx.x >> 7;
    float vv[64];
    #pragma unroll
    for (int i = 0; i < 64; i++) vv[i] = smf[(seg * 64 + i) * 129 + c];
    const size_t off = ((size_t)(b * 3 + h) * DMODEL + dim0 + c) * SEQ + tok0 + seg * 64;
    store_h64(VT, off, vv);
}

// scores: bf16 split-3 + exact reference masking; upper tiles skipped
__global__ __launch_bounds__(256, 1)
void k_scores(const __nv_bfloat16* __restrict__ qh, const __nv_bfloat16* __restrict__ ql,
              const __nv_bfloat16* __restrict__ kh, const __nv_bfloat16* __restrict__ kl,
              float* __restrict__ s) {
    const int bh = blockIdx.z;
    const int b = bh / 3, h = bh % 3;
    const int m0 = blockIdx.y * 128, n0 = blockIdx.x * 128;
    if (n0 > m0) return;
    float* C = s + (size_t)bh * SEQ * SEQ;

    extern __shared__ char smem[];
    const uint32_t sb = smem_to_u32(smem);
    float acc[2][8][4];
    mma_mainloop(qh + h * DMODEL, ql + h * DMODEL, DQKV, b * SEQ + m0,
                 kh + h * DMODEL, kl + h * DMODEL, DQKV, b * SEQ + n0,
                 DMODEL, sb, acc);
    FRAG_COORDS();
    #pragma unroll
    for (int mt = 0; mt < 2; mt++)
        #pragma unroll
        for (int nt = 0; nt < 8; nt++) {
            const int gj = n0 + warp_n * 64 + nt * 8 + t4 * 2;
            #pragma unroll
            for (int half = 0; half < 2; half++) {
                const int gi = m0 + warp_m * 32 + mt * 16 + gid + half * 8;
                float v0 = acc[mt][nt][half * 2];
                float v1 = acc[mt][nt][half * 2 + 1];
                if (gj > gi || v0 == 0.0f) v0 = -99999.0f;
                if (gj + 1 > gi || v1 == 0.0f) v1 = -99999.0f;
                *(float2*)(C + (size_t)gi * SEQ + gj) = make_float2(v0, v1);
            }
        }
}

// PV (fp16 path): K truncated at diagonal; split-fp16 out into [8192,2304]
__global__ __launch_bounds__(256, 2)
void k_pv(const __half* __restrict__ ph, const __half* __restrict__ pl,
          const __half* __restrict__ vt,
          __half* __restrict__ oh, __half* __restrict__ ol) {
    extern __shared__ char smem[];
    const uint32_t sb = smem_to_u32(smem);
    const int bh = blockIdx.z;
    const int b = bh / 3, h = bh % 3;
    const int m0 = blockIdx.y * 128, n0 = blockIdx.x * 128;
    float acc[2][8][4];
    mma_mainloop_f16(ph + (size_t)bh * SEQ * SEQ, pl + (size_t)bh * SEQ * SEQ, SEQ, m0,
                     vt + (size_t)bh * DMODEL * SEQ, SEQ, n0, m0 + 128, sb, acc);
    FRAG_COORDS();
    #pragma unroll
    for (int mt = 0; mt < 2; mt++)
        #pragma unroll
        for (int nt = 0; nt < 8; nt++) {
            const int col = h * DMODEL + n0 + warp_n * 64 + nt * 8 + t4 * 2;
            const int r0 = b * SEQ + m0 + warp_m * 32 + mt * 16 + gid;
            split_store2h(oh, ol, (size_t)r0 * DQKV + col, acc[mt][nt][0], acc[mt][nt][1]);
            split_store2h(oh, ol, (size_t)(r0 + 8) * DQKV + col, acc[mt][nt][2], acc[mt][nt][3]);
        }
}

// Wo projection (fp16 path): fp32 out
__global__ __launch_bounds__(256, 2)
void k_gemm_wo(const __half* __restrict__ Ah, const __half* __restrict__ Al,
               const __half* __restrict__ B, const float* __restrict__ bias,
               float* __restrict__ C) {
    extern __shared__ char smem[];
    const uint32_t sb = smem_to_u32(smem);
    const int m0 = blockIdx.y * 128, n0 = blockIdx.x * 128;
    float acc[2][8][4];
    mma_mainloop_f16(Ah, Al, DQKV, m0, B, DQKV, n0, DQKV, sb, acc);
    FRAG_COORDS();
    #pragma unroll
    for (int mt = 0; mt < 2; mt++)
        #pragma unroll
        for (int nt = 0; nt < 8; nt++) {
            const int col = n0 + warp_n * 64 + nt * 8 + t4 * 2;
            const float bx = bias[col], by = bias[col + 1];
            const int r0 = m0 + warp_m * 32 + mt * 16 + gid;
            *(float2*)(C + (size_t)r0 * DMODEL + col) =
                make_float2(acc[mt][nt][0] + bx, acc[mt][nt][1] + by);
            *(float2*)(C + (size_t)(r0 + 8) * DMODEL + col) =
                make_float2(acc[mt][nt][2] + bx, acc[mt][nt][3] + by);
        }
}

// final (fp16 path): out = leaky_relu(A*Wf^T + bf)
__global__ __launch_bounds__(256, 2)
void k_final(const __half* __restrict__ Ah, const __half* __restrict__ Al,
             const __half* __restrict__ B, const float* __restrict__ bias,
             float* __restrict__ out) {
    extern __shared__ char smem[];
    const uint32_t sb = smem_to_u32(smem);
    const int m0 = blockIdx.y * 128, n0 = blockIdx.x * 128;
    float acc[2][8][4];
    mma_mainloop_f16(Ah, Al, DMODEL, m0, B, DMODEL, n0, DMODEL, sb, acc);
    FRAG_COORDS();
    #pragma unroll
    for (int mt = 0; mt < 2; mt++)
        #pragma unroll
        for (int nt = 0; nt < 8; nt++) {
            const int col = n0 + warp_n * 64 + nt * 8 + t4 * 2;
            const float bx = bias[col], by = bias[col + 1];
            const int r0 = m0 + warp_m * 32 + mt * 16 + gid;
            float t0 = acc[mt][nt][0] + bx, t1 = acc[mt][nt][1] + by;
            float t2 = acc[mt][nt][2] + bx, t3 = acc[mt][nt][3] + by;
            t0 = t0 > 0.f ? t0 : 0.01f * t0;
            t1 = t1 > 0.f ? t1 : 0.01f * t1;
            t2 = t2 > 0.f ? t2 : 0.01f * t2;
            t3 = t3 > 0.f ? t3 : 0.01f * t3;
            *(float2*)(out + (size_t)r0 * DMODEL + col) = make_float2(t0, t1);
            *(float2*)(out + (size_t)(r0 + 8) * DMODEL + col) = make_float2(t2, t3);
        }
}

// ---------------------------------------------------------------------------
// Non-GEMM kernels
// ---------------------------------------------------------------------------
// x -> bf16 hi/lo (Q/K path) + fp16 hi/lo (V path)
__global__ void split_kernel(const float* __restrict__ src,
                             __nv_bfloat16* __restrict__ H, __nv_bfloat16* __restrict__ L,
                             __half* __restrict__ H2, __half* __restrict__ L2, int n) {
    int i = (blockIdx.x * 256 + threadIdx.x) * 4;
    if (i >= n) return;
    float4 v = *(const float4*)(src + i);
    {
        __nv_bfloat16 h0, h1, h2, h3, l0, l1, l2, l3;
        split2(v.x, h0, l0); split2(v.y, h1, l1); split2(v.z, h2, l2); split2(v.w, h3, l3);
        __nv_bfloat162 a = __halves2bfloat162(h0, h1), b2 = __halves2bfloat162(h2, h3);
        __nv_bfloat162 c = __halves2bfloat162(l0, l1), d = __halves2bfloat162(l2, l3);
        uint2 hp, lp;
        hp.x = reinterpret_cast<uint32_t&>(a); hp.y = reinterpret_cast<uint32_t&>(b2);
        lp.x = reinterpret_cast<uint32_t&>(c); lp.y = reinterpret_cast<uint32_t&>(d);
        *(uint2*)(H + i) = hp;
        *(uint2*)(L + i) = lp;
    }
    {
        __half h0, h1, h2, h3, l0, l1, l2, l3;
        split2h(v.x, h0, l0); split2h(v.y, h1, l1); split2h(v.z, h2, l2); split2h(v.w, h3, l3);
        __half2 a = __halves2half2(h0, h1), b2 = __halves2half2(h2, h3);
        __half2 c = __halves2half2(l0, l1), d = __halves2half2(l2, l3);
        uint2 hp, lp;
        hp.x = reinterpret_cast<uint32_t&>(a); hp.y = reinterpret_cast<uint32_t&>(b2);
        lp.x = reinterpret_cast<uint32_t&>(c); lp.y = reinterpret_cast<uint32_t&>(d);
        *(uint2*)(H2 + i) = hp;
        *(uint2*)(L2 + i) = lp;
    }
}

// Wq/Wk -> bf16 hi/lo transpose; Wv -> single fp16 transpose (z selects)
__global__ void transpose_split_qkv(const float* __restrict__ Wq, const float* __restrict__ Wk,
                                    const float* __restrict__ Wv,
                                    __nv_bfloat16* __restrict__ QH, __nv_bfloat16* __restrict__ QL,
                                    __nv_bfloat16* __restrict__ KH, __nv_bfloat16* __restrict__ KL,
                                    __half* __restrict__ V16) {
    const float* W = (blockIdx.z == 0) ? Wq : (blockIdx.z == 1) ? Wk : Wv;
    __shared__ float t[32][33];
    const int n0 = blockIdx.x * 32, k0 = blockIdx.y * 32;
    const int tx = threadIdx.x, ty = threadIdx.y;
    #pragma unroll
    for (int i = ty; i < 32; i += 8)
        t[i][tx] = W[(size_t)(k0 + i) * DQKV + n0 + tx];
    __syncthreads();
    if (blockIdx.z == 2) {
        #pragma unroll
        for (int i = ty; i < 32; i += 8) {
            const size_t off = (size_t)(n0 + i) * DMODEL + k0 + tx;
            V16[off] = __float2half(t[tx][i]);
        }
    } else {
        __nv_bfloat16* TH = (blockIdx.z == 0) ? QH : KH;
        __nv_bfloat16* TL = (blockIdx.z == 0) ? QL : KL;
        #pragma unroll
        for (int i = ty; i < 32; i += 8) {
            float v = t[tx][i];
            __nv_bfloat16 h, l;
            split2(v, h, l);
            const size_t off = (size_t)(n0 + i) * DMODEL + k0 + tx;
            TH[off] = h;
            TL[off] = l;
        }
    }
}

// W[K,N] fp32 -> Wt[N,K] single fp16 (Wo, Wf)
__global__ void transpose_f16(const float* __restrict__ W, int K, int N,
                              __half* __restrict__ T) {
    __shared__ float t[32][33];
    const int n0 = blockIdx.x * 32, k0 = blockIdx.y * 32;
    const int tx = threadIdx.x, ty = threadIdx.y;
    #pragma unroll
    for (int i = ty; i < 32; i += 8)
        t[i][tx] = W[(size_t)(k0 + i) * N + n0 + tx];
    __syncthreads();
    #pragma unroll
    for (int i = ty; i < 32; i += 8) {
        const size_t off = (size_t)(n0 + i) * K + k0 + tx;
        T[off] = __float2half(t[tx][i]);
    }
}

// causal-aware row softmax -> split-fp16 probabilities
__global__ void softmax_split_causal(const float* __restrict__ s,
                                     __half* __restrict__ PH, __half* __restrict__ PL) {
    const int row = blockIdx.x & (SEQ - 1);
    const int L = ((row >> 7) + 1) << 7;
    const float* p = s + (size_t)blockIdx.x * SEQ;
    __half* ph = PH + (size_t)blockIdx.x * SEQ;
    __half* pl = PL + (size_t)blockIdx.x * SEQ;
    const int tid = threadIdx.x;
    const int lane = tid & 31, wid = tid >> 5;
    __shared__ float red[8];

    float v[8];
    int cnt = 0;
    float m = -3.4e38f;
    for (int j = tid; j < L; j += 256) { float x = p[j]; v[cnt++] = x; m = fmaxf(m, x); }
    #pragma unroll
    for (int o = 16; o; o >>= 1) m = fmaxf(m, __shfl_xor_sync(0xffffffffu, m, o));
    if (lane == 0) red[wid] = m;
    __syncthreads();
    float mall = red[0];
    #pragma unroll
    for (int i = 1; i < 8; i++) mall = fmaxf(mall, red[i]);

    float ssum = 0.f;
    for (int i = 0; i < cnt; i++) {
        v[i] = exp2f((v[i] - mall) * 1.4426950408889634f);
        ssum += v[i];
    }
    #pragma unroll
    for (int o = 16; o; o >>= 1) ssum += __shfl_xor_sync(0xffffffffu, ssum, o);
    __syncthreads();
    if (lane == 0) red[wid] = ssum;
    __syncthreads();
    float tot = 0.f;
    #pragma unroll
    for (int i = 0; i < 8; i++) tot += red[i];
    const float inv = 1.0f / tot;

    int i2 = 0;
    for (int j = tid; j < L; j += 256) {
        float pv = v[i2++] * inv;
        __half h, l;
        split2h(pv, h, l);
        ph[j] = h;
        pl[j] = l;
    }
}

__global__ void reduce_partial(const float* __restrict__ a, float* __restrict__ part) {
    const int n = MTOK * DMODEL;
    float s = 0.f;
    for (int i = blockIdx.x * 256 + threadIdx.x; i < n; i += 1024 * 256) s += a[i];
    __shared__ float sm[256];
    sm[threadIdx.x] = s; __syncthreads();
    #pragma unroll
    for (int st = 128; st > 0; st >>= 1) {
        if (threadIdx.x < st) sm[threadIdx.x] += sm[threadIdx.x + st];
        __syncthreads();
    }
    if (threadIdx.x == 0) part[blockIdx.x] = sm[0];
}

__global__ void reduce_final(const float* __restrict__ part, float* __restrict__ mean) {
    float s = 0.f;
    for (int i = threadIdx.x; i < 1024; i += 256) s += part[i];
    __shared__ float sm[256];
    sm[threadIdx.x] = s; __syncthreads();
    #pragma unroll
    for (int st = 128; st > 0; st >>= 1) {
        if (threadIdx.x < st) sm[threadIdx.x] += sm[threadIdx.x + st];
        __syncthreads();
    }
    if (threadIdx.x == 0) mean[0] = sm[0] * (1.0f / ((float)MTOK * DMODEL));
}

// n = a - mean + x, split-fp16
__global__ void fuse_split_kernel(const float* __restrict__ a, const float* __restrict__ x,
                                  const float* __restrict__ meanp,
                                  __half* __restrict__ NH, __half* __restrict__ NL, int n) {
    const float mean = meanp[0];
    int i = (blockIdx.x * 256 + threadIdx.x) * 4;
    if (i >= n) return;
    float4 va = *(const float4*)(a + i);
    float4 vx = *(const float4*)(x + i);
    float f0 = va.x - mean + vx.x, f1 = va.y - mean + vx.y;
    float f2 = va.z - mean + vx.z, f3 = va.w - mean + vx.w;
    __half h0, h1, h2, h3, l0, l1, l2, l3;
    split2h(f0, h0, l0); split2h(f1, h1, l1); split2h(f2, h2, l2); split2h(f3, h3, l3);
    __half2 aa = __halves2half2(h0, h1), bb = __halves2half2(h2, h3);
    __half2 cc = __halves2half2(l0, l1), dd = __halves2half2(l2, l3);
    uint2 hp, lp;
    hp.x = reinterpret_cast<uint32_t&>(aa); hp.y = reinterpret_cast<uint32_t&>(bb);
    lp.x = reinterpret_cast<uint32_t&>(cc); lp.y = reinterpret_cast<uint32_t&>(dd);
    *(uint2*)(NH + i) = hp;
    *(uint2*)(NL + i) = lp;
}

// ---------------------------------------------------------------------------
extern "C" void kernel_launch(void* const* d_in, const int* in_sizes, int n_in,
                              void* d_out, int out_size) {
    const float* x  = (const float*)d_in[0];
    const float* Wq = (const float*)d_in[1];
    const float* bq = (const float*)d_in[2];
    const float* Wk = (const float*)d_in[3];
    const float* bk = (const float*)d_in[4];
    const float* Wv = (const float*)d_in[5];
    const float* bv = (const float*)d_in[6];
    const float* Wo = (const float*)d_in[7];
    const float* bo = (const float*)d_in[8];
    const float* Wf = (const float*)d_in[9];
    const float* bf = (const float*)d_in[10];
    float* out = (float*)d_out;

    static bool attr_done = false;
    if (!attr_done) {
        cudaFuncSetAttribute(k_gemm_bias_split, cudaFuncAttributeMaxDynamicSharedMemorySize, DYN_SMEM);
        cudaFuncSetAttribute(k_scores,          cudaFuncAttributeMaxDynamicSharedMemorySize, DYN_SMEM);
        cudaFuncSetAttribute(k_gemm_v,          cudaFuncAttributeMaxDynamicSharedMemorySize, DYN_SMEM2);
        cudaFuncSetAttribute(k_pv,              cudaFuncAttributeMaxDynamicSharedMemorySize, DYN_SMEM2);
        cudaFuncSetAttribute(k_gemm_wo,         cudaFuncAttributeMaxDynamicSharedMemorySize, DYN_SMEM2);
        cudaFuncSetAttribute(k_final,           cudaFuncAttributeMaxDynamicSharedMemorySize, DYN_SMEM2);
        attr_done = true;
    }

    __nv_bfloat16 *xh, *xl, *wqth, *wqtl, *wkth, *wktl, *qh, *ql, *kh, *kl;
    __half *xh2, *xl2, *wvt16, *wot16, *wft16, *vt16, *ph, *pl, *oh, *ol, *nh, *nl;
    float *s, *a, *part, *mean;
    cudaGetSymbolAddress((void**)&xh, g_xh);     cudaGetSymbolAddress((void**)&xl, g_xl);
    cudaGetSymbolAddress((void**)&xh2, g_xh2);   cudaGetSymbolAddress((void**)&xl2, g_xl2);
    cudaGetSymbolAddress((void**)&wqth, g_wqth); cudaGetSymbolAddress((void**)&wqtl, g_wqtl);
    cudaGetSymbolAddress((void**)&wkth, g_wkth); cudaGetSymbolAddress((void**)&wktl, g_wktl);
    cudaGetSymbolAddress((void**)&wvt16, g_wvt16);
    cudaGetSymbolAddress((void**)&wot16, g_wot16);
    cudaGetSymbolAddress((void**)&wft16, g_wft16);
    cudaGetSymbolAddress((void**)&qh, g_qh);     cudaGetSymbolAddress((void**)&ql, g_ql);
    cudaGetSymbolAddress((void**)&kh, g_kh);     cudaGetSymbolAddress((void**)&kl, g_kl);
    cudaGetSymbolAddress((void**)&vt16, g_vt16);
    cudaGetSymbolAddress((void**)&s, g_s);
    cudaGetSymbolAddress((void**)&ph, g_ph);     cudaGetSymbolAddress((void**)&pl, g_pl);
    cudaGetSymbolAddress((void**)&oh, g_oh);     cudaGetSymbolAddress((void**)&ol, g_ol);
    cudaGetSymbolAddress((void**)&a, g_a);
    cudaGetSymbolAddress((void**)&nh, g_nh);     cudaGetSymbolAddress((void**)&nl, g_nl);
    cudaGetSymbolAddress((void**)&part, g_part); cudaGetSymbolAddress((void**)&mean, g_mean);

    // 0) splits / transposes of inputs
    const int nx = MTOK * DMODEL;
    split_kernel<<<(nx / 4 + 255) / 256, 256>>>(x, xh, xl, xh2, xl2, nx);
    transpose_split_qkv<<<dim3(DQKV / 32, DMODEL / 32, 3), dim3(32, 8)>>>(
        Wq, Wk, Wv, wqth, wqtl, wkth, wktl, wvt16);
    transpose_f16<<<dim3(DMODEL / 32, DQKV / 32), dim3(32, 8)>>>(Wo, DQKV, DMODEL, wot16);
    transpose_f16<<<dim3(DMODEL / 32, DMODEL / 32), dim3(32, 8)>>>(Wf, DMODEL, DMODEL, wft16);

    // 1) Q, K projections (bf16 split-3), V projection (fp16 split-2, transposed out)
    dim3 qkvGrid(DQKV / 128, MTOK / 128);
    k_gemm_bias_split<<<qkvGrid, 256, DYN_SMEM>>>(xh, xl, DMODEL, wqth, wqtl, DMODEL, bq, qh, ql, DQKV, DMODEL);
    k_gemm_bias_split<<<qkvGrid, 256, DYN_SMEM>>>(xh, xl, DMODEL, wkth, wktl, DMODEL, bk, kh, kl, DQKV, DMODEL);
    k_gemm_v<<<qkvGrid, 256, DYN_SMEM2>>>(xh2, xl2, wvt16, bv, vt16);

    // 2) masked scores (lower-triangle tiles only)
    k_scores<<<dim3(SEQ / 128, SEQ / 128, NBH), 256, DYN_SMEM>>>(qh, ql, kh, kl, s);

    // 3) causal softmax -> split-fp16 P
    softmax_split_causal<<<NBH * SEQ, 256>>>(s, ph, pl);

    // 4) o = attn @ v (fp16 split-2, causal-truncated k-loop)
    k_pv<<<dim3(DMODEL / 128, SEQ / 128, NBH), 256, DYN_SMEM2>>>(ph, pl, vt16, oh, ol);

    // 5) a = o @ Wo + bo (fp16 split-2, fp32 out)
    k_gemm_wo<<<dim3(DMODEL / 128, MTOK / 128), 256, DYN_SMEM2>>>(oh, ol, wot16, bo, a);

    // 6) deterministic global mean
    reduce_partial<<<1024, 256>>>(a, part);
    reduce_final<<<1, 256>>>(part, mean);

    // 7) n = a - mean + x (split-fp16)
    fuse_split_kernel<<<(nx / 4 + 255) / 256, 256>>>(a, x, mean, nh, nl, nx);

    // 8) out = leaky_relu(n @ Wf + bf) (fp16 split-2)
    k_final<<<dim3(DMODEL / 128, MTOK / 128), 256, DYN_SMEM2>>>(nh, nl, wft16, bf, out);
}

// round 16
// speedup vs baseline: 3.6741x; 1.0062x over previous
#include <cuda_runtime.h>
#include <cuda_bf16.h>
#include <cuda_fp16.h>
#include <cstdint>
#include <cstddef>

// ===========================================================================
// B=4, S=2048, D=768, H=3.  MTOK=8192, DQKV=2304.
// Q/K proj + scores: bf16 split-3 (AhBh+AhBl+AlBh), 3 MMAs -> err ~1e-5.
// V proj, PV, Wo, Wf: fp16 A-split-2 x B-single, 2 MMAs -> err ~3e-4.
// R14: 64x64 warp tiles, 128-thread GEMM blocks (4 warps, 2x2 grid).
// ===========================================================================

#define MTOK 8192
#define DMODEL 768
#define DQKV 2304
#define SEQ 2048
#define NBH 12

#define TILE_B 16384            // 128 rows x 128B
#define STAGE_B (4 * TILE_B)    // bf16 path: Ah, Al, Bh, Bl
#define DYN_SMEM (3 * STAGE_B)  // 196608
#define STAGE2_B (3 * TILE_B)   // f16 path: Ah, Al, B
#define DYN_SMEM2 (2 * STAGE2_B) // 98304 -> 2 CTAs/SM

__device__ __forceinline__ uint32_t smem_to_u32(const void* p) {
    uint32_t a;
    asm("{ .reg .u64 t; cvta.to.shared.u64 t, %1; cvt.u32.u64 %0, t; }" : "=r"(a) : "l"(p));
    return a;
}

__device__ __forceinline__ void ldmatrix_x4(uint32_t* r, uint32_t addr) {
    asm volatile("ldmatrix.sync.aligned.m8n8.x4.shared.b16 {%0,%1,%2,%3}, [%4];"
                 : "=r"(r[0]), "=r"(r[1]), "=r"(r[2]), "=r"(r[3]) : "r"(addr));
}

__device__ __forceinline__ void mma16816(float* c, const uint32_t* a, const uint32_t* b) {
    asm volatile(
        "mma.sync.aligned.m16n8k16.row.col.f32.bf16.bf16.f32 "
        "{%0,%1,%2,%3}, {%4,%5,%6,%7}, {%8,%9}, {%0,%1,%2,%3};"
        : "+f"(c[0]), "+f"(c[1]), "+f"(c[2]), "+f"(c[3])
        : "r"(a[0]), "r"(a[1]), "r"(a[2]), "r"(a[3]), "r"(b[0]), "r"(b[1]));
}

__device__ __forceinline__ void mma16816h(float* c, const uint32_t* a, const uint32_t* b) {
    asm volatile(
        "mma.sync.aligned.m16n8k16.row.col.f32.f16.f16.f32 "
        "{%0,%1,%2,%3}, {%4,%5,%6,%7}, {%8,%9}, {%0,%1,%2,%3};"
        : "+f"(c[0]), "+f"(c[1]), "+f"(c[2]), "+f"(c[3])
        : "r"(a[0]), "r"(a[1]), "r"(a[2]), "r"(a[3]), "r"(b[0]), "r"(b[1]));
}

#define CP_ASYNC16(dst, src) \
    asm volatile("cp.async.cg.shared.global [%0], [%1], 16;" :: "r"(dst), "l"(src))
#define CP_COMMIT() asm volatile("cp.async.commit_group;" ::: "memory")
#define CP_WAIT0()  asm volatile("cp.async.wait_group 0;" ::: "memory")
#define CP_WAIT1()  asm volatile("cp.async.wait_group 1;" ::: "memory")

__device__ __forceinline__ uint32_t swz(int r, int g) {
    return (uint32_t)(r * 128 + ((g ^ (r & 7)) << 4));
}

// ---------------------------------------------------------------------------
// Scratch (allocation-free device globals)
// ---------------------------------------------------------------------------
__device__ __nv_bfloat16 g_xh[(size_t)MTOK * DMODEL], g_xl[(size_t)MTOK * DMODEL];
__device__ __half        g_xh2[(size_t)MTOK * DMODEL], g_xl2[(size_t)MTOK * DMODEL];
__device__ __nv_bfloat16 g_wqth[(size_t)DQKV * DMODEL], g_wqtl[(size_t)DQKV * DMODEL];
__device__ __nv_bfloat16 g_wkth[(size_t)DQKV * DMODEL], g_wktl[(size_t)DQKV * DMODEL];
__device__ __half        g_wvt16[(size_t)DQKV * DMODEL];
__device__ __half        g_wot16[(size_t)DMODEL * DQKV];
__device__ __half        g_wft16[(size_t)DMODEL * DMODEL];
__device__ __nv_bfloat16 g_qh[(size_t)MTOK * DQKV], g_ql[(size_t)MTOK * DQKV];
__device__ __nv_bfloat16 g_kh[(size_t)MTOK * DQKV], g_kl[(size_t)MTOK * DQKV];
__device__ __half        g_vt16[(size_t)NBH * DMODEL * SEQ];
__device__ float         g_s[(size_t)NBH * SEQ * SEQ];
__device__ __half        g_ph[(size_t)NBH * SEQ * SEQ], g_pl[(size_t)NBH * SEQ * SEQ];
__device__ __half        g_oh[(size_t)MTOK * DQKV], g_ol[(size_t)MTOK * DQKV];
__device__ float         g_a[(size_t)MTOK * DMODEL];
__device__ __half        g_nh[(size_t)MTOK * DMODEL], g_nl[(size_t)MTOK * DMODEL];
__device__ float         g_part[1024];
__device__ float         g_mean[1];

// ---------------------------------------------------------------------------
// Engine (GEMM blocks have 128 threads)
// ---------------------------------------------------------------------------
template <typename T>
__device__ __forceinline__ void load_tile_async(uint32_t sbase, const T* __restrict__ G,
                                                int ld, int row0, int k0) {
    const int t = threadIdx.x;       // 0..127
    const int g = t & 7;
    const int r = t >> 3;            // 0..15
    const T* src = G + (size_t)(row0 + r) * ld + k0 + g * 8;
    #pragma unroll
    for (int p = 0; p < 8; p++) {
        CP_ASYNC16(sbase + swz(r + p * 16, g), src + (size_t)p * 16 * ld);
    }
}

__device__ __forceinline__ void fill_stage(uint32_t st,
                                           const __nv_bfloat16* __restrict__ Ah,
                                           const __nv_bfloat16* __restrict__ Al, int lda, int arow0,
                                           const __nv_bfloat16* __restrict__ Bh,
                                           const __nv_bfloat16* __restrict__ Bl, int ldb, int brow0,
                                           int k0) {
    load_tile_async(st + 0 * TILE_B, Ah, lda, arow0, k0);
    load_tile_async(st + 1 * TILE_B, Al, lda, arow0, k0);
    load_tile_async(st + 2 * TILE_B, Bh, ldb, brow0, k0);
    load_tile_async(st + 3 * TILE_B, Bl, ldb, brow0, k0);
    CP_COMMIT();
}

__device__ __forceinline__ void compute_chunk(uint32_t sbase, int warp_m, int warp_n,
                                              int lane, float acc[4][8][4]) {
    const int arow = warp_m * 64 + (lane & 7) + ((lane >> 3) & 1) * 8;
    const int brow = warp_n * 64 + (lane & 7) + (lane >> 4) * 8;
    #pragma unroll
    for (int kk = 0; kk < 4; kk++) {
        const int ag = kk * 2 + (lane >> 4);
        const int bg = kk * 2 + ((lane >> 3) & 1);
        uint32_t ah[4][4], al[4][4], bh[4][4], bl[4][4];
        #pragma unroll
        for (int mt = 0; mt < 4; mt++) {
            ldmatrix_x4(ah[mt], sbase + 0 * TILE_B + swz(arow + mt * 16, ag));
            ldmatrix_x4(al[mt], sbase + 1 * TILE_B + swz(arow + mt * 16, ag));
        }
        #pragma unroll
        for (int nt2 = 0; nt2 < 4; nt2++) {
            ldmatrix_x4(bh[nt2], sbase + 2 * TILE_B + swz(brow + nt2 * 16, bg));
            ldmatrix_x4(bl[nt2], sbase + 3 * TILE_B + swz(brow + nt2 * 16, bg));
        }
        #pragma unroll
        for (int mt = 0; mt < 4; mt++)
            #pragma unroll
            for (int nt = 0; nt < 8; nt++) {
                const uint32_t* pbh = &bh[nt >> 1][(nt & 1) * 2];
                const uint32_t* pbl = &bl[nt >> 1][(nt & 1) * 2];
                mma16816(acc[mt][nt], ah[mt], pbh);
                mma16816(acc[mt][nt], ah[mt], pbl);
                mma16816(acc[mt][nt], al[mt], pbh);
            }
    }
}

__device__ void mma_mainloop(const __nv_bfloat16* __restrict__ Ah,
                             const __nv_bfloat16* __restrict__ Al, int lda, int arow0,
                             const __nv_bfloat16* __restrict__ Bh,
                             const __nv_bfloat16* __restrict__ Bl, int ldb, int brow0,
                             int K, uint32_t sb, float acc[4][8][4]) {
    const int C = K >> 6;
    const int warp = threadIdx.x >> 5, lane = threadIdx.x & 31;
    const int warp_m = warp & 1, warp_n = warp >> 1;

    #pragma unroll
    for (int mt = 0; mt < 4; mt++)
        #pragma unroll
        for (int nt = 0; nt < 8; nt++)
            #pragma unroll
            for (int i = 0; i < 4; i++) acc[mt][nt][i] = 0.f;

    fill_stage(sb + 0 * STAGE_B, Ah, Al, lda, arow0, Bh, Bl, ldb, brow0, 0);
    fill_stage(sb + 1 * STAGE_B, Ah, Al, lda, arow0, Bh, Bl, ldb, brow0, 64);

    int slot = 0;
    for (int c = 0; c < C; c++) {
        if (c + 1 < C) { CP_WAIT1(); } else { CP_WAIT0(); }
        __syncthreads();
        compute_chunk(sb + slot * STAGE_B, warp_m, warp_n, lane, acc);
        if (c + 2 < C) {
            fill_stage(sb + ((c + 2) % 3) * STAGE_B, Ah, Al, lda, arow0,
                       Bh, Bl, ldb, brow0, (c + 2) << 6);
        }
        slot = (slot + 1) % 3;
    }
}

__device__ __forceinline__ void fill_stage_f16(uint32_t st,
                                               const __half* __restrict__ Ah,
                                               const __half* __restrict__ Al, int lda, int arow0,
                                               const __half* __restrict__ B, int ldb, int brow0,
                                               int k0) {
    load_tile_async(st + 0 * TILE_B, Ah, lda, arow0, k0);
    load_tile_async(st + 1 * TILE_B, Al, lda, arow0, k0);
    load_tile_async(st + 2 * TILE_B, B, ldb, brow0, k0);
    CP_COMMIT();
}

__device__ __forceinline__ void compute_chunk_f16(uint32_t sbase, int warp_m, int warp_n,
                                                  int lane, float acc[4][8][4]) {
    const int arow = warp_m * 64 + (lane & 7) + ((lane >> 3) & 1) * 8;
    const int brow = warp_n * 64 + (lane & 7) + (lane >> 4) * 8;
    #pragma unroll
    for (int kk = 0; kk < 4; kk++) {
        const int ag = kk * 2 + (lane >> 4);
        const int bg = kk * 2 + ((lane >> 3) & 1);
        uint32_t ah[4][4], al[4][4], b[4][4];
        #pragma unroll
        for (int mt = 0; mt < 4; mt++) {
            ldmatrix_x4(ah[mt], sbase + 0 * TILE_B + swz(arow + mt * 16, ag));
            ldmatrix_x4(al[mt], sbase + 1 * TILE_B + swz(arow + mt * 16, ag));
        }
        #pragma unroll
        for (int nt2 = 0; nt2 < 4; nt2++)
            ldmatrix_x4(b[nt2], sbase + 2 * TILE_B + swz(brow + nt2 * 16, bg));
        #pragma unroll
        for (int mt = 0; mt < 4; mt++)
            #pragma unroll
            for (int nt = 0; nt < 8; nt++) {
                const uint32_t* pb = &b[nt >> 1][(nt & 1) * 2];
                mma16816h(acc[mt][nt], ah[mt], pb);
                mma16816h(acc[mt][nt], al[mt], pb);
            }
    }
}

__device__ void mma_mainloop_f16(const __half* __restrict__ Ah,
                                 const __half* __restrict__ Al, int lda, int arow0,
                                 const __half* __restrict__ B, int ldb, int brow0,
                                 int K, uint32_t sb, float acc[4][8][4]) {
    const int C = K >> 6;
    const int warp = threadIdx.x >> 5, lane = threadIdx.x & 31;
    const int warp_m = warp & 1, warp_n = warp >> 1;

    #pragma unroll
    for (int mt = 0; mt < 4; mt++)
        #pragma unroll
        for (int nt = 0; nt < 8; nt++)
            #pragma unroll
            for (int i = 0; i < 4; i++) acc[mt][nt][i] = 0.f;

    fill_stage_f16(sb + 0 * STAGE2_B, Ah, Al, lda, arow0, B, ldb, brow0, 0);
    fill_stage_f16(sb + 1 * STAGE2_B, Ah, Al, lda, arow0, B, ldb, brow0, 64);

    for (int c = 0; c < C; c++) {
        if (c + 1 < C) { CP_WAIT1(); } else { CP_WAIT0(); }
        __syncthreads();
        compute_chunk_f16(sb + (c & 1) * STAGE2_B, warp_m, warp_n, lane, acc);
        __syncthreads();   // all reads of slot c&1 done before refilling it
        if (c + 2 < C) {
            fill_stage_f16(sb + (c & 1) * STAGE2_B, Ah, Al, lda, arow0,
                           B, ldb, brow0, (c + 2) << 6);
        }
    }
}

// ---------------------------------------------------------------------------
// Epilogue helpers
// ---------------------------------------------------------------------------
__device__ __forceinline__ void split2(float v, __nv_bfloat16& h, __nv_bfloat16& l) {
    h = __float2bfloat16(v);
    l = __float2bfloat16(v - __bfloat162float(h));
}
__device__ __forceinline__ void split2h(float v, __half& h, __half& l) {
    h = __float2half(v);
    l = __float2half(v - __half2float(h));
}

__device__ __forceinline__ void split_store2(__nv_bfloat16* __restrict__ H,
                                             __nv_bfloat16* __restrict__ L,
                                             size_t off, float v0, float v1) {
    __nv_bfloat16 h0, h1, l0, l1;
    split2(v0, h0, l0); split2(v1, h1, l1);
    *(__nv_bfloat162*)(H + off) = __halves2bfloat162(h0, h1);
    *(__nv_bfloat162*)(L + off) = __halves2bfloat162(l0, l1);
}

__device__ __forceinline__ void split_store2h(__half* __restrict__ H,
                                              __half* __restrict__ L,
                                              size_t off, float v0, float v1) {
    __half h0, h1, l0, l1;
    split2h(v0, h0, l0); split2h(v1, h1, l1);
    *(__half2*)(H + off) = __halves2half2(h0, h1);
    *(__half2*)(L + off) = __halves2half2(l0, l1);
}

__device__ __forceinline__ void store_h64(__half* __restrict__ V, size_t off, const float* v) {
    uint32_t p[32];
    #pragma unroll
    for (int j = 0; j < 64; j += 2) {
        __half2 hh = __halves2half2(__float2half(v[j]), __float2half(v[j + 1]));
        p[j >> 1] = reinterpret_cast<uint32_t&>(hh);
    }
    #pragma unroll
    for (int i = 0; i < 8; i++)
        *(uint4*)((char*)(V + off) + i * 16) = ((uint4*)p)[i];
}

#define FRAG_COORDS() \
    const int warp = threadIdx.x >> 5, lane = threadIdx.x & 31; \
    const int warp_m = warp & 1, warp_n = warp >> 1; \
    const int gid = lane >> 2, t4 = lane & 3;

// ---------------------------------------------------------------------------
// GEMM kernels (128 threads each)
// ---------------------------------------------------------------------------
__global__ __launch_bounds__(128, 1)
void k_gemm_bias_split(const __nv_bfloat16* __restrict__ Ah, const __nv_bfloat16* __restrict__ Al, int lda,
                       const __nv_bfloat16* __restrict__ Bh, const __nv_bfloat16* __restrict__ Bl, int ldb,
                       const float* __restrict__ bias,
                       __nv_bfloat16* __restrict__ Ch, __nv_bfloat16* __restrict__ Cl, int ldc, int K) {
    extern __shared__ char smem[];
    const uint32_t sb = smem_to_u32(smem);
    const int m0 = blockIdx.y * 128, n0 = blockIdx.x * 128;
    float acc[4][8][4];
    mma_mainloop(Ah, Al, lda, m0, Bh, Bl, ldb, n0, K, sb, acc);
    FRAG_COORDS();
    #pragma unroll
    for (int mt = 0; mt < 4; mt++)
        #pragma unroll
        for (int nt = 0; nt < 8; nt++) {
            const int col = n0 + warp_n * 64 + nt * 8 + t4 * 2;
            const float bx = bias[col], by = bias[col + 1];
            const int r0 = m0 + warp_m * 64 + mt * 16 + gid;
            split_store2(Ch, Cl, (size_t)r0 * ldc + col, acc[mt][nt][0] + bx, acc[mt][nt][1] + by);
            split_store2(Ch, Cl, (size_t)(r0 + 8) * ldc + col, acc[mt][nt][2] + bx, acc[mt][nt][3] + by);
        }
}

__global__ __launch_bounds__(128, 2)
void k_gemm_v(const __half* __restrict__ Ah, const __half* __restrict__ Al,
              const __half* __restrict__ B, const float* __restrict__ bias,
              __half* __restrict__ VT) {
    extern __shared__ char smem[];
    const uint32_t sb = smem_to_u32(smem);
    const int m0 = blockIdx.y * 128, n0 = blockIdx.x * 128;
    float acc[4][8][4];
    mma_mainloop_f16(Ah, Al, DMODEL, m0, B, DMODEL, n0, DMODEL, sb, acc);
    FRAG_COORDS();

    float* smf = (float*)smem;  // [128][129] = 66048 B <= 96KB
    __syncthreads();
    #pragma unroll
    for (int mt = 0; mt < 4; mt++)
        #pragma unroll
        for (int nt = 0; nt < 8; nt++) {
            const int lc = warp_n * 64 + nt * 8 + t4 * 2;
            const float bx = bias[n0 + lc], by = bias[n0 + lc + 1];
            const int lr = warp_m * 64 + mt * 16 + gid;
            smf[lr * 129 + lc] = acc[mt][nt][0] + bx;
            smf[lr * 129 + lc + 1] = acc[mt][nt][1] + by;
            smf[(lr + 8) * 129 + lc] = acc[mt][nt][2] + bx;
            smf[(lr + 8) * 129 + lc + 1] = acc[mt][nt][3] + by;
        }
    __syncthreads();

    const int b = m0 / SEQ, tok0 = m0 % SEQ;
    const int h = n0 / DMODEL, dim0 = n0 % DMODEL;
    const int c = threadIdx.x;   // 0..127
    #pragma unroll
    for (int seg = 0; seg < 2; seg++) {
        float vv[64];
        #pragma unroll
        for (int i = 0; i < 64; i++) vv[i] = smf[(seg * 64 + i) * 129 + c];
        const size_t off = ((size_t)(b * 3 + h) * DMODEL + dim0 + c) * SEQ + tok0 + seg * 64;
        store_h64(VT, off, vv);
    }
}

__global__ __launch_bounds__(128, 1)
void k_scores(const __nv_bfloat16* __restrict__ qh, const __nv_bfloat16* __restrict__ ql,
              const __nv_bfloat16* __restrict__ kh, const __nv_bfloat16* __restrict__ kl,
              float* __restrict__ s) {
    const int bh = blockIdx.z;
    const int b = bh / 3, h = bh % 3;
    const int m0 = blockIdx.y * 128, n0 = blockIdx.x * 128;
    if (n0 > m0) return;
    float* C = s + (size_t)bh * SEQ * SEQ;

    extern __shared__ char smem[];
    const uint32_t sb = smem_to_u32(smem);
    float acc[4][8][4];
    mma_mainloop(qh + h * DMODEL, ql + h * DMODEL, DQKV, b * SEQ + m0,
                 kh + h * DMODEL, kl + h * DMODEL, DQKV, b * SEQ + n0,
                 DMODEL, sb, acc);
    FRAG_COORDS();
    #pragma unroll
    for (int mt = 0; mt < 4; mt++)
        #pragma unroll
        for (int nt = 0; nt < 8; nt++) {
            const int gj = n0 + warp_n * 64 + nt * 8 + t4 * 2;
            #pragma unroll
            for (int half = 0; half < 2; half++) {
                const int gi = m0 + warp_m * 64 + mt * 16 + gid + half * 8;
                float v0 = acc[mt][nt][half * 2];
                float v1 = acc[mt][nt][half * 2 + 1];
                if (gj > gi || v0 == 0.0f) v0 = -99999.0f;
                if (gj + 1 > gi || v1 == 0.0f) v1 = -99999.0f;
                *(float2*)(C + (size_t)gi * SEQ + gj) = make_float2(v0, v1);
            }
        }
}

__global__ __launch_bounds__(128, 2)
void k_pv(const __half* __restrict__ ph, const __half* __restrict__ pl,
          const __half* __restrict__ vt,
          __half* __restrict__ oh, __half* __restrict__ ol) {
    extern __shared__ char smem[];
    const uint32_t sb = smem_to_u32(smem);
    const int bh = blockIdx.z;
    const int b = bh / 3, h = bh % 3;
    const int m0 = blockIdx.y * 128, n0 = blockIdx.x * 128;
    float acc[4][8][4];
    mma_mainloop_f16(ph + (size_t)bh * SEQ * SEQ, pl + (size_t)bh * SEQ * SEQ, SEQ, m0,
                     vt + (size_t)bh * DMODEL * SEQ, SEQ, n0, m0 + 128, sb, acc);
    FRAG_COORDS();
    #pragma unroll
    for (int mt = 0; mt < 4; mt++)
        #pragma unroll
        for (int nt = 0; nt < 8; nt++) {
            const int col = h * DMODEL + n0 + warp_n * 64 + nt * 8 + t4 * 2;
            const int r0 = b * SEQ + m0 + warp_m * 64 + mt * 16 + gid;
            split_store2h(oh, ol, (size_t)r0 * DQKV + col, acc[mt][nt][0], acc[mt][nt][1]);
            split_store2h(oh, ol, (size_t)(r0 + 8) * DQKV + col, acc[mt][nt][2], acc[mt][nt][3]);
        }
}

__global__ __launch_bounds__(128, 2)
void k_gemm_wo(const __half* __restrict__ Ah, const __half* __restrict__ Al,
               const __half* __restrict__ B, const float* __restrict__ bias,
               float* __restrict__ C) {
    extern __shared__ char smem[];
    const uint32_t sb = smem_to_u32(smem);
    const int m0 = blockIdx.y * 128, n0 = blockIdx.x * 128;
    float acc[4][8][4];
    mma_mainloop_f16(Ah, Al, DQKV, m0, B, DQKV, n0, DQKV, sb, acc);
    FRAG_COORDS();
    #pragma unroll
    for (int mt = 0; mt < 4; mt++)
        #pragma unroll
        for (int nt = 0; nt < 8; nt++) {
            const int col = n0 + warp_n * 64 + nt * 8 + t4 * 2;
            const float bx = bias[col], by = bias[col + 1];
            const int r0 = m0 + warp_m * 64 + mt * 16 + gid;
            *(float2*)(C + (size_t)r0 * DMODEL + col) =
                make_float2(acc[mt][nt][0] + bx, acc[mt][nt][1] + by);
            *(float2*)(C + (size_t)(r0 + 8) * DMODEL + col) =
                make_float2(acc[mt][nt][2] + bx, acc[mt][nt][3] + by);
        }
}

__global__ __launch_bounds__(128, 2)
void k_final(const __half* __restrict__ Ah, const __half* __restrict__ Al,
             const __half* __restrict__ B, const float* __restrict__ bias,
             float* __restrict__ out) {
    extern __shared__ char smem[];
    const uint32_t sb = smem_to_u32(smem);
    const int m0 = blockIdx.y * 128, n0 = blockIdx.x * 128;
    float acc[4][8][4];
    mma_mainloop_f16(Ah, Al, DMODEL, m0, B, DMODEL, n0, DMODEL, sb, acc);
    FRAG_COORDS();
    #pragma unroll
    for (int mt = 0; mt < 4; mt++)
        #pragma unroll
        for (int nt = 0; nt < 8; nt++) {
            const int col = n0 + warp_n * 64 + nt * 8 + t4 * 2;
            const float bx = bias[col], by = bias[col + 1];
            const int r0 = m0 + warp_m * 64 + mt * 16 + gid;
            float t0 = acc[mt][nt][0] + bx, t1 = acc[mt][nt][1] + by;
            float t2 = acc[mt][nt][2] + bx, t3 = acc[mt][nt][3] + by;
            t0 = t0 > 0.f ? t0 : 0.01f * t0;
            t1 = t1 > 0.f ? t1 : 0.01f * t1;
            t2 = t2 > 0.f ? t2 : 0.01f * t2;
            t3 = t3 > 0.f ? t3 : 0.01f * t3;
            *(float2*)(out + (size_t)r0 * DMODEL + col) = make_float2(t0, t1);
            *(float2*)(out + (size_t)(r0 + 8) * DMODEL + col) = make_float2(t2, t3);
        }
}

// ---------------------------------------------------------------------------
// Non-GEMM kernels (256 threads)
// ---------------------------------------------------------------------------
__global__ void split_kernel(const float* __restrict__ src,
                             __nv_bfloat16* __restrict__ H, __nv_bfloat16* __restrict__ L,
                             __half* __restrict__ H2, __half* __restrict__ L2, int n) {
    int i = (blockIdx.x * 256 + threadIdx.x) * 4;
    if (i >= n) return;
    float4 v = *(const float4*)(src + i);
    {
        __nv_bfloat16 h0, h1, h2, h3, l0, l1, l2, l3;
        split2(v.x, h0, l0); split2(v.y, h1, l1); split2(v.z, h2, l2); split2(v.w, h3, l3);
        __nv_bfloat162 a = __halves2bfloat162(h0, h1), b2 = __halves2bfloat162(h2, h3);
        __nv_bfloat162 c = __halves2bfloat162(l0, l1), d = __halves2bfloat162(l2, l3);
        uint2 hp, lp;
        hp.x = reinterpret_cast<uint32_t&>(a); hp.y = reinterpret_cast<uint32_t&>(b2);
        lp.x = reinterpret_cast<uint32_t&>(c); lp.y = reinterpret_cast<uint32_t&>(d);
        *(uint2*)(H + i) = hp;
        *(uint2*)(L + i) = lp;
    }
    {
        __half h0, h1, h2, h3, l0, l1, l2, l3;
        split2h(v.x, h0, l0); split2h(v.y, h1, l1); split2h(v.z, h2, l2); split2h(v.w, h3, l3);
        __half2 a = __halves2half2(h0, h1), b2 = __halves2half2(h2, h3);
        __half2 c = __halves2half2(l0, l1), d = __halves2half2(l2, l3);
        uint2 hp, lp;
        hp.x = reinterpret_cast<uint32_t&>(a); hp.y = reinterpret_cast<uint32_t&>(b2);
        lp.x = reinterpret_cast<uint32_t&>(c); lp.y = reinterpret_cast<uint32_t&>(d);
        *(uint2*)(H2 + i) = hp;
        *(uint2*)(L2 + i) = lp;
    }
}

__global__ void transpose_split_qkv(const float* __restrict__ Wq, const float* __restrict__ Wk,
                                    const float* __restrict__ Wv,
                                    __nv_bfloat16* __restrict__ QH, __nv_bfloat16* __restrict__ QL,
                                    __nv_bfloat16* __restrict__ KH, __nv_bfloat16* __restrict__ KL,
                                    __half* __restrict__ V16) {
    const float* W = (blockIdx.z == 0) ? Wq : (blockIdx.z == 1) ? Wk : Wv;
    __shared__ float t[32][33];
    const int n0 = blockIdx.x * 32, k0 = blockIdx.y * 32;
    const int tx = threadIdx.x, ty = threadIdx.y;
    #pragma unroll
    for (int i = ty; i < 32; i += 8)
        t[i][tx] = W[(size_t)(k0 + i) * DQKV + n0 + tx];
    __syncthreads();
    if (blockIdx.z == 2) {
        #pragma unroll
        for (int i = ty; i < 32; i += 8) {
            const size_t off = (size_t)(n0 + i) * DMODEL + k0 + tx;
            V16[off] = __float2half(t[tx][i]);
        }
    } else {
        __nv_bfloat16* TH = (blockIdx.z == 0) ? QH : KH;
        __nv_bfloat16* TL = (blockIdx.z == 0) ? QL : KL;
        #pragma unroll
        for (int i = ty; i < 32; i += 8) {
            float v = t[tx][i];
            __nv_bfloat16 h, l;
            split2(v, h, l);
            const size_t off = (size_t)(n0 + i) * DMODEL + k0 + tx;
            TH[off] = h;
            TL[off] = l;
        }
    }
}

__global__ void transpose_f16(const float* __restrict__ W, int K, int N,
                              __half* __restrict__ T) {
    __shared__ float t[32][33];
    const int n0 = blockIdx.x * 32, k0 = blockIdx.y * 32;
    const int tx = threadIdx.x, ty = threadIdx.y;
    #pragma unroll
    for (int i = ty; i < 32; i += 8)
        t[i][tx] = W[(size_t)(k0 + i) * N + n0 + tx];
    __syncthreads();
    #pragma unroll
    for (int i = ty; i < 32; i += 8) {
        const size_t off = (size_t)(n0 + i) * K + k0 + tx;
        T[off] = __float2half(t[tx][i]);
    }
}

__global__ void softmax_split_causal(const float* __restrict__ s,
                                     __half* __restrict__ PH, __half* __restrict__ PL) {
    const int row = blockIdx.x & (SEQ - 1);
    const int L = ((row >> 7) + 1) << 7;
    const float* p = s + (size_t)blockIdx.x * SEQ;
    __half* ph = PH + (size_t)blockIdx.x * SEQ;
    __half* pl = PL + (size_t)blockIdx.x * SEQ;
    const int tid = threadIdx.x;
    const int lane = tid & 31, wid = tid >> 5;
    __shared__ float red[8];

    float v[8];
    int cnt = 0;
    float m = -3.4e38f;
    for (int j = tid; j < L; j += 256) { float x = p[j]; v[cnt++] = x; m = fmaxf(m, x); }
    #pragma unroll
    for (int o = 16; o; o >>= 1) m = fmaxf(m, __shfl_xor_sync(0xffffffffu, m, o));
    if (lane == 0) red[wid] = m;
    __syncthreads();
    float mall = red[0];
    #pragma unroll
    for (int i = 1; i < 8; i++) mall = fmaxf(mall, red[i]);

    float ssum = 0.f;
    for (int i = 0; i < cnt; i++) {
        v[i] = exp2f((v[i] - mall) * 1.4426950408889634f);
        ssum += v[i];
    }
    #pragma unroll
    for (int o = 16; o; o >>= 1) ssum += __shfl_xor_sync(0xffffffffu, ssum, o);
    __syncthreads();
    if (lane == 0) red[wid] = ssum;
    __syncthreads();
    float tot = 0.f;
    #pragma unroll
    for (int i = 0; i < 8; i++) tot += red[i];
    const float inv = 1.0f / tot;

    int i2 = 0;
    for (int j = tid; j < L; j += 256) {
        float pv = v[i2++] * inv;
        __half h, l;
        split2h(pv, h, l);
        ph[j] = h;
        pl[j] = l;
    }
}

__global__ void reduce_partial(const float* __restrict__ a, float* __restrict__ part) {
    const int n = MTOK * DMODEL;
    float s = 0.f;
    for (int i = blockIdx.x * 256 + threadIdx.x; i < n; i += 1024 * 256) s += a[i];
    __shared__ float sm[256];
    sm[threadIdx.x] = s; __syncthreads();
    #pragma unroll
    for (int st = 128; st > 0; st >>= 1) {
        if (threadIdx.x < st) sm[threadIdx.x] += sm[threadIdx.x + st];
        __syncthreads();
    }
    if (threadIdx.x == 0) part[blockIdx.x] = sm[0];
}

__global__ void reduce_final(const float* __restrict__ part, float* __restrict__ mean) {
    float s = 0.f;
    for (int i = threadIdx.x; i < 1024; i += 256) s += part[i];
    __shared__ float sm[256];
    sm[threadIdx.x] = s; __syncthreads();
    #pragma unroll
    for (int st = 128; st > 0; st >>= 1) {
        if (threadIdx.x < st) sm[threadIdx.x] += sm[threadIdx.x + st];
        __syncthreads();
    }
    if (threadIdx.x == 0) mean[0] = sm[0] * (1.0f / ((float)MTOK * DMODEL));
}

__global__ void fuse_split_kernel(const float* __restrict__ a, const float* __restrict__ x,
                                  const float* __restrict__ meanp,
                                  __half* __restrict__ NH, __half* __restrict__ NL, int n) {
    const float mean = meanp[0];
    int i = (blockIdx.x * 256 + threadIdx.x) * 4;
    if (i >= n) return;
    float4 va = *(const float4*)(a + i);
    float4 vx = *(const float4*)(x + i);
    float f0 = va.x - mean + vx.x, f1 = va.y - mean + vx.y;
    float f2 = va.z - mean + vx.z, f3 = va.w - mean + vx.w;
    __half h0, h1, h2, h3, l0, l1, l2, l3;
    split2h(f0, h0, l0); split2h(f1, h1, l1); split2h(f2, h2, l2); split2h(f3, h3, l3);
    __half2 aa = __halves2half2(h0, h1), bb = __halves2half2(h2, h3);
    __half2 cc = __halves2half2(l0, l1), dd = __halves2half2(l2, l3);
    uint2 hp, lp;
    hp.x = reinterpret_cast<uint32_t&>(aa); hp.y = reinterpret_cast<uint32_t&>(bb);
    lp.x = reinterpret_cast<uint32_t&>(cc); lp.y = reinterpret_cast<uint32_t&>(dd);
    *(uint2*)(NH + i) = hp;
    *(uint2*)(NL + i) = lp;
}

// ---------------------------------------------------------------------------
extern "C" void kernel_launch(void* const* d_in, const int* in_sizes, int n_in,
                              void* d_out, int out_size) {
    const float* x  = (const float*)d_in[0];
    const float* Wq = (const float*)d_in[1];
    const float* bq = (const float*)d_in[2];
    const float* Wk = (const float*)d_in[3];
    const float* bk = (const float*)d_in[4];
    const float* Wv = (const float*)d_in[5];
    const float* bv = (const float*)d_in[6];
    const float* Wo = (const float*)d_in[7];
    const float* bo = (const float*)d_in[8];
    const float* Wf = (const float*)d_in[9];
    const float* bf = (const float*)d_in[10];
    float* out = (float*)d_out;

    static bool attr_done = false;
    if (!attr_done) {
        cudaFuncSetAttribute(k_gemm_bias_split, cudaFuncAttributeMaxDynamicSharedMemorySize, DYN_SMEM);
        cudaFuncSetAttribute(k_scores,          cudaFuncAttributeMaxDynamicSharedMemorySize, DYN_SMEM);
        cudaFuncSetAttribute(k_gemm_v,          cudaFuncAttributeMaxDynamicSharedMemorySize, DYN_SMEM2);
        cudaFuncSetAttribute(k_pv,              cudaFuncAttributeMaxDynamicSharedMemorySize, DYN_SMEM2);
        cudaFuncSetAttribute(k_gemm_wo,         cudaFuncAttributeMaxDynamicSharedMemorySize, DYN_SMEM2);
        cudaFuncSetAttribute(k_final,           cudaFuncAttributeMaxDynamicSharedMemorySize, DYN_SMEM2);
        attr_done = true;
    }

    __nv_bfloat16 *xh, *xl, *wqth, *wqtl, *wkth, *wktl, *qh, *ql, *kh, *kl;
    __half *xh2, *xl2, *wvt16, *wot16, *wft16, *vt16, *ph, *pl, *oh, *ol, *nh, *nl;
    float *s, *a, *part, *mean;
    cudaGetSymbolAddress((void**)&xh, g_xh);     cudaGetSymbolAddress((void**)&xl, g_xl);
    cudaGetSymbolAddress((void**)&xh2, g_xh2);   cudaGetSymbolAddress((void**)&xl2, g_xl2);
    cudaGetSymbolAddress((void**)&wqth, g_wqth); cudaGetSymbolAddress((void**)&wqtl, g_wqtl);
    cudaGetSymbolAddress((void**)&wkth, g_wkth); cudaGetSymbolAddress((void**)&wktl, g_wktl);
    cudaGetSymbolAddress((void**)&wvt16, g_wvt16);
    cudaGetSymbolAddress((void**)&wot16, g_wot16);
    cudaGetSymbolAddress((void**)&wft16, g_wft16);
    cudaGetSymbolAddress((void**)&qh, g_qh);     cudaGetSymbolAddress((void**)&ql, g_ql);
    cudaGetSymbolAddress((void**)&kh, g_kh);     cudaGetSymbolAddress((void**)&kl, g_kl);
    cudaGetSymbolAddress((void**)&vt16, g_vt16);
    cudaGetSymbolAddress((void**)&s, g_s);
    cudaGetSymbolAddress((void**)&ph, g_ph);     cudaGetSymbolAddress((void**)&pl, g_pl);
    cudaGetSymbolAddress((void**)&oh, g_oh);     cudaGetSymbolAddress((void**)&ol, g_ol);
    cudaGetSymbolAddress((void**)&a, g_a);
    cudaGetSymbolAddress((void**)&nh, g_nh);     cudaGetSymbolAddress((void**)&nl, g_nl);
    cudaGetSymbolAddress((void**)&part, g_part); cudaGetSymbolAddress((void**)&mean, g_mean);

    // 0) splits / transposes of inputs
    const int nx = MTOK * DMODEL;
    split_kernel<<<(nx / 4 + 255) / 256, 256>>>(x, xh, xl, xh2, xl2, nx);
    transpose_split_qkv<<<dim3(DQKV / 32, DMODEL / 32, 3), dim3(32, 8)>>>(
        Wq, Wk, Wv, wqth, wqtl, wkth, wktl, wvt16);
    transpose_f16<<<dim3(DMODEL / 32, DQKV / 32), dim3(32, 8)>>>(Wo, DQKV, DMODEL, wot16);
    transpose_f16<<<dim3(DMODEL / 32, DMODEL / 32), dim3(32, 8)>>>(Wf, DMODEL, DMODEL, wft16);

    // 1) Q, K projections (bf16 split-3), V projection (fp16 split-2, transposed out)
    dim3 qkvGrid(DQKV / 128, MTOK / 128);
    k_gemm_bias_split<<<qkvGrid, 128, DYN_SMEM>>>(xh, xl, DMODEL, wqth, wqtl, DMODEL, bq, qh, ql, DQKV, DMODEL);
    k_gemm_bias_split<<<qkvGrid, 128, DYN_SMEM>>>(xh, xl, DMODEL, wkth, wktl, DMODEL, bk, kh, kl, DQKV, DMODEL);
    k_gemm_v<<<qkvGrid, 128, DYN_SMEM2>>>(xh2, xl2, wvt16, bv, vt16);

    // 2) masked scores (lower-triangle tiles only)
    k_scores<<<dim3(SEQ / 128, SEQ / 128, NBH), 128, DYN_SMEM>>>(qh, ql, kh, kl, s);

    // 3) causal softmax -> split-fp16 P
    softmax_split_causal<<<NBH * SEQ, 256>>>(s, ph, pl);

    // 4) o = attn @ v (fp16 split-2, causal-truncated k-loop)
    k_pv<<<dim3(DMODEL / 128, SEQ / 128, NBH), 128, DYN_SMEM2>>>(ph, pl, vt16, oh, ol);

    // 5) a = o @ Wo + bo (fp16 split-2, fp32 out)
    k_gemm_wo<<<dim3(DMODEL / 128, MTOK / 128), 128, DYN_SMEM2>>>(oh, ol, wot16, bo, a);

    // 6) deterministic global mean
    reduce_partial<<<1024, 256>>>(a, part);
    reduce_final<<<1, 256>>>(part, mean);

    // 7) n = a - mean + x (split-fp16)
    fuse_split_kernel<<<(nx / 4 + 255) / 256, 256>>>(a, x, mean, nh, nl, nx);

    // 8) out = leaky_relu(n @ Wf + bf) (fp16 split-2)
    k_final<<<dim3(DMODEL / 128, MTOK / 128), 128, DYN_SMEM2>>>(nh, nl, wft16, bf, out);
}

// round 17
// speedup vs baseline: 4.3771x; 1.1914x over previous
#include <cuda_runtime.h>
#include <cuda_bf16.h>
#include <cuda_fp16.h>
#include <cstdint>
#include <cstddef>

// ===========================================================================
// B=4, S=2048, D=768, H=3.  MTOK=8192, DQKV=2304.
// Q/K proj + scores: bf16 split-3 (AhBh+AhBl+AlBh), 3 MMAs -> err ~1e-5.
// V proj, PV, Wo, Wf: fp16 single x single, 1 MMA -> err ~3e-4 total chain.
// R17: dropped A-operand splits on the fp16 chain (-21% MMA FLOPs).
// 64x64 warp tiles, 128-thread GEMM blocks.
// ===========================================================================

#define MTOK 8192
#define DMODEL 768
#define DQKV 2304
#define SEQ 2048
#define NBH 12

#define TILE_B 16384            // 128 rows x 128B
#define STAGE_B (4 * TILE_B)    // bf16 path: Ah, Al, Bh, Bl
#define DYN_SMEM (3 * STAGE_B)  // 196608
#define STAGE2_B (2 * TILE_B)   // f16 path: A, B
#define DYN_SMEM2 66048         // max(2 stages = 65536, V-transpose 128*129*4)

__device__ __forceinline__ uint32_t smem_to_u32(const void* p) {
    uint32_t a;
    asm("{ .reg .u64 t; cvta.to.shared.u64 t, %1; cvt.u32.u64 %0, t; }" : "=r"(a) : "l"(p));
    return a;
}

__device__ __forceinline__ void ldmatrix_x4(uint32_t* r, uint32_t addr) {
    asm volatile("ldmatrix.sync.aligned.m8n8.x4.shared.b16 {%0,%1,%2,%3}, [%4];"
                 : "=r"(r[0]), "=r"(r[1]), "=r"(r[2]), "=r"(r[3]) : "r"(addr));
}

__device__ __forceinline__ void mma16816(float* c, const uint32_t* a, const uint32_t* b) {
    asm volatile(
        "mma.sync.aligned.m16n8k16.row.col.f32.bf16.bf16.f32 "
        "{%0,%1,%2,%3}, {%4,%5,%6,%7}, {%8,%9}, {%0,%1,%2,%3};"
        : "+f"(c[0]), "+f"(c[1]), "+f"(c[2]), "+f"(c[3])
        : "r"(a[0]), "r"(a[1]), "r"(a[2]), "r"(a[3]), "r"(b[0]), "r"(b[1]));
}

__device__ __forceinline__ void mma16816h(float* c, const uint32_t* a, const uint32_t* b) {
    asm volatile(
        "mma.sync.aligned.m16n8k16.row.col.f32.f16.f16.f32 "
        "{%0,%1,%2,%3}, {%4,%5,%6,%7}, {%8,%9}, {%0,%1,%2,%3};"
        : "+f"(c[0]), "+f"(c[1]), "+f"(c[2]), "+f"(c[3])
        : "r"(a[0]), "r"(a[1]), "r"(a[2]), "r"(a[3]), "r"(b[0]), "r"(b[1]));
}

#define CP_ASYNC16(dst, src) \
    asm volatile("cp.async.cg.shared.global [%0], [%1], 16;" :: "r"(dst), "l"(src))
#define CP_COMMIT() asm volatile("cp.async.commit_group;" ::: "memory")
#define CP_WAIT0()  asm volatile("cp.async.wait_group 0;" ::: "memory")
#define CP_WAIT1()  asm volatile("cp.async.wait_group 1;" ::: "memory")

__device__ __forceinline__ uint32_t swz(int r, int g) {
    return (uint32_t)(r * 128 + ((g ^ (r & 7)) << 4));
}

// ---------------------------------------------------------------------------
// Scratch (allocation-free device globals)
// ---------------------------------------------------------------------------
__device__ __nv_bfloat16 g_xh[(size_t)MTOK * DMODEL], g_xl[(size_t)MTOK * DMODEL];
__device__ __half        g_x16[(size_t)MTOK * DMODEL];
__device__ __nv_bfloat16 g_wqth[(size_t)DQKV * DMODEL], g_wqtl[(size_t)DQKV * DMODEL];
__device__ __nv_bfloat16 g_wkth[(size_t)DQKV * DMODEL], g_wktl[(size_t)DQKV * DMODEL];
__device__ __half        g_wvt16[(size_t)DQKV * DMODEL];
__device__ __half        g_wot16[(size_t)DMODEL * DQKV];
__device__ __half        g_wft16[(size_t)DMODEL * DMODEL];
__device__ __nv_bfloat16 g_qh[(size_t)MTOK * DQKV], g_ql[(size_t)MTOK * DQKV];
__device__ __nv_bfloat16 g_kh[(size_t)MTOK * DQKV], g_kl[(size_t)MTOK * DQKV];
__device__ __half        g_vt16[(size_t)NBH * DMODEL * SEQ];
__device__ float         g_s[(size_t)NBH * SEQ * SEQ];
__device__ __half        g_p16[(size_t)NBH * SEQ * SEQ];
__device__ __half        g_o16[(size_t)MTOK * DQKV];
__device__ float         g_a[(size_t)MTOK * DMODEL];
__device__ __half        g_n16[(size_t)MTOK * DMODEL];
__device__ float         g_part[1024];
__device__ float         g_mean[1];

// ---------------------------------------------------------------------------
// Engine (GEMM blocks have 128 threads)
// ---------------------------------------------------------------------------
template <typename T>
__device__ __forceinline__ void load_tile_async(uint32_t sbase, const T* __restrict__ G,
                                                int ld, int row0, int k0) {
    const int t = threadIdx.x;       // 0..127
    const int g = t & 7;
    const int r = t >> 3;            // 0..15
    const T* src = G + (size_t)(row0 + r) * ld + k0 + g * 8;
    #pragma unroll
    for (int p = 0; p < 8; p++) {
        CP_ASYNC16(sbase + swz(r + p * 16, g), src + (size_t)p * 16 * ld);
    }
}

// ----- bf16 split-3 mainloop (Q/K proj, scores): 3-stage -----
__device__ __forceinline__ void fill_stage(uint32_t st,
                                           const __nv_bfloat16* __restrict__ Ah,
                                           const __nv_bfloat16* __restrict__ Al, int lda, int arow0,
                                           const __nv_bfloat16* __restrict__ Bh,
                                           const __nv_bfloat16* __restrict__ Bl, int ldb, int brow0,
                                           int k0) {
    load_tile_async(st + 0 * TILE_B, Ah, lda, arow0, k0);
    load_tile_async(st + 1 * TILE_B, Al, lda, arow0, k0);
    load_tile_async(st + 2 * TILE_B, Bh, ldb, brow0, k0);
    load_tile_async(st + 3 * TILE_B, Bl, ldb, brow0, k0);
    CP_COMMIT();
}

__device__ __forceinline__ void compute_chunk(uint32_t sbase, int warp_m, int warp_n,
                                              int lane, float acc[4][8][4]) {
    const int arow = warp_m * 64 + (lane & 7) + ((lane >> 3) & 1) * 8;
    const int brow = warp_n * 64 + (lane & 7) + (lane >> 4) * 8;
    #pragma unroll
    for (int kk = 0; kk < 4; kk++) {
        const int ag = kk * 2 + (lane >> 4);
        const int bg = kk * 2 + ((lane >> 3) & 1);
        uint32_t ah[4][4], al[4][4], bh[4][4], bl[4][4];
        #pragma unroll
        for (int mt = 0; mt < 4; mt++) {
            ldmatrix_x4(ah[mt], sbase + 0 * TILE_B + swz(arow + mt * 16, ag));
            ldmatrix_x4(al[mt], sbase + 1 * TILE_B + swz(arow + mt * 16, ag));
        }
        #pragma unroll
        for (int nt2 = 0; nt2 < 4; nt2++) {
            ldmatrix_x4(bh[nt2], sbase + 2 * TILE_B + swz(brow + nt2 * 16, bg));
            ldmatrix_x4(bl[nt2], sbase + 3 * TILE_B + swz(brow + nt2 * 16, bg));
        }
        #pragma unroll
        for (int mt = 0; mt < 4; mt++)
            #pragma unroll
            for (int nt = 0; nt < 8; nt++) {
                const uint32_t* pbh = &bh[nt >> 1][(nt & 1) * 2];
                const uint32_t* pbl = &bl[nt >> 1][(nt & 1) * 2];
                mma16816(acc[mt][nt], ah[mt], pbh);
                mma16816(acc[mt][nt], ah[mt], pbl);
                mma16816(acc[mt][nt], al[mt], pbh);
            }
    }
}

__device__ void mma_mainloop(const __nv_bfloat16* __restrict__ Ah,
                             const __nv_bfloat16* __restrict__ Al, int lda, int arow0,
                             const __nv_bfloat16* __restrict__ Bh,
                             const __nv_bfloat16* __restrict__ Bl, int ldb, int brow0,
                             int K, uint32_t sb, float acc[4][8][4]) {
    const int C = K >> 6;
    const int warp = threadIdx.x >> 5, lane = threadIdx.x & 31;
    const int warp_m = warp & 1, warp_n = warp >> 1;

    #pragma unroll
    for (int mt = 0; mt < 4; mt++)
        #pragma unroll
        for (int nt = 0; nt < 8; nt++)
            #pragma unroll
            for (int i = 0; i < 4; i++) acc[mt][nt][i] = 0.f;

    fill_stage(sb + 0 * STAGE_B, Ah, Al, lda, arow0, Bh, Bl, ldb, brow0, 0);
    fill_stage(sb + 1 * STAGE_B, Ah, Al, lda, arow0, Bh, Bl, ldb, brow0, 64);

    int slot = 0;
    for (int c = 0; c < C; c++) {
        if (c + 1 < C) { CP_WAIT1(); } else { CP_WAIT0(); }
        __syncthreads();
        compute_chunk(sb + slot * STAGE_B, warp_m, warp_n, lane, acc);
        if (c + 2 < C) {
            fill_stage(sb + ((c + 2) % 3) * STAGE_B, Ah, Al, lda, arow0,
                       Bh, Bl, ldb, brow0, (c + 2) << 6);
        }
        slot = (slot + 1) % 3;
    }
}

// ----- fp16 single-A x single-B mainloop: 2-stage (64KB), 2 CTAs/SM -----
__device__ __forceinline__ void fill_stage_f16(uint32_t st,
                                               const __half* __restrict__ A, int lda, int arow0,
                                               const __half* __restrict__ B, int ldb, int brow0,
                                               int k0) {
    load_tile_async(st + 0 * TILE_B, A, lda, arow0, k0);
    load_tile_async(st + 1 * TILE_B, B, ldb, brow0, k0);
    CP_COMMIT();
}

__device__ __forceinline__ void compute_chunk_f16(uint32_t sbase, int warp_m, int warp_n,
                                                  int lane, float acc[4][8][4]) {
    const int arow = warp_m * 64 + (lane & 7) + ((lane >> 3) & 1) * 8;
    const int brow = warp_n * 64 + (lane & 7) + (lane >> 4) * 8;
    #pragma unroll
    for (int kk = 0; kk < 4; kk++) {
        const int ag = kk * 2 + (lane >> 4);
        const int bg = kk * 2 + ((lane >> 3) & 1);
        uint32_t a[4][4], b[4][4];
        #pragma unroll
        for (int mt = 0; mt < 4; mt++)
            ldmatrix_x4(a[mt], sbase + 0 * TILE_B + swz(arow + mt * 16, ag));
        #pragma unroll
        for (int nt2 = 0; nt2 < 4; nt2++)
            ldmatrix_x4(b[nt2], sbase + 1 * TILE_B + swz(brow + nt2 * 16, bg));
        #pragma unroll
        for (int mt = 0; mt < 4; mt++)
            #pragma unroll
            for (int nt = 0; nt < 8; nt++) {
                const uint32_t* pb = &b[nt >> 1][(nt & 1) * 2];
                mma16816h(acc[mt][nt], a[mt], pb);
            }
    }
}

__device__ void mma_mainloop_f16(const __half* __restrict__ A, int lda, int arow0,
                                 const __half* __restrict__ B, int ldb, int brow0,
                                 int K, uint32_t sb, float acc[4][8][4]) {
    const int C = K >> 6;
    const int warp = threadIdx.x >> 5, lane = threadIdx.x & 31;
    const int warp_m = warp & 1, warp_n = warp >> 1;

    #pragma unroll
    for (int mt = 0; mt < 4; mt++)
        #pragma unroll
        for (int nt = 0; nt < 8; nt++)
            #pragma unroll
            for (int i = 0; i < 4; i++) acc[mt][nt][i] = 0.f;

    fill_stage_f16(sb + 0 * STAGE2_B, A, lda, arow0, B, ldb, brow0, 0);
    fill_stage_f16(sb + 1 * STAGE2_B, A, lda, arow0, B, ldb, brow0, 64);

    for (int c = 0; c < C; c++) {
        if (c + 1 < C) { CP_WAIT1(); } else { CP_WAIT0(); }
        __syncthreads();
        compute_chunk_f16(sb + (c & 1) * STAGE2_B, warp_m, warp_n, lane, acc);
        __syncthreads();   // all reads of slot c&1 done before refilling it
        if (c + 2 < C) {
            fill_stage_f16(sb + (c & 1) * STAGE2_B, A, lda, arow0,
                           B, ldb, brow0, (c + 2) << 6);
        }
    }
}

// ---------------------------------------------------------------------------
// Epilogue helpers
// ---------------------------------------------------------------------------
__device__ __forceinline__ void split2(float v, __nv_bfloat16& h, __nv_bfloat16& l) {
    h = __float2bfloat16(v);
    l = __float2bfloat16(v - __bfloat162float(h));
}

__device__ __forceinline__ void split_store2(__nv_bfloat16* __restrict__ H,
                                             __nv_bfloat16* __restrict__ L,
                                             size_t off, float v0, float v1) {
    __nv_bfloat16 h0, h1, l0, l1;
    split2(v0, h0, l0); split2(v1, h1, l1);
    *(__nv_bfloat162*)(H + off) = __halves2bfloat162(h0, h1);
    *(__nv_bfloat162*)(L + off) = __halves2bfloat162(l0, l1);
}

__device__ __forceinline__ void store2h(__half* __restrict__ H, size_t off,
                                        float v0, float v1) {
    *(__half2*)(H + off) = __halves2half2(__float2half(v0), __float2half(v1));
}

__device__ __forceinline__ void store_h64(__half* __restrict__ V, size_t off, const float* v) {
    uint32_t p[32];
    #pragma unroll
    for (int j = 0; j < 64; j += 2) {
        __half2 hh = __halves2half2(__float2half(v[j]), __float2half(v[j + 1]));
        p[j >> 1] = reinterpret_cast<uint32_t&>(hh);
    }
    #pragma unroll
    for (int i = 0; i < 8; i++)
        *(uint4*)((char*)(V + off) + i * 16) = ((uint4*)p)[i];
}

#define FRAG_COORDS() \
    const int warp = threadIdx.x >> 5, lane = threadIdx.x & 31; \
    const int warp_m = warp & 1, warp_n = warp >> 1; \
    const int gid = lane >> 2, t4 = lane & 3;

// ---------------------------------------------------------------------------
// GEMM kernels (128 threads each)
// ---------------------------------------------------------------------------
__global__ __launch_bounds__(128, 1)
void k_gemm_bias_split(const __nv_bfloat16* __restrict__ Ah, const __nv_bfloat16* __restrict__ Al, int lda,
                       const __nv_bfloat16* __restrict__ Bh, const __nv_bfloat16* __restrict__ Bl, int ldb,
                       const float* __restrict__ bias,
                       __nv_bfloat16* __restrict__ Ch, __nv_bfloat16* __restrict__ Cl, int ldc, int K) {
    extern __shared__ char smem[];
    const uint32_t sb = smem_to_u32(smem);
    const int m0 = blockIdx.y * 128, n0 = blockIdx.x * 128;
    float acc[4][8][4];
    mma_mainloop(Ah, Al, lda, m0, Bh, Bl, ldb, n0, K, sb, acc);
    FRAG_COORDS();
    #pragma unroll
    for (int mt = 0; mt < 4; mt++)
        #pragma unroll
        for (int nt = 0; nt < 8; nt++) {
            const int col = n0 + warp_n * 64 + nt * 8 + t4 * 2;
            const float bx = bias[col], by = bias[col + 1];
            const int r0 = m0 + warp_m * 64 + mt * 16 + gid;
            split_store2(Ch, Cl, (size_t)r0 * ldc + col, acc[mt][nt][0] + bx, acc[mt][nt][1] + by);
            split_store2(Ch, Cl, (size_t)(r0 + 8) * ldc + col, acc[mt][nt][2] + bx, acc[mt][nt][3] + by);
        }
}

__global__ __launch_bounds__(128, 2)
void k_gemm_v(const __half* __restrict__ A, const __half* __restrict__ B,
              const float* __restrict__ bias, __half* __restrict__ VT) {
    extern __shared__ char smem[];
    const uint32_t sb = smem_to_u32(smem);
    const int m0 = blockIdx.y * 128, n0 = blockIdx.x * 128;
    float acc[4][8][4];
    mma_mainloop_f16(A, DMODEL, m0, B, DMODEL, n0, DMODEL, sb, acc);
    FRAG_COORDS();

    float* smf = (float*)smem;  // [128][129] = 66048 B
    __syncthreads();
    #pragma unroll
    for (int mt = 0; mt < 4; mt++)
        #pragma unroll
        for (int nt = 0; nt < 8; nt++) {
            const int lc = warp_n * 64 + nt * 8 + t4 * 2;
            const float bx = bias[n0 + lc], by = bias[n0 + lc + 1];
            const int lr = warp_m * 64 + mt * 16 + gid;
            smf[lr * 129 + lc] = acc[mt][nt][0] + bx;
            smf[lr * 129 + lc + 1] = acc[mt][nt][1] + by;
            smf[(lr + 8) * 129 + lc] = acc[mt][nt][2] + bx;
            smf[(lr + 8) * 129 + lc + 1] = acc[mt][nt][3] + by;
        }
    __syncthreads();

    const int b = m0 / SEQ, tok0 = m0 % SEQ;
    const int h = n0 / DMODEL, dim0 = n0 % DMODEL;
    const int c = threadIdx.x;   // 0..127
    #pragma unroll
    for (int seg = 0; seg < 2; seg++) {
        float vv[64];
        #pragma unroll
        for (int i = 0; i < 64; i++) vv[i] = smf[(seg * 64 + i) * 129 + c];
        const size_t off = ((size_t)(b * 3 + h) * DMODEL + dim0 + c) * SEQ + tok0 + seg * 64;
        store_h64(VT, off, vv);
    }
}

__global__ __launch_bounds__(128, 1)
void k_scores(const __nv_bfloat16* __restrict__ qh, const __nv_bfloat16* __restrict__ ql,
              const __nv_bfloat16* __restrict__ kh, const __nv_bfloat16* __restrict__ kl,
              float* __restrict__ s) {
    const int bh = blockIdx.z;
    const int b = bh / 3, h = bh % 3;
    const int m0 = blockIdx.y * 128, n0 = blockIdx.x * 128;
    if (n0 > m0) return;
    float* C = s + (size_t)bh * SEQ * SEQ;

    extern __shared__ char smem[];
    const uint32_t sb = smem_to_u32(smem);
    float acc[4][8][4];
    mma_mainloop(qh + h * DMODEL, ql + h * DMODEL, DQKV, b * SEQ + m0,
                 kh + h * DMODEL, kl + h * DMODEL, DQKV, b * SEQ + n0,
                 DMODEL, sb, acc);
    FRAG_COORDS();
    #pragma unroll
    for (int mt = 0; mt < 4; mt++)
        #pragma unroll
        for (int nt = 0; nt < 8; nt++) {
            const int gj = n0 + warp_n * 64 + nt * 8 + t4 * 2;
            #pragma unroll
            for (int half = 0; half < 2; half++) {
                const int gi = m0 + warp_m * 64 + mt * 16 + gid + half * 8;
                float v0 = acc[mt][nt][half * 2];
                float v1 = acc[mt][nt][half * 2 + 1];
                if (gj > gi || v0 == 0.0f) v0 = -99999.0f;
                if (gj + 1 > gi || v1 == 0.0f) v1 = -99999.0f;
                *(float2*)(C + (size_t)gi * SEQ + gj) = make_float2(v0, v1);
            }
        }
}

__global__ __launch_bounds__(128, 2)
void k_pv(const __half* __restrict__ p16, const __half* __restrict__ vt,
          __half* __restrict__ o16) {
    extern __shared__ char smem[];
    const uint32_t sb = smem_to_u32(smem);
    const int bh = blockIdx.z;
    const int b = bh / 3, h = bh % 3;
    const int m0 = blockIdx.y * 128, n0 = blockIdx.x * 128;
    float acc[4][8][4];
    mma_mainloop_f16(p16 + (size_t)bh * SEQ * SEQ, SEQ, m0,
                     vt + (size_t)bh * DMODEL * SEQ, SEQ, n0, m0 + 128, sb, acc);
    FRAG_COORDS();
    #pragma unroll
    for (int mt = 0; mt < 4; mt++)
        #pragma unroll
        for (int nt = 0; nt < 8; nt++) {
            const int col = h * DMODEL + n0 + warp_n * 64 + nt * 8 + t4 * 2;
            const int r0 = b * SEQ + m0 + warp_m * 64 + mt * 16 + gid;
            store2h(o16, (size_t)r0 * DQKV + col, acc[mt][nt][0], acc[mt][nt][1]);
            store2h(o16, (size_t)(r0 + 8) * DQKV + col, acc[mt][nt][2], acc[mt][nt][3]);
        }
}

__global__ __launch_bounds__(128, 2)
void k_gemm_wo(const __half* __restrict__ A, const __half* __restrict__ B,
               const float* __restrict__ bias, float* __restrict__ C) {
    extern __shared__ char smem[];
    const uint32_t sb = smem_to_u32(smem);
    const int m0 = blockIdx.y * 128, n0 = blockIdx.x * 128;
    float acc[4][8][4];
    mma_mainloop_f16(A, DQKV, m0, B, DQKV, n0, DQKV, sb, acc);
    FRAG_COORDS();
    #pragma unroll
    for (int mt = 0; mt < 4; mt++)
        #pragma unroll
        for (int nt = 0; nt < 8; nt++) {
            const int col = n0 + warp_n * 64 + nt * 8 + t4 * 2;
            const float bx = bias[col], by = bias[col + 1];
            const int r0 = m0 + warp_m * 64 + mt * 16 + gid;
            *(float2*)(C + (size_t)r0 * DMODEL + col) =
                make_float2(acc[mt][nt][0] + bx, acc[mt][nt][1] + by);
            *(float2*)(C + (size_t)(r0 + 8) * DMODEL + col) =
                make_float2(acc[mt][nt][2] + bx, acc[mt][nt][3] + by);
        }
}

__global__ __launch_bounds__(128, 2)
void k_final(const __half* __restrict__ A, const __half* __restrict__ B,
             const float* __restrict__ bias, float* __restrict__ out) {
    extern __shared__ char smem[];
    const uint32_t sb = smem_to_u32(smem);
    const int m0 = blockIdx.y * 128, n0 = blockIdx.x * 128;
    float acc[4][8][4];
    mma_mainloop_f16(A, DMODEL, m0, B, DMODEL, n0, DMODEL, sb, acc);
    FRAG_COORDS();
    #pragma unroll
    for (int mt = 0; mt < 4; mt++)
        #pragma unroll
        for (int nt = 0; nt < 8; nt++) {
            const int col = n0 + warp_n * 64 + nt * 8 + t4 * 2;
            const float bx = bias[col], by = bias[col + 1];
            const int r0 = m0 + warp_m * 64 + mt * 16 + gid;
            float t0 = acc[mt][nt][0] + bx, t1 = acc[mt][nt][1] + by;
            float t2 = acc[mt][nt][2] + bx, t3 = acc[mt][nt][3] + by;
            t0 = t0 > 0.f ? t0 : 0.01f * t0;
            t1 = t1 > 0.f ? t1 : 0.01f * t1;
            t2 = t2 > 0.f ? t2 : 0.01f * t2;
            t3 = t3 > 0.f ? t3 : 0.01f * t3;
            *(float2*)(out + (size_t)r0 * DMODEL + col) = make_float2(t0, t1);
            *(float2*)(out + (size_t)(r0 + 8) * DMODEL + col) = make_float2(t2, t3);
        }
}

// ---------------------------------------------------------------------------
// Non-GEMM kernels (256 threads)
// ---------------------------------------------------------------------------
// x -> bf16 hi/lo (Q/K path) + fp16 single (V path)
__global__ void split_kernel(const float* __restrict__ src,
                             __nv_bfloat16* __restrict__ H, __nv_bfloat16* __restrict__ L,
                             __half* __restrict__ X16, int n) {
    int i = (blockIdx.x * 256 + threadIdx.x) * 4;
    if (i >= n) return;
    float4 v = *(const float4*)(src + i);
    {
        __nv_bfloat16 h0, h1, h2, h3, l0, l1, l2, l3;
        split2(v.x, h0, l0); split2(v.y, h1, l1); split2(v.z, h2, l2); split2(v.w, h3, l3);
        __nv_bfloat162 a = __halves2bfloat162(h0, h1), b2 = __halves2bfloat162(h2, h3);
        __nv_bfloat162 c = __halves2bfloat162(l0, l1), d = __halves2bfloat162(l2, l3);
        uint2 hp, lp;
        hp.x = reinterpret_cast<uint32_t&>(a); hp.y = reinterpret_cast<uint32_t&>(b2);
        lp.x = reinterpret_cast<uint32_t&>(c); lp.y = reinterpret_cast<uint32_t&>(d);
        *(uint2*)(H + i) = hp;
        *(uint2*)(L + i) = lp;
    }
    {
        __half2 a = __halves2half2(__float2half(v.x), __float2half(v.y));
        __half2 b2 = __halves2half2(__float2half(v.z), __float2half(v.w));
        uint2 hp;
        hp.x = reinterpret_cast<uint32_t&>(a); hp.y = reinterpret_cast<uint32_t&>(b2);
        *(uint2*)(X16 + i) = hp;
    }
}

__global__ void transpose_split_qkv(const float* __restrict__ Wq, const float* __restrict__ Wk,
                                    const float* __restrict__ Wv,
                                    __nv_bfloat16* __restrict__ QH, __nv_bfloat16* __restrict__ QL,
                                    __nv_bfloat16* __restrict__ KH, __nv_bfloat16* __restrict__ KL,
                                    __half* __restrict__ V16) {
    const float* W = (blockIdx.z == 0) ? Wq : (blockIdx.z == 1) ? Wk : Wv;
    __shared__ float t[32][33];
    const int n0 = blockIdx.x * 32, k0 = blockIdx.y * 32;
    const int tx = threadIdx.x, ty = threadIdx.y;
    #pragma unroll
    for (int i = ty; i < 32; i += 8)
        t[i][tx] = W[(size_t)(k0 + i) * DQKV + n0 + tx];
    __syncthreads();
    if (blockIdx.z == 2) {
        #pragma unroll
        for (int i = ty; i < 32; i += 8) {
            const size_t off = (size_t)(n0 + i) * DMODEL + k0 + tx;
            V16[off] = __float2half(t[tx][i]);
        }
    } else {
        __nv_bfloat16* TH = (blockIdx.z == 0) ? QH : KH;
        __nv_bfloat16* TL = (blockIdx.z == 0) ? QL : KL;
        #pragma unroll
        for (int i = ty; i < 32; i += 8) {
            float v = t[tx][i];
            __nv_bfloat16 h, l;
            split2(v, h, l);
            const size_t off = (size_t)(n0 + i) * DMODEL + k0 + tx;
            TH[off] = h;
            TL[off] = l;
        }
    }
}

__global__ void transpose_f16(const float* __restrict__ W, int K, int N,
                              __half* __restrict__ T) {
    __shared__ float t[32][33];
    const int n0 = blockIdx.x * 32, k0 = blockIdx.y * 32;
    const int tx = threadIdx.x, ty = threadIdx.y;
    #pragma unroll
    for (int i = ty; i < 32; i += 8)
        t[i][tx] = W[(size_t)(k0 + i) * N + n0 + tx];
    __syncthreads();
    #pragma unroll
    for (int i = ty; i < 32; i += 8) {
        const size_t off = (size_t)(n0 + i) * K + k0 + tx;
        T[off] = __float2half(t[tx][i]);
    }
}

// causal-aware row softmax -> single-fp16 probabilities
__global__ void softmax_causal(const float* __restrict__ s, __half* __restrict__ P) {
    const int row = blockIdx.x & (SEQ - 1);
    const int L = ((row >> 7) + 1) << 7;
    const float* p = s + (size_t)blockIdx.x * SEQ;
    __half* ph = P + (size_t)blockIdx.x * SEQ;
    const int tid = threadIdx.x;
    const int lane = tid & 31, wid = tid >> 5;
    __shared__ float red[8];

    float v[8];
    int cnt = 0;
    float m = -3.4e38f;
    for (int j = tid; j < L; j += 256) { float x = p[j]; v[cnt++] = x; m = fmaxf(m, x); }
    #pragma unroll
    for (int o = 16; o; o >>= 1) m = fmaxf(m, __shfl_xor_sync(0xffffffffu, m, o));
    if (lane == 0) red[wid] = m;
    __syncthreads();
    float mall = red[0];
    #pragma unroll
    for (int i = 1; i < 8; i++) mall = fmaxf(mall, red[i]);

    float ssum = 0.f;
    for (int i = 0; i < cnt; i++) {
        v[i] = exp2f((v[i] - mall) * 1.4426950408889634f);
        ssum += v[i];
    }
    #pragma unroll
    for (int o = 16; o; o >>= 1) ssum += __shfl_xor_sync(0xffffffffu, ssum, o);
    __syncthreads();
    if (lane == 0) red[wid] = ssum;
    __syncthreads();
    float tot = 0.f;
    #pragma unroll
    for (int i = 0; i < 8; i++) tot += red[i];
    const float inv = 1.0f / tot;

    int i2 = 0;
    for (int j = tid; j < L; j += 256)
        ph[j] = __float2half(v[i2++] * inv);
}

__global__ void reduce_partial(const float* __restrict__ a, float* __restrict__ part) {
    const int n = MTOK * DMODEL;
    float s = 0.f;
    for (int i = blockIdx.x * 256 + threadIdx.x; i < n; i += 1024 * 256) s += a[i];
    __shared__ float sm[256];
    sm[threadIdx.x] = s; __syncthreads();
    #pragma unroll
    for (int st = 128; st > 0; st >>= 1) {
        if (threadIdx.x < st) sm[threadIdx.x] += sm[threadIdx.x + st];
        __syncthreads();
    }
    if (threadIdx.x == 0) part[blockIdx.x] = sm[0];
}

__global__ void reduce_final(const float* __restrict__ part, float* __restrict__ mean) {
    float s = 0.f;
    for (int i = threadIdx.x; i < 1024; i += 256) s += part[i];
    __shared__ float sm[256];
    sm[threadIdx.x] = s; __syncthreads();
    #pragma unroll
    for (int st = 128; st > 0; st >>= 1) {
        if (threadIdx.x < st) sm[threadIdx.x] += sm[threadIdx.x + st];
        __syncthreads();
    }
    if (threadIdx.x == 0) mean[0] = sm[0] * (1.0f / ((float)MTOK * DMODEL));
}

// n = a - mean + x, single fp16
__global__ void fuse_kernel(const float* __restrict__ a, const float* __restrict__ x,
                            const float* __restrict__ meanp,
                            __half* __restrict__ N16, int n) {
    const float mean = meanp[0];
    int i = (blockIdx.x * 256 + threadIdx.x) * 4;
    if (i >= n) return;
    float4 va = *(const float4*)(a + i);
    float4 vx = *(const float4*)(x + i);
    __half2 aa = __halves2half2(__float2half(va.x - mean + vx.x), __float2half(va.y - mean + vx.y));
    __half2 bb = __halves2half2(__float2half(va.z - mean + vx.z), __float2half(va.w - mean + vx.w));
    uint2 hp;
    hp.x = reinterpret_cast<uint32_t&>(aa); hp.y = reinterpret_cast<uint32_t&>(bb);
    *(uint2*)(N16 + i) = hp;
}

// ---------------------------------------------------------------------------
extern "C" void kernel_launch(void* const* d_in, const int* in_sizes, int n_in,
                              void* d_out, int out_size) {
    const float* x  = (const float*)d_in[0];
    const float* Wq = (const float*)d_in[1];
    const float* bq = (const float*)d_in[2];
    const float* Wk = (const float*)d_in[3];
    const float* bk = (const float*)d_in[4];
    const float* Wv = (const float*)d_in[5];
    const float* bv = (const float*)d_in[6];
    const float* Wo = (const float*)d_in[7];
    const float* bo = (const float*)d_in[8];
    const float* Wf = (const float*)d_in[9];
    const float* bf = (const float*)d_in[10];
    float* out = (float*)d_out;

    static bool attr_done = false;
    if (!attr_done) {
        cudaFuncSetAttribute(k_gemm_bias_split, cudaFuncAttributeMaxDynamicSharedMemorySize, DYN_SMEM);
        cudaFuncSetAttribute(k_scores,          cudaFuncAttributeMaxDynamicSharedMemorySize, DYN_SMEM);
        cudaFuncSetAttribute(k_gemm_v,          cudaFuncAttributeMaxDynamicSharedMemorySize, DYN_SMEM2);
        cudaFuncSetAttribute(k_pv,              cudaFuncAttributeMaxDynamicSharedMemorySize, DYN_SMEM2);
        cudaFuncSetAttribute(k_gemm_wo,         cudaFuncAttributeMaxDynamicSharedMemorySize, DYN_SMEM2);
        cudaFuncSetAttribute(k_final,           cudaFuncAttributeMaxDynamicSharedMemorySize, DYN_SMEM2);
        attr_done = true;
    }

    __nv_bfloat16 *xh, *xl, *wqth, *wqtl, *wkth, *wktl, *qh, *ql, *kh, *kl;
    __half *x16, *wvt16, *wot16, *wft16, *vt16, *p16, *o16, *n16;
    float *s, *a, *part, *mean;
    cudaGetSymbolAddress((void**)&xh, g_xh);     cudaGetSymbolAddress((void**)&xl, g_xl);
    cudaGetSymbolAddress((void**)&x16, g_x16);
    cudaGetSymbolAddress((void**)&wqth, g_wqth); cudaGetSymbolAddress((void**)&wqtl, g_wqtl);
    cudaGetSymbolAddress((void**)&wkth, g_wkth); cudaGetSymbolAddress((void**)&wktl, g_wktl);
    cudaGetSymbolAddress((void**)&wvt16, g_wvt16);
    cudaGetSymbolAddress((void**)&wot16, g_wot16);
    cudaGetSymbolAddress((void**)&wft16, g_wft16);
    cudaGetSymbolAddress((void**)&qh, g_qh);     cudaGetSymbolAddress((void**)&ql, g_ql);
    cudaGetSymbolAddress((void**)&kh, g_kh);     cudaGetSymbolAddress((void**)&kl, g_kl);
    cudaGetSymbolAddress((void**)&vt16, g_vt16);
    cudaGetSymbolAddress((void**)&s, g_s);
    cudaGetSymbolAddress((void**)&p16, g_p16);
    cudaGetSymbolAddress((void**)&o16, g_o16);
    cudaGetSymbolAddress((void**)&a, g_a);
    cudaGetSymbolAddress((void**)&n16, g_n16);
    cudaGetSymbolAddress((void**)&part, g_part); cudaGetSymbolAddress((void**)&mean, g_mean);

    // 0) splits / transposes of inputs
    const int nx = MTOK * DMODEL;
    split_kernel<<<(nx / 4 + 255) / 256, 256>>>(x, xh, xl, x16, nx);
    transpose_split_qkv<<<dim3(DQKV / 32, DMODEL / 32, 3), dim3(32, 8)>>>(
        Wq, Wk, Wv, wqth, wqtl, wkth, wktl, wvt16);
    transpose_f16<<<dim3(DMODEL / 32, DQKV / 32), dim3(32, 8)>>>(Wo, DQKV, DMODEL, wot16);
    transpose_f16<<<dim3(DMODEL / 32, DMODEL / 32), dim3(32, 8)>>>(Wf, DMODEL, DMODEL, wft16);

    // 1) Q, K projections (bf16 split-3), V projection (fp16 single, transposed out)
    dim3 qkvGrid(DQKV / 128, MTOK / 128);
    k_gemm_bias_split<<<qkvGrid, 128, DYN_SMEM>>>(xh, xl, DMODEL, wqth, wqtl, DMODEL, bq, qh, ql, DQKV, DMODEL);
    k_gemm_bias_split<<<qkvGrid, 128, DYN_SMEM>>>(xh, xl, DMODEL, wkth, wktl, DMODEL, bk, kh, kl, DQKV, DMODEL);
    k_gemm_v<<<qkvGrid, 128, DYN_SMEM2>>>(x16, wvt16, bv, vt16);

    // 2) masked scores (lower-triangle tiles only)
    k_scores<<<dim3(SEQ / 128, SEQ / 128, NBH), 128, DYN_SMEM>>>(qh, ql, kh, kl, s);

    // 3) causal softmax -> single-fp16 P
    softmax_causal<<<NBH * SEQ, 256>>>(s, p16);

    // 4) o = attn @ v (fp16 single, causal-truncated k-loop)
    k_pv<<<dim3(DMODEL / 128, SEQ / 128, NBH), 128, DYN_SMEM2>>>(p16, vt16, o16);

    // 5) a = o @ Wo + bo (fp16 single, fp32 out)
    k_gemm_wo<<<dim3(DMODEL / 128, MTOK / 128), 128, DYN_SMEM2>>>(o16, wot16, bo, a);

    // 6) deterministic global mean
    reduce_partial<<<1024, 256>>>(a, part);
    reduce_final<<<1, 256>>>(part, mean);

    // 7) n = a - mean + x (single fp16)
    fuse_kernel<<<(nx / 4 + 255) / 256, 256>>>(a, x, mean, n16, nx);

    // 8) out = leaky_relu(n @ Wf + bf) (fp16 single)
    k_final<<<dim3(DMODEL / 128, MTOK / 128), 128, DYN_SMEM2>>>(n16, wft16, bf, out);
}